// round 2
// baseline (speedup 1.0000x reference)
#include <cuda_runtime.h>
#include <math.h>

// Problem constants
#define S_LEN   2048
#define D_MODEL 1024
#define NH      16
#define NKV     4
#define HDIM    64
#define BATCH   2
#define M_TOT   (BATCH * S_LEN)   // 4096

// Scratch (device globals — no allocation allowed)
__device__ float g_q[(size_t)BATCH * NH  * S_LEN * HDIM]; // (b,h,s,d)
__device__ float g_k[(size_t)BATCH * NKV * S_LEN * HDIM]; // (b,kvh,s,d) roped
__device__ float g_v[(size_t)BATCH * NKV * S_LEN * HDIM];
__device__ float g_o[(size_t)BATCH * S_LEN * D_MODEL];    // (b,s,h*64+d)

// ---------------------------------------------------------------------------
// Fused QKV projection GEMM: X(4096x1024) @ [Wq|Wk|Wv](1024x1536)
// 128x128x8 tile, 256 threads, 8x8 microtile. RoPE fused in epilogue.
// ---------------------------------------------------------------------------
__global__ __launch_bounds__(256) void qkv_gemm(
    const float* __restrict__ X,
    const float* __restrict__ Wq,
    const float* __restrict__ Wk,
    const float* __restrict__ Wv)
{
    __shared__ float As[8 * 128];
    __shared__ float Bs[8 * 128];

    const int tid = threadIdx.x;
    const int bn  = blockIdx.x * 128;   // 0..1535
    const int bm  = blockIdx.y * 128;   // 0..4095

    // Block-uniform selection of which weight this N-tile belongs to.
    const float* Bp; int ldb, nofs, kind;
    if (bn < 1024)      { Bp = Wq; ldb = 1024; nofs = bn;        kind = 0; }
    else if (bn < 1280) { Bp = Wk; ldb = 256;  nofs = bn - 1024; kind = 1; }
    else                { Bp = Wv; ldb = 256;  nofs = bn - 1280; kind = 2; }

    const int arow = tid >> 1,  acol = (tid & 1) << 2;   // 128 rows x 8 k
    const int brow = tid >> 5,  bcol = (tid & 31) << 2;  // 8 k x 128 cols
    const int tx = tid & 15, ty = tid >> 4;

    float acc[8][8];
#pragma unroll
    for (int i = 0; i < 8; ++i)
#pragma unroll
        for (int j = 0; j < 8; ++j) acc[i][j] = 0.f;

    const float* Aptr = X  + (size_t)(bm + arow) * 1024 + acol;
    const float* Bptr = Bp + (size_t)brow * ldb + nofs + bcol;

    for (int kt = 0; kt < 1024; kt += 8) {
        float4 av = *(const float4*)(Aptr + kt);
        float4 bv = *(const float4*)(Bptr + (size_t)kt * ldb);
        As[(acol + 0) * 128 + arow] = av.x;
        As[(acol + 1) * 128 + arow] = av.y;
        As[(acol + 2) * 128 + arow] = av.z;
        As[(acol + 3) * 128 + arow] = av.w;
        *(float4*)&Bs[brow * 128 + bcol] = bv;
        __syncthreads();
#pragma unroll
        for (int k = 0; k < 8; ++k) {
            float4 a0 = *(const float4*)&As[k * 128 + ty * 8];
            float4 a1 = *(const float4*)&As[k * 128 + ty * 8 + 4];
            float4 b0 = *(const float4*)&Bs[k * 128 + tx * 8];
            float4 b1 = *(const float4*)&Bs[k * 128 + tx * 8 + 4];
            float ar[8] = {a0.x, a0.y, a0.z, a0.w, a1.x, a1.y, a1.z, a1.w};
            float br[8] = {b0.x, b0.y, b0.z, b0.w, b1.x, b1.y, b1.z, b1.w};
#pragma unroll
            for (int i = 0; i < 8; ++i)
#pragma unroll
                for (int j = 0; j < 8; ++j) acc[i][j] += ar[i] * br[j];
        }
        __syncthreads();
    }

    // Epilogue: RoPE + scatter into (b,head,s,d) scratch.
    const double CL = 9.210340371976184 / 1024.0;  // ln(10000)/1024
#pragma unroll
    for (int i = 0; i < 8; ++i) {
        int m = bm + ty * 8 + i;
        int b = m >> 11, s = m & 2047;
#pragma unroll
        for (int j = 0; j < 8; j += 2) {
            int n = bn + tx * 8 + j;                 // even
            float c0 = acc[i][j], c1 = acc[i][j + 1];
            if (kind == 0) {
                // Q: global pair index p = n/2 -> freq = theta^(-n/1024)
                double ang = (double)s * exp(-(double)n * CL);
                double sd, cd; sincos(ang, &sd, &cd);
                float sn = (float)sd, cs = (float)cd;
                float r0 = c0 * cs - c1 * sn;
                float r1 = c0 * sn + c1 * cs;
                int h = n >> 6, d = n & 63;
                float* dst = g_q + (((size_t)b * NH + h) * S_LEN + s) * HDIM + d;
                dst[0] = r0; dst[1] = r1;
            } else if (kind == 1) {
                // K: per-head pair index -> freq = theta^(-(d&~1)/1024)
                int np = n - 1024, kvh = np >> 6, d = np & 63;
                double ang = (double)s * exp(-(double)(d & ~1) * CL);
                double sd, cd; sincos(ang, &sd, &cd);
                float sn = (float)sd, cs = (float)cd;
                float r0 = c0 * cs - c1 * sn;
                float r1 = c0 * sn + c1 * cs;
                float* dst = g_k + (((size_t)b * NKV + kvh) * S_LEN + s) * HDIM + d;
                dst[0] = r0; dst[1] = r1;
            } else {
                int np = n - 1280, kvh = np >> 6, d = np & 63;
                float* dst = g_v + (((size_t)b * NKV + kvh) * S_LEN + s) * HDIM + d;
                dst[0] = c0; dst[1] = c1;
            }
        }
    }
}

// ---------------------------------------------------------------------------
// Flash attention: one CTA per (b, h, 128-row q tile). KV tiles of 64 rows.
// 256 threads, 8x4 microtile over the 128x64 S tile. Online softmax.
// ---------------------------------------------------------------------------
#define FA_SMEM_FLOATS (128*65 + 64*65 + 64*65 + 128*65 + 3*128)
#define FA_SMEM_BYTES  (FA_SMEM_FLOATS * 4)

__global__ __launch_bounds__(256, 2) void flash_kernel()
{
    extern __shared__ float sm[];
    float* Qs  = sm;                   // 128 x 65
    float* Ks  = Qs + 128 * 65;        // 64 x 65
    float* Vs  = Ks + 64 * 65;         // 64 x 65
    float* Ss  = Vs + 64 * 65;         // 128 x 65
    float* m_s = Ss + 128 * 65;        // 128
    float* l_s = m_s + 128;            // 128
    float* c_s = l_s + 128;            // 128

    const int tid = threadIdx.x;
    const int qt = blockIdx.x, h = blockIdx.y, b = blockIdx.z;
    const int kvh = h >> 2;            // jnp.repeat(axis=2): h -> h/G

    const float* Qg = g_q + (((size_t)b * NH  + h  ) * S_LEN + qt * 128) * HDIM;
    const float* Kg = g_k + (((size_t)b * NKV + kvh) * S_LEN) * HDIM;
    const float* Vg = g_v + (((size_t)b * NKV + kvh) * S_LEN) * HDIM;

    // Load Q tile (128x64): 2048 float4, 8 per thread.
#pragma unroll
    for (int t = 0; t < 8; ++t) {
        int f = tid + t * 256;
        int r = f >> 4, c4 = (f & 15) << 2;
        float4 v = *(const float4*)&Qg[(size_t)r * HDIM + c4];
        float* d = &Qs[r * 65 + c4];
        d[0] = v.x; d[1] = v.y; d[2] = v.z; d[3] = v.w;
    }
    if (tid < 128) { m_s[tid] = -INFINITY; l_s[tid] = 0.f; }

    const int tx = tid & 15, ty = tid >> 4;  // cols tx*4.., rows ty*8..
    float o[8][4];
#pragma unroll
    for (int i = 0; i < 8; ++i)
#pragma unroll
        for (int j = 0; j < 4; ++j) o[i][j] = 0.f;

    const float scale = 0.03125f;  // 1/sqrt(1024)

    for (int kt = 0; kt < 32; ++kt) {
        __syncthreads();  // previous PV done before K/V overwrite
        const float* Kt = Kg + (size_t)kt * 64 * HDIM;
        const float* Vt = Vg + (size_t)kt * 64 * HDIM;
#pragma unroll
        for (int t = 0; t < 4; ++t) {
            int f = tid + t * 256;
            int r = f >> 4, c4 = (f & 15) << 2;
            float4 kv = *(const float4*)&Kt[(size_t)r * HDIM + c4];
            float* dk = &Ks[r * 65 + c4];
            dk[0] = kv.x; dk[1] = kv.y; dk[2] = kv.z; dk[3] = kv.w;
            float4 vv = *(const float4*)&Vt[(size_t)r * HDIM + c4];
            float* dv = &Vs[r * 65 + c4];
            dv[0] = vv.x; dv[1] = vv.y; dv[2] = vv.z; dv[3] = vv.w;
        }
        __syncthreads();

        // S = Q K^T (128x64 over hd=64)
        float acc[8][4];
#pragma unroll
        for (int i = 0; i < 8; ++i)
#pragma unroll
            for (int j = 0; j < 4; ++j) acc[i][j] = 0.f;

#pragma unroll 4
        for (int d = 0; d < 64; ++d) {
            float kk[4];
#pragma unroll
            for (int j = 0; j < 4; ++j) kk[j] = Ks[(tx * 4 + j) * 65 + d];
#pragma unroll
            for (int i = 0; i < 8; ++i) {
                float qv = Qs[(ty * 8 + i) * 65 + d];
#pragma unroll
                for (int j = 0; j < 4; ++j) acc[i][j] += qv * kk[j];
            }
        }
#pragma unroll
        for (int i = 0; i < 8; ++i)
#pragma unroll
            for (int j = 0; j < 4; ++j)
                Ss[(ty * 8 + i) * 65 + tx * 4 + j] = acc[i][j] * scale;
        __syncthreads();

        // Online softmax, one thread per row.
        if (tid < 128) {
            float* Sr = &Ss[tid * 65];
            float tmax = -INFINITY;
#pragma unroll 8
            for (int j = 0; j < 64; ++j) tmax = fmaxf(tmax, Sr[j]);
            float mo = m_s[tid];
            float nm = fmaxf(mo, tmax);
            float cf = __expf(mo - nm);     // 0 on first tile (mo = -inf)
            float ls = 0.f;
#pragma unroll 8
            for (int j = 0; j < 64; ++j) {
                float e = __expf(Sr[j] - nm);
                Sr[j] = e;
                ls += e;
            }
            l_s[tid] = l_s[tid] * cf + ls;
            m_s[tid] = nm;
            c_s[tid] = cf;
        }
        __syncthreads();

        // O = O*corr + P V
        float cri[8];
#pragma unroll
        for (int i = 0; i < 8; ++i) cri[i] = c_s[ty * 8 + i];
#pragma unroll
        for (int i = 0; i < 8; ++i)
#pragma unroll
            for (int j = 0; j < 4; ++j) o[i][j] *= cri[i];

#pragma unroll 4
        for (int p = 0; p < 64; ++p) {
            float vv[4];
#pragma unroll
            for (int j = 0; j < 4; ++j) vv[j] = Vs[p * 65 + tx * 4 + j];
#pragma unroll
            for (int i = 0; i < 8; ++i) {
                float pe = Ss[(ty * 8 + i) * 65 + p];
#pragma unroll
                for (int j = 0; j < 4; ++j) o[i][j] += pe * vv[j];
            }
        }
    }

    // Final normalize + write to (b,s,D) layout for the O projection.
#pragma unroll
    for (int i = 0; i < 8; ++i) {
        int r = ty * 8 + i;
        float inv = 1.f / l_s[r];
        int s = qt * 128 + r;
        float4 ov;
        ov.x = o[i][0] * inv; ov.y = o[i][1] * inv;
        ov.z = o[i][2] * inv; ov.w = o[i][3] * inv;
        *(float4*)&g_o[((size_t)b * S_LEN + s) * D_MODEL + h * HDIM + tx * 4] = ov;
    }
}

// ---------------------------------------------------------------------------
// Output projection: g_o(4096x1024) @ Wo(1024x1024) -> out
// ---------------------------------------------------------------------------
__global__ __launch_bounds__(256) void out_gemm(
    const float* __restrict__ Wo, float* __restrict__ out)
{
    __shared__ float As[8 * 128];
    __shared__ float Bs[8 * 128];

    const int tid = threadIdx.x;
    const int bn  = blockIdx.x * 128;
    const int bm  = blockIdx.y * 128;

    const int arow = tid >> 1,  acol = (tid & 1) << 2;
    const int brow = tid >> 5,  bcol = (tid & 31) << 2;
    const int tx = tid & 15, ty = tid >> 4;

    float acc[8][8];
#pragma unroll
    for (int i = 0; i < 8; ++i)
#pragma unroll
        for (int j = 0; j < 8; ++j) acc[i][j] = 0.f;

    const float* Aptr = g_o + (size_t)(bm + arow) * 1024 + acol;
    const float* Bptr = Wo  + (size_t)brow * 1024 + bn + bcol;

    for (int kt = 0; kt < 1024; kt += 8) {
        float4 av = *(const float4*)(Aptr + kt);
        float4 bv = *(const float4*)(Bptr + (size_t)kt * 1024);
        As[(acol + 0) * 128 + arow] = av.x;
        As[(acol + 1) * 128 + arow] = av.y;
        As[(acol + 2) * 128 + arow] = av.z;
        As[(acol + 3) * 128 + arow] = av.w;
        *(float4*)&Bs[brow * 128 + bcol] = bv;
        __syncthreads();
#pragma unroll
        for (int k = 0; k < 8; ++k) {
            float4 a0 = *(const float4*)&As[k * 128 + ty * 8];
            float4 a1 = *(const float4*)&As[k * 128 + ty * 8 + 4];
            float4 b0 = *(const float4*)&Bs[k * 128 + tx * 8];
            float4 b1 = *(const float4*)&Bs[k * 128 + tx * 8 + 4];
            float ar[8] = {a0.x, a0.y, a0.z, a0.w, a1.x, a1.y, a1.z, a1.w};
            float br[8] = {b0.x, b0.y, b0.z, b0.w, b1.x, b1.y, b1.z, b1.w};
#pragma unroll
            for (int i = 0; i < 8; ++i)
#pragma unroll
                for (int j = 0; j < 8; ++j) acc[i][j] += ar[i] * br[j];
        }
        __syncthreads();
    }

#pragma unroll
    for (int i = 0; i < 8; ++i) {
        int m = bm + ty * 8 + i;
        float4 o0, o1;
        o0.x = acc[i][0]; o0.y = acc[i][1]; o0.z = acc[i][2]; o0.w = acc[i][3];
        o1.x = acc[i][4]; o1.y = acc[i][5]; o1.z = acc[i][6]; o1.w = acc[i][7];
        *(float4*)&out[(size_t)m * 1024 + bn + tx * 8]     = o0;
        *(float4*)&out[(size_t)m * 1024 + bn + tx * 8 + 4] = o1;
    }
}

// ---------------------------------------------------------------------------
extern "C" void kernel_launch(void* const* d_in, const int* in_sizes, int n_in,
                              void* d_out, int out_size)
{
    const float* x  = (const float*)d_in[0];
    const float* Wq = (const float*)d_in[1];
    const float* Wk = (const float*)d_in[2];
    const float* Wv = (const float*)d_in[3];
    const float* Wo = (const float*)d_in[4];
    float* out = (float*)d_out;

    (void)in_sizes; (void)n_in; (void)out_size;

    // Opt-in to >48KB dynamic smem for the flash kernel (not a stream op;
    // graph-capture safe, deterministic).
    cudaFuncSetAttribute(flash_kernel,
                         cudaFuncAttributeMaxDynamicSharedMemorySize,
                         FA_SMEM_BYTES);

    qkv_gemm<<<dim3(12, 32), 256>>>(x, Wq, Wk, Wv);
    flash_kernel<<<dim3(16, 16, 2), 256, FA_SMEM_BYTES>>>();
    out_gemm<<<dim3(8, 32), 256>>>(Wo, out);
}

// round 4
// speedup vs baseline: 2.5584x; 2.5584x over previous
#include <cuda_runtime.h>
#include <math.h>

// Problem constants
#define S_LEN   2048
#define D_MODEL 1024
#define NH      16
#define NKV     4
#define HDIM    64
#define BATCH   2

// Scratch (device globals — no allocation allowed)
__device__ float g_q[(size_t)BATCH * NH  * S_LEN * HDIM]; // (b,h,s,d) roped
__device__ float g_k[(size_t)BATCH * NKV * S_LEN * HDIM]; // (b,kvh,s,d) roped
__device__ float g_v[(size_t)BATCH * NKV * S_LEN * HDIM];
__device__ float g_o[(size_t)BATCH * S_LEN * D_MODEL];    // (b,s,h*64+d)

// ---------------------------------------------------------------------------
// tf32 helpers
// ---------------------------------------------------------------------------
__device__ __forceinline__ unsigned f2tf(float f) {
    unsigned u;
    asm("cvt.rna.tf32.f32 %0, %1;" : "=r"(u) : "f"(f));
    return u;
}

__device__ __forceinline__ void mma8(float* d, const unsigned* a, const unsigned* b) {
    asm volatile(
        "mma.sync.aligned.m16n8k8.row.col.f32.tf32.tf32.f32 "
        "{%0,%1,%2,%3}, {%4,%5,%6,%7}, {%8,%9}, {%0,%1,%2,%3};"
        : "+f"(d[0]), "+f"(d[1]), "+f"(d[2]), "+f"(d[3])
        : "r"(a[0]), "r"(a[1]), "r"(a[2]), "r"(a[3]),
          "r"(b[0]), "r"(b[1]));
}

// ---------------------------------------------------------------------------
// Fused QKV projection GEMM (tf32 MMA): X(4096x1024) @ [Wq|Wk|Wv](1024x1536)
// 128x128 tile, BK=16, 8 warps (2x4), warp tile 64x32. RoPE in epilogue.
// ---------------------------------------------------------------------------
#define GP 136   // smem row stride (words); banks (8t+g)%32 all distinct

__global__ __launch_bounds__(256, 2) void qkv_gemm(
    const float* __restrict__ X,
    const float* __restrict__ Wq,
    const float* __restrict__ Wk,
    const float* __restrict__ Wv)
{
    __shared__ unsigned As[16][GP];   // [k][m]
    __shared__ unsigned Bs[16][GP];   // [k][n]

    const int tid  = threadIdx.x;
    const int lane = tid & 31, warp = tid >> 5;
    const int g = lane >> 2, t = lane & 3;
    const int wm = (warp >> 2) * 64, wn = (warp & 3) * 32;
    const int bn = blockIdx.x * 128, bm = blockIdx.y * 128;

    const float* Bp; int ldb, nofs, kind;
    if (bn < 1024)      { Bp = Wq; ldb = 1024; nofs = bn;        kind = 0; }
    else if (bn < 1280) { Bp = Wk; ldb = 256;  nofs = bn - 1024; kind = 1; }
    else                { Bp = Wv; ldb = 256;  nofs = bn - 1280; kind = 2; }

    float acc[4][4][4];
#pragma unroll
    for (int mi = 0; mi < 4; ++mi)
#pragma unroll
        for (int ni = 0; ni < 4; ++ni)
#pragma unroll
            for (int c = 0; c < 4; ++c) acc[mi][ni][c] = 0.f;

    for (int kt = 0; kt < 1024; kt += 16) {
        // Load A 128x16 (transpose into [k][m])
#pragma unroll
        for (int p = 0; p < 2; ++p) {
            int f = tid + p * 256;
            int row = f >> 2, kc = (f & 3) << 2;
            float4 v = *(const float4*)(X + (size_t)(bm + row) * 1024 + kt + kc);
            As[kc + 0][row] = f2tf(v.x);
            As[kc + 1][row] = f2tf(v.y);
            As[kc + 2][row] = f2tf(v.z);
            As[kc + 3][row] = f2tf(v.w);
        }
        // Load B 16x128
#pragma unroll
        for (int p = 0; p < 2; ++p) {
            int f = tid + p * 256;
            int br = f >> 5, bc = (f & 31) << 2;
            float4 v = *(const float4*)(Bp + (size_t)(kt + br) * ldb + nofs + bc);
            uint4 u = { f2tf(v.x), f2tf(v.y), f2tf(v.z), f2tf(v.w) };
            *(uint4*)&Bs[br][bc] = u;
        }
        __syncthreads();

#pragma unroll
        for (int kk = 0; kk < 2; ++kk) {
            unsigned a[4][4], b[4][2];
#pragma unroll
            for (int mi = 0; mi < 4; ++mi) {
                int m = wm + mi * 16 + g;
                a[mi][0] = As[kk * 8 + t]    [m];
                a[mi][1] = As[kk * 8 + t]    [m + 8];
                a[mi][2] = As[kk * 8 + t + 4][m];
                a[mi][3] = As[kk * 8 + t + 4][m + 8];
            }
#pragma unroll
            for (int ni = 0; ni < 4; ++ni) {
                int n = wn + ni * 8 + g;
                b[ni][0] = Bs[kk * 8 + t]    [n];
                b[ni][1] = Bs[kk * 8 + t + 4][n];
            }
#pragma unroll
            for (int mi = 0; mi < 4; ++mi)
#pragma unroll
                for (int ni = 0; ni < 4; ++ni)
                    mma8(acc[mi][ni], a[mi], b[ni]);
        }
        __syncthreads();
    }

    // Epilogue: RoPE + scatter. Accum pair (c0,c1)=(col n,n+1) row g; (c2,c3) row g+8.
    const double CL = 9.210340371976184 / 1024.0;  // ln(10000)/1024
#pragma unroll
    for (int mi = 0; mi < 4; ++mi) {
#pragma unroll
        for (int ni = 0; ni < 4; ++ni) {
            int n = bn + wn + ni * 8 + 2 * t;       // even
#pragma unroll
            for (int half = 0; half < 2; ++half) {
                int m = bm + wm + mi * 16 + g + half * 8;
                int b = m >> 11, s = m & 2047;
                float c0 = acc[mi][ni][half * 2 + 0];
                float c1 = acc[mi][ni][half * 2 + 1];
                if (kind == 0) {
                    double ang = (double)s * exp(-(double)n * CL);
                    double sd, cd; sincos(ang, &sd, &cd);
                    float sn = (float)sd, cs = (float)cd;
                    float2 r = { c0 * cs - c1 * sn, c0 * sn + c1 * cs };
                    int h = n >> 6, d = n & 63;
                    *(float2*)(g_q + (((size_t)b * NH + h) * S_LEN + s) * HDIM + d) = r;
                } else if (kind == 1) {
                    int np = n - 1024, kvh = np >> 6, d = np & 63;
                    double ang = (double)s * exp(-(double)d * CL);  // d even
                    double sd, cd; sincos(ang, &sd, &cd);
                    float sn = (float)sd, cs = (float)cd;
                    float2 r = { c0 * cs - c1 * sn, c0 * sn + c1 * cs };
                    *(float2*)(g_k + (((size_t)b * NKV + kvh) * S_LEN + s) * HDIM + d) = r;
                } else {
                    int np = n - 1280, kvh = np >> 6, d = np & 63;
                    float2 r = { c0, c1 };
                    *(float2*)(g_v + (((size_t)b * NKV + kvh) * S_LEN + s) * HDIM + d) = r;
                }
            }
        }
    }
}

// ---------------------------------------------------------------------------
// Flash attention (tf32 MMA): CTA = (b, h, 128 q rows). KV tiles of 64.
// 8 warps, each owns 16 q rows. Softmax via 4-lane shfl reductions.
// ---------------------------------------------------------------------------
#define QS_P 68   // Qs/Ks/Ss stride: banks (4g+t)%32 distinct
#define VS_P 72   // Vs stride:       banks (8t+g)%32 distinct
#define FA_WORDS (128 * QS_P + 64 * QS_P + 64 * VS_P + 128 * QS_P)
#define FA_BYTES (FA_WORDS * 4)

__global__ __launch_bounds__(256, 2) void flash_kernel()
{
    extern __shared__ unsigned sm[];
    unsigned* Qs = sm;                    // 128 x 68 (tf32)
    unsigned* Ks = Qs + 128 * QS_P;       // 64 x 68
    unsigned* Vs = Ks + 64 * QS_P;        // 64 x 72
    unsigned* Ss = Vs + 64 * VS_P;        // 128 x 68 (P, tf32)

    const int tid  = threadIdx.x;
    const int lane = tid & 31, warp = tid >> 5;
    const int g = lane >> 2, t = lane & 3;
    const int qt = blockIdx.x, h = blockIdx.y, b = blockIdx.z;
    const int kvh = h >> 2;
    const int wrow = warp * 16;           // this warp's q-row base

    const float* Qg = g_q + (((size_t)b * NH  + h  ) * S_LEN + qt * 128) * HDIM;
    const float* Kg = g_k + (((size_t)b * NKV + kvh) * S_LEN) * HDIM;
    const float* Vg = g_v + (((size_t)b * NKV + kvh) * S_LEN) * HDIM;

    // Load Q tile (128x64) as tf32
#pragma unroll
    for (int p = 0; p < 8; ++p) {
        int f = tid + p * 256;
        int r = f >> 4, c = (f & 15) << 2;
        float4 v = *(const float4*)&Qg[(size_t)r * HDIM + c];
        uint4 u = { f2tf(v.x), f2tf(v.y), f2tf(v.z), f2tf(v.w) };
        *(uint4*)&Qs[r * QS_P + c] = u;
    }

    float o[8][4];
#pragma unroll
    for (int j = 0; j < 8; ++j)
#pragma unroll
        for (int c = 0; c < 4; ++c) o[j][c] = 0.f;
    float m0 = -INFINITY, m1 = -INFINITY, l0 = 0.f, l1 = 0.f;
    const float scale = 0.03125f;  // 1/sqrt(1024)

    for (int kt = 0; kt < 32; ++kt) {
        __syncthreads();  // prior reads of Ks/Vs done
        const float* Kt = Kg + (size_t)kt * 64 * HDIM;
        const float* Vt = Vg + (size_t)kt * 64 * HDIM;
#pragma unroll
        for (int p = 0; p < 4; ++p) {
            int f = tid + p * 256;
            int r = f >> 4, c = (f & 15) << 2;
            float4 kv = *(const float4*)&Kt[(size_t)r * HDIM + c];
            uint4 uk = { f2tf(kv.x), f2tf(kv.y), f2tf(kv.z), f2tf(kv.w) };
            *(uint4*)&Ks[r * QS_P + c] = uk;
            float4 vv = *(const float4*)&Vt[(size_t)r * HDIM + c];
            uint4 uv = { f2tf(vv.x), f2tf(vv.y), f2tf(vv.z), f2tf(vv.w) };
            *(uint4*)&Vs[r * VS_P + c] = uv;
        }
        __syncthreads();

        // S = Q K^T : warp computes 16 x 64
        float s[8][4];
#pragma unroll
        for (int j = 0; j < 8; ++j)
#pragma unroll
            for (int c = 0; c < 4; ++c) s[j][c] = 0.f;

#pragma unroll
        for (int kk = 0; kk < 8; ++kk) {
            unsigned a[4];
            a[0] = Qs[(wrow + g)     * QS_P + kk * 8 + t];
            a[1] = Qs[(wrow + g + 8) * QS_P + kk * 8 + t];
            a[2] = Qs[(wrow + g)     * QS_P + kk * 8 + t + 4];
            a[3] = Qs[(wrow + g + 8) * QS_P + kk * 8 + t + 4];
#pragma unroll
            for (int j = 0; j < 8; ++j) {
                unsigned bb[2];
                bb[0] = Ks[(j * 8 + g) * QS_P + kk * 8 + t];
                bb[1] = Ks[(j * 8 + g) * QS_P + kk * 8 + t + 4];
                mma8(s[j], a, bb);
            }
        }

        // scale
#pragma unroll
        for (int j = 0; j < 8; ++j)
#pragma unroll
            for (int c = 0; c < 4; ++c) s[j][c] *= scale;

        // row max (rows g and g+8), reduce over the 4-lane group
        float rm0 = -INFINITY, rm1 = -INFINITY;
#pragma unroll
        for (int j = 0; j < 8; ++j) {
            rm0 = fmaxf(rm0, fmaxf(s[j][0], s[j][1]));
            rm1 = fmaxf(rm1, fmaxf(s[j][2], s[j][3]));
        }
#pragma unroll
        for (int off = 1; off <= 2; off <<= 1) {
            rm0 = fmaxf(rm0, __shfl_xor_sync(0xffffffffu, rm0, off));
            rm1 = fmaxf(rm1, __shfl_xor_sync(0xffffffffu, rm1, off));
        }
        float nm0 = fmaxf(m0, rm0), nm1 = fmaxf(m1, rm1);
        float cf0 = __expf(m0 - nm0), cf1 = __expf(m1 - nm1);

        float rs0 = 0.f, rs1 = 0.f;
#pragma unroll
        for (int j = 0; j < 8; ++j) {
            s[j][0] = __expf(s[j][0] - nm0);
            s[j][1] = __expf(s[j][1] - nm0);
            s[j][2] = __expf(s[j][2] - nm1);
            s[j][3] = __expf(s[j][3] - nm1);
            rs0 += s[j][0] + s[j][1];
            rs1 += s[j][2] + s[j][3];
        }
#pragma unroll
        for (int off = 1; off <= 2; off <<= 1) {
            rs0 += __shfl_xor_sync(0xffffffffu, rs0, off);
            rs1 += __shfl_xor_sync(0xffffffffu, rs1, off);
        }
        l0 = l0 * cf0 + rs0;  m0 = nm0;
        l1 = l1 * cf1 + rs1;  m1 = nm1;

        // store P (tf32) into this warp's own Ss stripe
#pragma unroll
        for (int j = 0; j < 8; ++j) {
            uint2 p0 = { f2tf(s[j][0]), f2tf(s[j][1]) };
            uint2 p1 = { f2tf(s[j][2]), f2tf(s[j][3]) };
            *(uint2*)&Ss[(wrow + g)     * QS_P + j * 8 + 2 * t] = p0;
            *(uint2*)&Ss[(wrow + g + 8) * QS_P + j * 8 + 2 * t] = p1;
        }
        __syncwarp();

        // O = O*cf + P V
#pragma unroll
        for (int jn = 0; jn < 8; ++jn) {
            o[jn][0] *= cf0; o[jn][1] *= cf0;
            o[jn][2] *= cf1; o[jn][3] *= cf1;
        }
#pragma unroll
        for (int kk = 0; kk < 8; ++kk) {
            unsigned a[4];
            a[0] = Ss[(wrow + g)     * QS_P + kk * 8 + t];
            a[1] = Ss[(wrow + g + 8) * QS_P + kk * 8 + t];
            a[2] = Ss[(wrow + g)     * QS_P + kk * 8 + t + 4];
            a[3] = Ss[(wrow + g + 8) * QS_P + kk * 8 + t + 4];
#pragma unroll
            for (int jn = 0; jn < 8; ++jn) {
                unsigned bb[2];
                bb[0] = Vs[(kk * 8 + t)     * VS_P + jn * 8 + g];
                bb[1] = Vs[(kk * 8 + t + 4) * VS_P + jn * 8 + g];
                mma8(o[jn], a, bb);
            }
        }
    }

    // Normalize + write (b,s,D)
    float inv0 = 1.f / l0, inv1 = 1.f / l1;
    int r0 = qt * 128 + wrow + g, r1 = r0 + 8;
#pragma unroll
    for (int jn = 0; jn < 8; ++jn) {
        int col = h * HDIM + jn * 8 + 2 * t;
        float2 v0 = { o[jn][0] * inv0, o[jn][1] * inv0 };
        float2 v1 = { o[jn][2] * inv1, o[jn][3] * inv1 };
        *(float2*)&g_o[((size_t)b * S_LEN + r0) * D_MODEL + col] = v0;
        *(float2*)&g_o[((size_t)b * S_LEN + r1) * D_MODEL + col] = v1;
    }
}

// ---------------------------------------------------------------------------
// Output projection (tf32 MMA): g_o(4096x1024) @ Wo(1024x1024) -> out
// ---------------------------------------------------------------------------
__global__ __launch_bounds__(256, 2) void out_gemm(
    const float* __restrict__ Wo, float* __restrict__ out)
{
    __shared__ unsigned As[16][GP];
    __shared__ unsigned Bs[16][GP];

    const int tid  = threadIdx.x;
    const int lane = tid & 31, warp = tid >> 5;
    const int g = lane >> 2, t = lane & 3;
    const int wm = (warp >> 2) * 64, wn = (warp & 3) * 32;
    const int bn = blockIdx.x * 128, bm = blockIdx.y * 128;

    float acc[4][4][4];
#pragma unroll
    for (int mi = 0; mi < 4; ++mi)
#pragma unroll
        for (int ni = 0; ni < 4; ++ni)
#pragma unroll
            for (int c = 0; c < 4; ++c) acc[mi][ni][c] = 0.f;

    for (int kt = 0; kt < 1024; kt += 16) {
#pragma unroll
        for (int p = 0; p < 2; ++p) {
            int f = tid + p * 256;
            int row = f >> 2, kc = (f & 3) << 2;
            float4 v = *(const float4*)(g_o + (size_t)(bm + row) * 1024 + kt + kc);
            As[kc + 0][row] = f2tf(v.x);
            As[kc + 1][row] = f2tf(v.y);
            As[kc + 2][row] = f2tf(v.z);
            As[kc + 3][row] = f2tf(v.w);
        }
#pragma unroll
        for (int p = 0; p < 2; ++p) {
            int f = tid + p * 256;
            int br = f >> 5, bc = (f & 31) << 2;
            float4 v = *(const float4*)(Wo + (size_t)(kt + br) * 1024 + bn + bc);
            uint4 u = { f2tf(v.x), f2tf(v.y), f2tf(v.z), f2tf(v.w) };
            *(uint4*)&Bs[br][bc] = u;
        }
        __syncthreads();

#pragma unroll
        for (int kk = 0; kk < 2; ++kk) {
            unsigned a[4][4], b[4][2];
#pragma unroll
            for (int mi = 0; mi < 4; ++mi) {
                int m = wm + mi * 16 + g;
                a[mi][0] = As[kk * 8 + t]    [m];
                a[mi][1] = As[kk * 8 + t]    [m + 8];
                a[mi][2] = As[kk * 8 + t + 4][m];
                a[mi][3] = As[kk * 8 + t + 4][m + 8];
            }
#pragma unroll
            for (int ni = 0; ni < 4; ++ni) {
                int n = wn + ni * 8 + g;
                b[ni][0] = Bs[kk * 8 + t]    [n];
                b[ni][1] = Bs[kk * 8 + t + 4][n];
            }
#pragma unroll
            for (int mi = 0; mi < 4; ++mi)
#pragma unroll
                for (int ni = 0; ni < 4; ++ni)
                    mma8(acc[mi][ni], a[mi], b[ni]);
        }
        __syncthreads();
    }

#pragma unroll
    for (int mi = 0; mi < 4; ++mi)
#pragma unroll
        for (int ni = 0; ni < 4; ++ni) {
            int n = bn + wn + ni * 8 + 2 * t;
#pragma unroll
            for (int half = 0; half < 2; ++half) {
                int m = bm + wm + mi * 16 + g + half * 8;
                float2 r = { acc[mi][ni][half * 2 + 0], acc[mi][ni][half * 2 + 1] };
                *(float2*)&out[(size_t)m * 1024 + n] = r;
            }
        }
}

// ---------------------------------------------------------------------------
extern "C" void kernel_launch(void* const* d_in, const int* in_sizes, int n_in,
                              void* d_out, int out_size)
{
    const float* x  = (const float*)d_in[0];
    const float* Wq = (const float*)d_in[1];
    const float* Wk = (const float*)d_in[2];
    const float* Wv = (const float*)d_in[3];
    const float* Wo = (const float*)d_in[4];
    float* out = (float*)d_out;

    (void)in_sizes; (void)n_in; (void)out_size;

    cudaFuncSetAttribute(flash_kernel,
                         cudaFuncAttributeMaxDynamicSharedMemorySize,
                         FA_BYTES);

    qkv_gemm<<<dim3(12, 32), 256>>>(x, Wq, Wk, Wv);
    flash_kernel<<<dim3(16, 16, 2), 256, FA_BYTES>>>();
    out_gemm<<<dim3(8, 32), 256>>>(Wo, out);
}

// round 5
// speedup vs baseline: 3.4024x; 1.3299x over previous
#include <cuda_runtime.h>
#include <math.h>

// Problem constants
#define S_LEN   2048
#define D_MODEL 1024
#define NH      16
#define NKV     4
#define HDIM    64
#define BATCH   2

// Scratch (device globals — no allocation allowed)
__device__ float g_q[(size_t)BATCH * NH  * S_LEN * HDIM]; // (b,h,s,d) roped
__device__ float g_k[(size_t)BATCH * NKV * S_LEN * HDIM]; // (b,kvh,s,d) roped
__device__ float g_v[(size_t)BATCH * NKV * S_LEN * HDIM];
__device__ float g_o[(size_t)BATCH * S_LEN * D_MODEL];    // (b,s,h*64+d)
__device__ float2 g_rope[(size_t)S_LEN * 512];            // [s][p] = (cos, sin)

// ---------------------------------------------------------------------------
// RoPE table: angle = s * theta^(-2p/1024). Double-accurate angle, range-
// reduced to [-pi,pi], then fast fp32 sincos. One thread per entry.
// ---------------------------------------------------------------------------
__global__ __launch_bounds__(256) void rope_table()
{
    int idx = blockIdx.x * 256 + threadIdx.x;     // 0 .. 2048*512-1
    int s = idx >> 9, p = idx & 511;
    const double CL2 = 9.210340371976184 / 512.0; // ln(10000)/512
    double inv = exp(-(double)p * CL2);
    double ang = (double)s * inv;
    const double TWO_PI = 6.283185307179586476925;
    double r = ang - TWO_PI * rint(ang * (1.0 / TWO_PI));  // [-pi, pi]
    float sf, cf;
    __sincosf((float)r, &sf, &cf);
    g_rope[idx] = make_float2(cf, sf);
}

// ---------------------------------------------------------------------------
// tf32 helpers
// ---------------------------------------------------------------------------
__device__ __forceinline__ unsigned f2tf(float f) {
    unsigned u;
    asm("cvt.rna.tf32.f32 %0, %1;" : "=r"(u) : "f"(f));
    return u;
}

__device__ __forceinline__ void mma8(float* d, const unsigned* a, const unsigned* b) {
    asm volatile(
        "mma.sync.aligned.m16n8k8.row.col.f32.tf32.tf32.f32 "
        "{%0,%1,%2,%3}, {%4,%5,%6,%7}, {%8,%9}, {%0,%1,%2,%3};"
        : "+f"(d[0]), "+f"(d[1]), "+f"(d[2]), "+f"(d[3])
        : "r"(a[0]), "r"(a[1]), "r"(a[2]), "r"(a[3]),
          "r"(b[0]), "r"(b[1]));
}

// ---------------------------------------------------------------------------
// Fused QKV projection GEMM (tf32 MMA, double-buffered + reg prefetch).
// X(4096x1024) @ [Wq|Wk|Wv](1024x1536). 128x128 tile, BK=16, 8 warps (2x4).
// ---------------------------------------------------------------------------
#define GP 136   // smem row stride (words); fragment LDS conflict-free

__global__ __launch_bounds__(256, 2) void qkv_gemm(
    const float* __restrict__ X,
    const float* __restrict__ Wq,
    const float* __restrict__ Wk,
    const float* __restrict__ Wv)
{
    __shared__ unsigned As[2][16][GP];   // [buf][k][m]
    __shared__ unsigned Bs[2][16][GP];   // [buf][k][n]

    const int tid  = threadIdx.x;
    const int lane = tid & 31, warp = tid >> 5;
    const int g = lane >> 2, t = lane & 3;
    const int wm = (warp >> 2) * 64, wn = (warp & 3) * 32;
    const int bn = blockIdx.x * 128, bm = blockIdx.y * 128;

    const float* Bp; int ldb, nofs, kind;
    if (bn < 1024)      { Bp = Wq; ldb = 1024; nofs = bn;        kind = 0; }
    else if (bn < 1280) { Bp = Wk; ldb = 256;  nofs = bn - 1024; kind = 1; }
    else                { Bp = Wv; ldb = 256;  nofs = bn - 1280; kind = 2; }

    // Per-thread load coordinates
    const int a_row = tid >> 2, a_kc = (tid & 3) << 2;   // rows a_row, a_row+64
    const int b_r   = tid >> 5, b_c  = (tid & 31) << 2;  // k rows b_r, b_r+8
    const float* Ap0 = X  + (size_t)(bm + a_row) * 1024 + a_kc;
    const float* Ap1 = Ap0 + (size_t)64 * 1024;
    const float* Bq0 = Bp + (size_t)b_r * ldb + nofs + b_c;
    const float* Bq1 = Bp + (size_t)(b_r + 8) * ldb + nofs + b_c;

    float acc[4][4][4];
#pragma unroll
    for (int mi = 0; mi < 4; ++mi)
#pragma unroll
        for (int ni = 0; ni < 4; ++ni)
#pragma unroll
            for (int c = 0; c < 4; ++c) acc[mi][ni][c] = 0.f;

    float4 ra0, ra1, rb0, rb1;
    // prologue: tile 0
    ra0 = *(const float4*)(Ap0);
    ra1 = *(const float4*)(Ap1);
    rb0 = *(const float4*)(Bq0);
    rb1 = *(const float4*)(Bq1);
    {
        As[0][a_kc + 0][a_row] = f2tf(ra0.x);
        As[0][a_kc + 1][a_row] = f2tf(ra0.y);
        As[0][a_kc + 2][a_row] = f2tf(ra0.z);
        As[0][a_kc + 3][a_row] = f2tf(ra0.w);
        As[0][a_kc + 0][a_row + 64] = f2tf(ra1.x);
        As[0][a_kc + 1][a_row + 64] = f2tf(ra1.y);
        As[0][a_kc + 2][a_row + 64] = f2tf(ra1.z);
        As[0][a_kc + 3][a_row + 64] = f2tf(ra1.w);
        uint4 u0 = { f2tf(rb0.x), f2tf(rb0.y), f2tf(rb0.z), f2tf(rb0.w) };
        uint4 u1 = { f2tf(rb1.x), f2tf(rb1.y), f2tf(rb1.z), f2tf(rb1.w) };
        *(uint4*)&Bs[0][b_r][b_c]     = u0;
        *(uint4*)&Bs[0][b_r + 8][b_c] = u1;
    }
    __syncthreads();

    for (int kt = 0; kt < 64; ++kt) {
        const int cur = kt & 1;
        if (kt < 63) {
            int ko = (kt + 1) * 16;
            ra0 = *(const float4*)(Ap0 + ko);
            ra1 = *(const float4*)(Ap1 + ko);
            rb0 = *(const float4*)(Bq0 + (size_t)ko * ldb);
            rb1 = *(const float4*)(Bq1 + (size_t)ko * ldb);
        }

#pragma unroll
        for (int kk = 0; kk < 2; ++kk) {
            unsigned a[4][4], b[4][2];
#pragma unroll
            for (int mi = 0; mi < 4; ++mi) {
                int m = wm + mi * 16 + g;
                a[mi][0] = As[cur][kk * 8 + t]    [m];
                a[mi][1] = As[cur][kk * 8 + t]    [m + 8];
                a[mi][2] = As[cur][kk * 8 + t + 4][m];
                a[mi][3] = As[cur][kk * 8 + t + 4][m + 8];
            }
#pragma unroll
            for (int ni = 0; ni < 4; ++ni) {
                int n = wn + ni * 8 + g;
                b[ni][0] = Bs[cur][kk * 8 + t]    [n];
                b[ni][1] = Bs[cur][kk * 8 + t + 4][n];
            }
#pragma unroll
            for (int mi = 0; mi < 4; ++mi)
#pragma unroll
                for (int ni = 0; ni < 4; ++ni)
                    mma8(acc[mi][ni], a[mi], b[ni]);
        }

        if (kt < 63) {
            const int nxt = cur ^ 1;
            As[nxt][a_kc + 0][a_row] = f2tf(ra0.x);
            As[nxt][a_kc + 1][a_row] = f2tf(ra0.y);
            As[nxt][a_kc + 2][a_row] = f2tf(ra0.z);
            As[nxt][a_kc + 3][a_row] = f2tf(ra0.w);
            As[nxt][a_kc + 0][a_row + 64] = f2tf(ra1.x);
            As[nxt][a_kc + 1][a_row + 64] = f2tf(ra1.y);
            As[nxt][a_kc + 2][a_row + 64] = f2tf(ra1.z);
            As[nxt][a_kc + 3][a_row + 64] = f2tf(ra1.w);
            uint4 u0 = { f2tf(rb0.x), f2tf(rb0.y), f2tf(rb0.z), f2tf(rb0.w) };
            uint4 u1 = { f2tf(rb1.x), f2tf(rb1.y), f2tf(rb1.z), f2tf(rb1.w) };
            *(uint4*)&Bs[nxt][b_r][b_c]     = u0;
            *(uint4*)&Bs[nxt][b_r + 8][b_c] = u1;
            __syncthreads();
        }
    }

    // Epilogue: RoPE via table + scatter. (c0,c1)=(col n,n+1) row g; (c2,c3) row g+8.
#pragma unroll
    for (int mi = 0; mi < 4; ++mi) {
#pragma unroll
        for (int ni = 0; ni < 4; ++ni) {
            int n = bn + wn + ni * 8 + 2 * t;       // even
#pragma unroll
            for (int half = 0; half < 2; ++half) {
                int m = bm + wm + mi * 16 + g + half * 8;
                int b = m >> 11, s = m & 2047;
                float c0 = acc[mi][ni][half * 2 + 0];
                float c1 = acc[mi][ni][half * 2 + 1];
                if (kind == 0) {
                    float2 cs = g_rope[(size_t)s * 512 + (n >> 1)];
                    float2 r = { c0 * cs.x - c1 * cs.y, c0 * cs.y + c1 * cs.x };
                    int h = n >> 6, d = n & 63;
                    *(float2*)(g_q + (((size_t)b * NH + h) * S_LEN + s) * HDIM + d) = r;
                } else if (kind == 1) {
                    int np = n - 1024, kvh = np >> 6, d = np & 63;
                    float2 cs = g_rope[(size_t)s * 512 + (d >> 1)];
                    float2 r = { c0 * cs.x - c1 * cs.y, c0 * cs.y + c1 * cs.x };
                    *(float2*)(g_k + (((size_t)b * NKV + kvh) * S_LEN + s) * HDIM + d) = r;
                } else {
                    int np = n - 1280, kvh = np >> 6, d = np & 63;
                    float2 r = { c0, c1 };
                    *(float2*)(g_v + (((size_t)b * NKV + kvh) * S_LEN + s) * HDIM + d) = r;
                }
            }
        }
    }
}

// ---------------------------------------------------------------------------
// Flash attention (tf32 MMA): CTA = (b, h, 128 q rows). KV tiles of 64,
// double-buffered in smem with register prefetch. P redistributed to
// A-fragment layout via quad shfl (no smem roundtrip).
// ---------------------------------------------------------------------------
#define QS_P 68   // Qs/Ks stride
#define VS_P 72   // Vs stride
#define FA_WORDS (128 * QS_P + 2 * 64 * QS_P + 2 * 64 * VS_P)
#define FA_BYTES (FA_WORDS * 4)

__global__ __launch_bounds__(256, 2) void flash_kernel()
{
    extern __shared__ unsigned sm[];
    unsigned* Qs = sm;                        // 128 x 68 (tf32)
    unsigned* Ks = Qs + 128 * QS_P;           // 2 x 64 x 68
    unsigned* Vs = Ks + 2 * 64 * QS_P;        // 2 x 64 x 72

    const int tid  = threadIdx.x;
    const int lane = tid & 31, warp = tid >> 5;
    const int g = lane >> 2, t = lane & 3;
    const int qt = blockIdx.x, h = blockIdx.y, b = blockIdx.z;
    const int kvh = h >> 2;
    const int wrow = warp * 16;

    const float* Qg = g_q + (((size_t)b * NH  + h  ) * S_LEN + qt * 128) * HDIM;
    const float* Kg = g_k + (((size_t)b * NKV + kvh) * S_LEN) * HDIM;
    const float* Vg = g_v + (((size_t)b * NKV + kvh) * S_LEN) * HDIM;

    // Load Q tile (128x64) as tf32
#pragma unroll
    for (int p = 0; p < 8; ++p) {
        int f = tid + p * 256;
        int r = f >> 4, c = (f & 15) << 2;
        float4 v = *(const float4*)&Qg[(size_t)r * HDIM + c];
        uint4 u = { f2tf(v.x), f2tf(v.y), f2tf(v.z), f2tf(v.w) };
        *(uint4*)&Qs[r * QS_P + c] = u;
    }

    const int kr = tid >> 4, kc = (tid & 15) << 2;   // rows kr+16p, cols kc..kc+3
    float4 pk[4], pv[4];
    // prologue: tile 0
#pragma unroll
    for (int p = 0; p < 4; ++p) {
        pk[p] = *(const float4*)&Kg[(size_t)(kr + 16 * p) * HDIM + kc];
        pv[p] = *(const float4*)&Vg[(size_t)(kr + 16 * p) * HDIM + kc];
    }
#pragma unroll
    for (int p = 0; p < 4; ++p) {
        uint4 uk = { f2tf(pk[p].x), f2tf(pk[p].y), f2tf(pk[p].z), f2tf(pk[p].w) };
        uint4 uv = { f2tf(pv[p].x), f2tf(pv[p].y), f2tf(pv[p].z), f2tf(pv[p].w) };
        *(uint4*)&Ks[(kr + 16 * p) * QS_P + kc] = uk;
        *(uint4*)&Vs[(kr + 16 * p) * VS_P + kc] = uv;
    }
    __syncthreads();

    float o[8][4];
#pragma unroll
    for (int j = 0; j < 8; ++j)
#pragma unroll
        for (int c = 0; c < 4; ++c) o[j][c] = 0.f;
    float m0 = -INFINITY, m1 = -INFINITY, l0 = 0.f, l1 = 0.f;
    const float scale = 0.03125f;  // 1/sqrt(1024)

    for (int kt = 0; kt < 32; ++kt) {
        const int cur = kt & 1;
        unsigned* Kc = Ks + cur * 64 * QS_P;
        unsigned* Vc = Vs + cur * 64 * VS_P;

        if (kt < 31) {
            const float* Kt = Kg + (size_t)(kt + 1) * 64 * HDIM;
            const float* Vt = Vg + (size_t)(kt + 1) * 64 * HDIM;
#pragma unroll
            for (int p = 0; p < 4; ++p) {
                pk[p] = *(const float4*)&Kt[(size_t)(kr + 16 * p) * HDIM + kc];
                pv[p] = *(const float4*)&Vt[(size_t)(kr + 16 * p) * HDIM + kc];
            }
        }

        // S = Q K^T : warp computes 16 x 64
        float s[8][4];
#pragma unroll
        for (int j = 0; j < 8; ++j)
#pragma unroll
            for (int c = 0; c < 4; ++c) s[j][c] = 0.f;

#pragma unroll
        for (int kk = 0; kk < 8; ++kk) {
            unsigned a[4];
            a[0] = Qs[(wrow + g)     * QS_P + kk * 8 + t];
            a[1] = Qs[(wrow + g + 8) * QS_P + kk * 8 + t];
            a[2] = Qs[(wrow + g)     * QS_P + kk * 8 + t + 4];
            a[3] = Qs[(wrow + g + 8) * QS_P + kk * 8 + t + 4];
#pragma unroll
            for (int j = 0; j < 8; ++j) {
                unsigned bb[2];
                bb[0] = Kc[(j * 8 + g) * QS_P + kk * 8 + t];
                bb[1] = Kc[(j * 8 + g) * QS_P + kk * 8 + t + 4];
                mma8(s[j], a, bb);
            }
        }

#pragma unroll
        for (int j = 0; j < 8; ++j)
#pragma unroll
            for (int c = 0; c < 4; ++c) s[j][c] *= scale;

        // row max (rows g and g+8), reduce over 4-lane quad
        float rm0 = -INFINITY, rm1 = -INFINITY;
#pragma unroll
        for (int j = 0; j < 8; ++j) {
            rm0 = fmaxf(rm0, fmaxf(s[j][0], s[j][1]));
            rm1 = fmaxf(rm1, fmaxf(s[j][2], s[j][3]));
        }
#pragma unroll
        for (int off = 1; off <= 2; off <<= 1) {
            rm0 = fmaxf(rm0, __shfl_xor_sync(0xffffffffu, rm0, off));
            rm1 = fmaxf(rm1, __shfl_xor_sync(0xffffffffu, rm1, off));
        }
        float nm0 = fmaxf(m0, rm0), nm1 = fmaxf(m1, rm1);
        float cf0 = __expf(m0 - nm0), cf1 = __expf(m1 - nm1);

        float rs0 = 0.f, rs1 = 0.f;
#pragma unroll
        for (int j = 0; j < 8; ++j) {
            s[j][0] = __expf(s[j][0] - nm0);
            s[j][1] = __expf(s[j][1] - nm0);
            s[j][2] = __expf(s[j][2] - nm1);
            s[j][3] = __expf(s[j][3] - nm1);
            rs0 += s[j][0] + s[j][1];
            rs1 += s[j][2] + s[j][3];
        }
#pragma unroll
        for (int off = 1; off <= 2; off <<= 1) {
            rs0 += __shfl_xor_sync(0xffffffffu, rs0, off);
            rs1 += __shfl_xor_sync(0xffffffffu, rs1, off);
        }
        l0 = l0 * cf0 + rs0;  m0 = nm0;
        l1 = l1 * cf1 + rs1;  m1 = nm1;

        // O = O*cf + P V ; P redistributed C-frag -> A-frag via quad shfl
#pragma unroll
        for (int jn = 0; jn < 8; ++jn) {
            o[jn][0] *= cf0; o[jn][1] *= cf0;
            o[jn][2] *= cf1; o[jn][3] *= cf1;
        }
        const unsigned FULL = 0xffffffffu;
        const int src_lo = (lane & 28) | (t >> 1);
        const int src_hi = src_lo + 2;
        const bool odd = (t & 1);
#pragma unroll
        for (int kk = 0; kk < 8; ++kk) {
            float x0 = __shfl_sync(FULL, s[kk][0], src_lo);
            float x1 = __shfl_sync(FULL, s[kk][1], src_lo);
            float y0 = __shfl_sync(FULL, s[kk][0], src_hi);
            float y1 = __shfl_sync(FULL, s[kk][1], src_hi);
            float z0 = __shfl_sync(FULL, s[kk][2], src_lo);
            float z1 = __shfl_sync(FULL, s[kk][3], src_lo);
            float w0 = __shfl_sync(FULL, s[kk][2], src_hi);
            float w1 = __shfl_sync(FULL, s[kk][3], src_hi);
            unsigned a[4];
            a[0] = f2tf(odd ? x1 : x0);   // P[g][8kk+t]
            a[1] = f2tf(odd ? z1 : z0);   // P[g+8][8kk+t]
            a[2] = f2tf(odd ? y1 : y0);   // P[g][8kk+t+4]
            a[3] = f2tf(odd ? w1 : w0);   // P[g+8][8kk+t+4]
#pragma unroll
            for (int jn = 0; jn < 8; ++jn) {
                unsigned bb[2];
                bb[0] = Vc[(kk * 8 + t)     * VS_P + jn * 8 + g];
                bb[1] = Vc[(kk * 8 + t + 4) * VS_P + jn * 8 + g];
                mma8(o[jn], a, bb);
            }
        }

        if (kt < 31) {
            const int nxt = cur ^ 1;
            unsigned* Kn = Ks + nxt * 64 * QS_P;
            unsigned* Vn = Vs + nxt * 64 * VS_P;
#pragma unroll
            for (int p = 0; p < 4; ++p) {
                uint4 uk = { f2tf(pk[p].x), f2tf(pk[p].y), f2tf(pk[p].z), f2tf(pk[p].w) };
                uint4 uv = { f2tf(pv[p].x), f2tf(pv[p].y), f2tf(pv[p].z), f2tf(pv[p].w) };
                *(uint4*)&Kn[(kr + 16 * p) * QS_P + kc] = uk;
                *(uint4*)&Vn[(kr + 16 * p) * VS_P + kc] = uv;
            }
            __syncthreads();
        }
    }

    // Normalize + write (b,s,D)
    float inv0 = 1.f / l0, inv1 = 1.f / l1;
    int r0 = qt * 128 + wrow + g, r1 = r0 + 8;
#pragma unroll
    for (int jn = 0; jn < 8; ++jn) {
        int col = h * HDIM + jn * 8 + 2 * t;
        float2 v0 = { o[jn][0] * inv0, o[jn][1] * inv0 };
        float2 v1 = { o[jn][2] * inv1, o[jn][3] * inv1 };
        *(float2*)&g_o[((size_t)b * S_LEN + r0) * D_MODEL + col] = v0;
        *(float2*)&g_o[((size_t)b * S_LEN + r1) * D_MODEL + col] = v1;
    }
}

// ---------------------------------------------------------------------------
// Output projection (tf32 MMA, double-buffered): g_o @ Wo(1024x1024) -> out
// ---------------------------------------------------------------------------
__global__ __launch_bounds__(256, 2) void out_gemm(
    const float* __restrict__ Wo, float* __restrict__ out)
{
    __shared__ unsigned As[2][16][GP];
    __shared__ unsigned Bs[2][16][GP];

    const int tid  = threadIdx.x;
    const int lane = tid & 31, warp = tid >> 5;
    const int g = lane >> 2, t = lane & 3;
    const int wm = (warp >> 2) * 64, wn = (warp & 3) * 32;
    const int bn = blockIdx.x * 128, bm = blockIdx.y * 128;

    const int a_row = tid >> 2, a_kc = (tid & 3) << 2;
    const int b_r   = tid >> 5, b_c  = (tid & 31) << 2;
    const float* Ap0 = g_o + (size_t)(bm + a_row) * 1024 + a_kc;
    const float* Ap1 = Ap0 + (size_t)64 * 1024;
    const float* Bq0 = Wo + (size_t)b_r * 1024 + bn + b_c;
    const float* Bq1 = Wo + (size_t)(b_r + 8) * 1024 + bn + b_c;

    float acc[4][4][4];
#pragma unroll
    for (int mi = 0; mi < 4; ++mi)
#pragma unroll
        for (int ni = 0; ni < 4; ++ni)
#pragma unroll
            for (int c = 0; c < 4; ++c) acc[mi][ni][c] = 0.f;

    float4 ra0, ra1, rb0, rb1;
    ra0 = *(const float4*)(Ap0);
    ra1 = *(const float4*)(Ap1);
    rb0 = *(const float4*)(Bq0);
    rb1 = *(const float4*)(Bq1);
    {
        As[0][a_kc + 0][a_row] = f2tf(ra0.x);
        As[0][a_kc + 1][a_row] = f2tf(ra0.y);
        As[0][a_kc + 2][a_row] = f2tf(ra0.z);
        As[0][a_kc + 3][a_row] = f2tf(ra0.w);
        As[0][a_kc + 0][a_row + 64] = f2tf(ra1.x);
        As[0][a_kc + 1][a_row + 64] = f2tf(ra1.y);
        As[0][a_kc + 2][a_row + 64] = f2tf(ra1.z);
        As[0][a_kc + 3][a_row + 64] = f2tf(ra1.w);
        uint4 u0 = { f2tf(rb0.x), f2tf(rb0.y), f2tf(rb0.z), f2tf(rb0.w) };
        uint4 u1 = { f2tf(rb1.x), f2tf(rb1.y), f2tf(rb1.z), f2tf(rb1.w) };
        *(uint4*)&Bs[0][b_r][b_c]     = u0;
        *(uint4*)&Bs[0][b_r + 8][b_c] = u1;
    }
    __syncthreads();

    for (int kt = 0; kt < 64; ++kt) {
        const int cur = kt & 1;
        if (kt < 63) {
            int ko = (kt + 1) * 16;
            ra0 = *(const float4*)(Ap0 + ko);
            ra1 = *(const float4*)(Ap1 + ko);
            rb0 = *(const float4*)(Bq0 + (size_t)ko * 1024);
            rb1 = *(const float4*)(Bq1 + (size_t)ko * 1024);
        }

#pragma unroll
        for (int kk = 0; kk < 2; ++kk) {
            unsigned a[4][4], b[4][2];
#pragma unroll
            for (int mi = 0; mi < 4; ++mi) {
                int m = wm + mi * 16 + g;
                a[mi][0] = As[cur][kk * 8 + t]    [m];
                a[mi][1] = As[cur][kk * 8 + t]    [m + 8];
                a[mi][2] = As[cur][kk * 8 + t + 4][m];
                a[mi][3] = As[cur][kk * 8 + t + 4][m + 8];
            }
#pragma unroll
            for (int ni = 0; ni < 4; ++ni) {
                int n = wn + ni * 8 + g;
                b[ni][0] = Bs[cur][kk * 8 + t]    [n];
                b[ni][1] = Bs[cur][kk * 8 + t + 4][n];
            }
#pragma unroll
            for (int mi = 0; mi < 4; ++mi)
#pragma unroll
                for (int ni = 0; ni < 4; ++ni)
                    mma8(acc[mi][ni], a[mi], b[ni]);
        }

        if (kt < 63) {
            const int nxt = cur ^ 1;
            As[nxt][a_kc + 0][a_row] = f2tf(ra0.x);
            As[nxt][a_kc + 1][a_row] = f2tf(ra0.y);
            As[nxt][a_kc + 2][a_row] = f2tf(ra0.z);
            As[nxt][a_kc + 3][a_row] = f2tf(ra0.w);
            As[nxt][a_kc + 0][a_row + 64] = f2tf(ra1.x);
            As[nxt][a_kc + 1][a_row + 64] = f2tf(ra1.y);
            As[nxt][a_kc + 2][a_row + 64] = f2tf(ra1.z);
            As[nxt][a_kc + 3][a_row + 64] = f2tf(ra1.w);
            uint4 u0 = { f2tf(rb0.x), f2tf(rb0.y), f2tf(rb0.z), f2tf(rb0.w) };
            uint4 u1 = { f2tf(rb1.x), f2tf(rb1.y), f2tf(rb1.z), f2tf(rb1.w) };
            *(uint4*)&Bs[nxt][b_r][b_c]     = u0;
            *(uint4*)&Bs[nxt][b_r + 8][b_c] = u1;
            __syncthreads();
        }
    }

#pragma unroll
    for (int mi = 0; mi < 4; ++mi)
#pragma unroll
        for (int ni = 0; ni < 4; ++ni) {
            int n = bn + wn + ni * 8 + 2 * t;
#pragma unroll
            for (int half = 0; half < 2; ++half) {
                int m = bm + wm + mi * 16 + g + half * 8;
                float2 r = { acc[mi][ni][half * 2 + 0], acc[mi][ni][half * 2 + 1] };
                *(float2*)&out[(size_t)m * 1024 + n] = r;
            }
        }
}

// ---------------------------------------------------------------------------
extern "C" void kernel_launch(void* const* d_in, const int* in_sizes, int n_in,
                              void* d_out, int out_size)
{
    const float* x  = (const float*)d_in[0];
    const float* Wq = (const float*)d_in[1];
    const float* Wk = (const float*)d_in[2];
    const float* Wv = (const float*)d_in[3];
    const float* Wo = (const float*)d_in[4];
    float* out = (float*)d_out;

    (void)in_sizes; (void)n_in; (void)out_size;

    cudaFuncSetAttribute(flash_kernel,
                         cudaFuncAttributeMaxDynamicSharedMemorySize,
                         FA_BYTES);

    rope_table<<<(S_LEN * 512) / 256, 256>>>();
    qkv_gemm<<<dim3(12, 32), 256>>>(x, Wq, Wk, Wv);
    flash_kernel<<<dim3(16, 16, 2), 256, FA_BYTES>>>();
    out_gemm<<<dim3(8, 32), 256>>>(Wo, out);
}

// round 6
// speedup vs baseline: 3.5269x; 1.0366x over previous
#include <cuda_runtime.h>
#include <math.h>

// Problem constants
#define S_LEN   2048
#define D_MODEL 1024
#define NH      16
#define NKV     4
#define HDIM    64
#define BATCH   2

// Scratch (device globals — no allocation allowed)
__device__ float g_q[(size_t)BATCH * NH  * S_LEN * HDIM]; // (b,h,s,d) roped
__device__ float g_k[(size_t)BATCH * NKV * S_LEN * HDIM]; // (b,kvh,s,d) roped
__device__ float g_v[(size_t)BATCH * NKV * S_LEN * HDIM];
__device__ float g_o[(size_t)BATCH * S_LEN * D_MODEL];    // (b,s,h*64+d)
__device__ float2 g_rope[(size_t)S_LEN * 512];            // [s][p] = (cos, sin)

// ---------------------------------------------------------------------------
// RoPE table: angle = s * theta^(-2p/1024).
// ---------------------------------------------------------------------------
__global__ __launch_bounds__(256) void rope_table()
{
    int idx = blockIdx.x * 256 + threadIdx.x;
    int s = idx >> 9, p = idx & 511;
    const double CL2 = 9.210340371976184 / 512.0; // ln(10000)/512
    double inv = exp(-(double)p * CL2);
    double ang = (double)s * inv;
    const double TWO_PI = 6.283185307179586476925;
    double r = ang - TWO_PI * rint(ang * (1.0 / TWO_PI));
    float sf, cf;
    __sincosf((float)r, &sf, &cf);
    g_rope[idx] = make_float2(cf, sf);
}

// ---------------------------------------------------------------------------
// tf32 helpers
// ---------------------------------------------------------------------------
__device__ __forceinline__ unsigned f2tf(float f) {
    unsigned u;
    asm("cvt.rna.tf32.f32 %0, %1;" : "=r"(u) : "f"(f));
    return u;
}

__device__ __forceinline__ void mma8(float* d, const unsigned* a, const unsigned* b) {
    asm volatile(
        "mma.sync.aligned.m16n8k8.row.col.f32.tf32.tf32.f32 "
        "{%0,%1,%2,%3}, {%4,%5,%6,%7}, {%8,%9}, {%0,%1,%2,%3};"
        : "+f"(d[0]), "+f"(d[1]), "+f"(d[2]), "+f"(d[3])
        : "r"(a[0]), "r"(a[1]), "r"(a[2]), "r"(a[3]),
          "r"(b[0]), "r"(b[1]));
}

// ---------------------------------------------------------------------------
// GEMM geometry: 256x128 CTA tile, BK=16, 8 warps (4x2), warp tile 64x64.
// Smem strides: AP=264 (A, 256 cols), GP=136 (B, 128 cols); both ≡8 mod 32
// so fragment LDS banks = 8t+g (conflict-free).
// ---------------------------------------------------------------------------
#define AP 264
#define GP 136
#define GEMM_SMEM_WORDS (2 * 16 * AP + 2 * 16 * GP)
#define GEMM_SMEM_BYTES (GEMM_SMEM_WORDS * 4)

// ---------------------------------------------------------------------------
// Fused QKV projection GEMM: X(4096x1024) @ [Wq|Wk|Wv](1024x1536). RoPE epi.
// ---------------------------------------------------------------------------
__global__ __launch_bounds__(256, 1) void qkv_gemm(
    const float* __restrict__ X,
    const float* __restrict__ Wq,
    const float* __restrict__ Wk,
    const float* __restrict__ Wv)
{
    extern __shared__ unsigned smg[];
    unsigned (*As)[16][AP] = (unsigned (*)[16][AP])smg;                   // [2][16][AP]
    unsigned (*Bs)[16][GP] = (unsigned (*)[16][GP])(smg + 2 * 16 * AP);   // [2][16][GP]

    const int tid  = threadIdx.x;
    const int lane = tid & 31, warp = tid >> 5;
    const int g = lane >> 2, t = lane & 3;
    const int wm = (warp >> 1) * 64, wn = (warp & 1) * 64;
    const int bn = blockIdx.x * 128, bm = blockIdx.y * 256;

    const float* Bp; int ldb, nofs, kind;
    if (bn < 1024)      { Bp = Wq; ldb = 1024; nofs = bn;        kind = 0; }
    else if (bn < 1280) { Bp = Wk; ldb = 256;  nofs = bn - 1024; kind = 1; }
    else                { Bp = Wv; ldb = 256;  nofs = bn - 1280; kind = 2; }

    // Load coordinates: A 256x16 (4 float4/thread), B 16x128 (2 float4/thread)
    const int a_row = tid >> 2, a_kc = (tid & 3) << 2;
    const int b_r   = tid >> 5, b_c  = (tid & 31) << 2;
    const float* Ap_[4];
#pragma unroll
    for (int q = 0; q < 4; ++q)
        Ap_[q] = X + (size_t)(bm + a_row + q * 64) * 1024 + a_kc;
    const float* Bq0 = Bp + (size_t)b_r * ldb + nofs + b_c;
    const float* Bq1 = Bp + (size_t)(b_r + 8) * ldb + nofs + b_c;

    float acc[4][8][4];
#pragma unroll
    for (int mi = 0; mi < 4; ++mi)
#pragma unroll
        for (int ni = 0; ni < 8; ++ni)
#pragma unroll
            for (int c = 0; c < 4; ++c) acc[mi][ni][c] = 0.f;

    float4 ra[4], rb0, rb1;
    // prologue
#pragma unroll
    for (int q = 0; q < 4; ++q) ra[q] = *(const float4*)(Ap_[q]);
    rb0 = *(const float4*)(Bq0);
    rb1 = *(const float4*)(Bq1);
#pragma unroll
    for (int q = 0; q < 4; ++q) {
        int r = a_row + q * 64;
        As[0][a_kc + 0][r] = f2tf(ra[q].x);
        As[0][a_kc + 1][r] = f2tf(ra[q].y);
        As[0][a_kc + 2][r] = f2tf(ra[q].z);
        As[0][a_kc + 3][r] = f2tf(ra[q].w);
    }
    {
        uint4 u0 = { f2tf(rb0.x), f2tf(rb0.y), f2tf(rb0.z), f2tf(rb0.w) };
        uint4 u1 = { f2tf(rb1.x), f2tf(rb1.y), f2tf(rb1.z), f2tf(rb1.w) };
        *(uint4*)&Bs[0][b_r][b_c]     = u0;
        *(uint4*)&Bs[0][b_r + 8][b_c] = u1;
    }
    __syncthreads();

    for (int kt = 0; kt < 64; ++kt) {
        const int cur = kt & 1;
        if (kt < 63) {
            int ko = (kt + 1) * 16;
#pragma unroll
            for (int q = 0; q < 4; ++q) ra[q] = *(const float4*)(Ap_[q] + ko);
            rb0 = *(const float4*)(Bq0 + (size_t)ko * ldb);
            rb1 = *(const float4*)(Bq1 + (size_t)ko * ldb);
        }

#pragma unroll
        for (int kk = 0; kk < 2; ++kk) {
            unsigned a[4][4], b[8][2];
#pragma unroll
            for (int mi = 0; mi < 4; ++mi) {
                int m = wm + mi * 16 + g;
                a[mi][0] = As[cur][kk * 8 + t]    [m];
                a[mi][1] = As[cur][kk * 8 + t]    [m + 8];
                a[mi][2] = As[cur][kk * 8 + t + 4][m];
                a[mi][3] = As[cur][kk * 8 + t + 4][m + 8];
            }
#pragma unroll
            for (int ni = 0; ni < 8; ++ni) {
                int n = wn + ni * 8 + g;
                b[ni][0] = Bs[cur][kk * 8 + t]    [n];
                b[ni][1] = Bs[cur][kk * 8 + t + 4][n];
            }
#pragma unroll
            for (int mi = 0; mi < 4; ++mi)
#pragma unroll
                for (int ni = 0; ni < 8; ++ni)
                    mma8(acc[mi][ni], a[mi], b[ni]);
        }

        if (kt < 63) {
            const int nxt = cur ^ 1;
#pragma unroll
            for (int q = 0; q < 4; ++q) {
                int r = a_row + q * 64;
                As[nxt][a_kc + 0][r] = f2tf(ra[q].x);
                As[nxt][a_kc + 1][r] = f2tf(ra[q].y);
                As[nxt][a_kc + 2][r] = f2tf(ra[q].z);
                As[nxt][a_kc + 3][r] = f2tf(ra[q].w);
            }
            uint4 u0 = { f2tf(rb0.x), f2tf(rb0.y), f2tf(rb0.z), f2tf(rb0.w) };
            uint4 u1 = { f2tf(rb1.x), f2tf(rb1.y), f2tf(rb1.z), f2tf(rb1.w) };
            *(uint4*)&Bs[nxt][b_r][b_c]     = u0;
            *(uint4*)&Bs[nxt][b_r + 8][b_c] = u1;
            __syncthreads();
        }
    }

    // Epilogue: RoPE via table + scatter.
#pragma unroll
    for (int mi = 0; mi < 4; ++mi) {
#pragma unroll
        for (int ni = 0; ni < 8; ++ni) {
            int n = bn + wn + ni * 8 + 2 * t;       // even
#pragma unroll
            for (int half = 0; half < 2; ++half) {
                int m = bm + wm + mi * 16 + g + half * 8;
                int b = m >> 11, s = m & 2047;
                float c0 = acc[mi][ni][half * 2 + 0];
                float c1 = acc[mi][ni][half * 2 + 1];
                if (kind == 0) {
                    float2 cs = g_rope[(size_t)s * 512 + (n >> 1)];
                    float2 r = { c0 * cs.x - c1 * cs.y, c0 * cs.y + c1 * cs.x };
                    int h = n >> 6, d = n & 63;
                    *(float2*)(g_q + (((size_t)b * NH + h) * S_LEN + s) * HDIM + d) = r;
                } else if (kind == 1) {
                    int np = n - 1024, kvh = np >> 6, d = np & 63;
                    float2 cs = g_rope[(size_t)s * 512 + (d >> 1)];
                    float2 r = { c0 * cs.x - c1 * cs.y, c0 * cs.y + c1 * cs.x };
                    *(float2*)(g_k + (((size_t)b * NKV + kvh) * S_LEN + s) * HDIM + d) = r;
                } else {
                    int np = n - 1280, kvh = np >> 6, d = np & 63;
                    float2 r = { c0, c1 };
                    *(float2*)(g_v + (((size_t)b * NKV + kvh) * S_LEN + s) * HDIM + d) = r;
                }
            }
        }
    }
}

// ---------------------------------------------------------------------------
// Flash attention: CTA = (b, h, 256 q rows). 8 warps x 32 q-rows (mi=0,1).
// KV tiles of 64, double-buffered. K/V fragments reused across both mi.
// ---------------------------------------------------------------------------
#define QS_P 68
#define VS_P 72
#define FA_WORDS (256 * QS_P + 2 * 64 * QS_P + 2 * 64 * VS_P)
#define FA_BYTES (FA_WORDS * 4)

__global__ __launch_bounds__(256, 1) void flash_kernel()
{
    extern __shared__ unsigned sm[];
    unsigned* Qs = sm;                        // 256 x 68 (tf32)
    unsigned* Ks = Qs + 256 * QS_P;           // 2 x 64 x 68
    unsigned* Vs = Ks + 2 * 64 * QS_P;        // 2 x 64 x 72

    const int tid  = threadIdx.x;
    const int lane = tid & 31, warp = tid >> 5;
    const int g = lane >> 2, t = lane & 3;
    const int qt = blockIdx.x, h = blockIdx.y, b = blockIdx.z;
    const int kvh = h >> 2;
    const int wrow = warp * 32;

    const float* Qg = g_q + (((size_t)b * NH  + h  ) * S_LEN + qt * 256) * HDIM;
    const float* Kg = g_k + (((size_t)b * NKV + kvh) * S_LEN) * HDIM;
    const float* Vg = g_v + (((size_t)b * NKV + kvh) * S_LEN) * HDIM;

    // Load Q tile (256x64) as tf32
#pragma unroll
    for (int p = 0; p < 16; ++p) {
        int f = tid + p * 256;
        int r = f >> 4, c = (f & 15) << 2;
        float4 v = *(const float4*)&Qg[(size_t)r * HDIM + c];
        uint4 u = { f2tf(v.x), f2tf(v.y), f2tf(v.z), f2tf(v.w) };
        *(uint4*)&Qs[r * QS_P + c] = u;
    }

    const int kr = tid >> 4, kc = (tid & 15) << 2;
    float4 pk[4], pv[4];
#pragma unroll
    for (int p = 0; p < 4; ++p) {
        pk[p] = *(const float4*)&Kg[(size_t)(kr + 16 * p) * HDIM + kc];
        pv[p] = *(const float4*)&Vg[(size_t)(kr + 16 * p) * HDIM + kc];
    }
#pragma unroll
    for (int p = 0; p < 4; ++p) {
        uint4 uk = { f2tf(pk[p].x), f2tf(pk[p].y), f2tf(pk[p].z), f2tf(pk[p].w) };
        uint4 uv = { f2tf(pv[p].x), f2tf(pv[p].y), f2tf(pv[p].z), f2tf(pv[p].w) };
        *(uint4*)&Ks[(kr + 16 * p) * QS_P + kc] = uk;
        *(uint4*)&Vs[(kr + 16 * p) * VS_P + kc] = uv;
    }
    __syncthreads();

    float o[2][8][4];
#pragma unroll
    for (int mi = 0; mi < 2; ++mi)
#pragma unroll
        for (int j = 0; j < 8; ++j)
#pragma unroll
            for (int c = 0; c < 4; ++c) o[mi][j][c] = 0.f;
    float mx[4] = {-INFINITY, -INFINITY, -INFINITY, -INFINITY};  // [2mi+half]
    float lx[4] = {0.f, 0.f, 0.f, 0.f};
    const float scale = 0.03125f;  // 1/sqrt(1024)

    const unsigned FULL = 0xffffffffu;
    const int src_lo = (lane & 28) | (t >> 1);
    const int src_hi = src_lo + 2;
    const bool odd = (t & 1);

    for (int kt = 0; kt < 32; ++kt) {
        const int cur = kt & 1;
        unsigned* Kc = Ks + cur * 64 * QS_P;
        unsigned* Vc = Vs + cur * 64 * VS_P;

        if (kt < 31) {
            const float* Kt = Kg + (size_t)(kt + 1) * 64 * HDIM;
            const float* Vt = Vg + (size_t)(kt + 1) * 64 * HDIM;
#pragma unroll
            for (int p = 0; p < 4; ++p) {
                pk[p] = *(const float4*)&Kt[(size_t)(kr + 16 * p) * HDIM + kc];
                pv[p] = *(const float4*)&Vt[(size_t)(kr + 16 * p) * HDIM + kc];
            }
        }

        // S = Q K^T : warp computes 32 x 64 (mi = 0,1)
        float s[2][8][4];
#pragma unroll
        for (int mi = 0; mi < 2; ++mi)
#pragma unroll
            for (int j = 0; j < 8; ++j)
#pragma unroll
                for (int c = 0; c < 4; ++c) s[mi][j][c] = 0.f;

#pragma unroll
        for (int kk = 0; kk < 8; ++kk) {
            unsigned a[2][4];
#pragma unroll
            for (int mi = 0; mi < 2; ++mi) {
                int r = wrow + mi * 16 + g;
                a[mi][0] = Qs[r       * QS_P + kk * 8 + t];
                a[mi][1] = Qs[(r + 8) * QS_P + kk * 8 + t];
                a[mi][2] = Qs[r       * QS_P + kk * 8 + t + 4];
                a[mi][3] = Qs[(r + 8) * QS_P + kk * 8 + t + 4];
            }
#pragma unroll
            for (int j = 0; j < 8; ++j) {
                unsigned bb[2];
                bb[0] = Kc[(j * 8 + g) * QS_P + kk * 8 + t];
                bb[1] = Kc[(j * 8 + g) * QS_P + kk * 8 + t + 4];
                mma8(s[0][j], a[0], bb);
                mma8(s[1][j], a[1], bb);
            }
        }

        // softmax per mi
        float cf[4];
#pragma unroll
        for (int mi = 0; mi < 2; ++mi) {
#pragma unroll
            for (int j = 0; j < 8; ++j)
#pragma unroll
                for (int c = 0; c < 4; ++c) s[mi][j][c] *= scale;

            float rm0 = -INFINITY, rm1 = -INFINITY;
#pragma unroll
            for (int j = 0; j < 8; ++j) {
                rm0 = fmaxf(rm0, fmaxf(s[mi][j][0], s[mi][j][1]));
                rm1 = fmaxf(rm1, fmaxf(s[mi][j][2], s[mi][j][3]));
            }
#pragma unroll
            for (int off = 1; off <= 2; off <<= 1) {
                rm0 = fmaxf(rm0, __shfl_xor_sync(FULL, rm0, off));
                rm1 = fmaxf(rm1, __shfl_xor_sync(FULL, rm1, off));
            }
            float nm0 = fmaxf(mx[2 * mi + 0], rm0);
            float nm1 = fmaxf(mx[2 * mi + 1], rm1);
            cf[2 * mi + 0] = __expf(mx[2 * mi + 0] - nm0);
            cf[2 * mi + 1] = __expf(mx[2 * mi + 1] - nm1);

            float rs0 = 0.f, rs1 = 0.f;
#pragma unroll
            for (int j = 0; j < 8; ++j) {
                s[mi][j][0] = __expf(s[mi][j][0] - nm0);
                s[mi][j][1] = __expf(s[mi][j][1] - nm0);
                s[mi][j][2] = __expf(s[mi][j][2] - nm1);
                s[mi][j][3] = __expf(s[mi][j][3] - nm1);
                rs0 += s[mi][j][0] + s[mi][j][1];
                rs1 += s[mi][j][2] + s[mi][j][3];
            }
#pragma unroll
            for (int off = 1; off <= 2; off <<= 1) {
                rs0 += __shfl_xor_sync(FULL, rs0, off);
                rs1 += __shfl_xor_sync(FULL, rs1, off);
            }
            lx[2 * mi + 0] = lx[2 * mi + 0] * cf[2 * mi + 0] + rs0;
            lx[2 * mi + 1] = lx[2 * mi + 1] * cf[2 * mi + 1] + rs1;
            mx[2 * mi + 0] = nm0;
            mx[2 * mi + 1] = nm1;
        }

        // O = O*cf + P V ; P C-frag -> A-frag via quad shfl, V frags reused
#pragma unroll
        for (int mi = 0; mi < 2; ++mi)
#pragma unroll
            for (int jn = 0; jn < 8; ++jn) {
                o[mi][jn][0] *= cf[2 * mi + 0]; o[mi][jn][1] *= cf[2 * mi + 0];
                o[mi][jn][2] *= cf[2 * mi + 1]; o[mi][jn][3] *= cf[2 * mi + 1];
            }
#pragma unroll
        for (int kk = 0; kk < 8; ++kk) {
            unsigned aP[2][4];
#pragma unroll
            for (int mi = 0; mi < 2; ++mi) {
                float x0 = __shfl_sync(FULL, s[mi][kk][0], src_lo);
                float x1 = __shfl_sync(FULL, s[mi][kk][1], src_lo);
                float y0 = __shfl_sync(FULL, s[mi][kk][0], src_hi);
                float y1 = __shfl_sync(FULL, s[mi][kk][1], src_hi);
                float z0 = __shfl_sync(FULL, s[mi][kk][2], src_lo);
                float z1 = __shfl_sync(FULL, s[mi][kk][3], src_lo);
                float w0 = __shfl_sync(FULL, s[mi][kk][2], src_hi);
                float w1 = __shfl_sync(FULL, s[mi][kk][3], src_hi);
                aP[mi][0] = f2tf(odd ? x1 : x0);
                aP[mi][1] = f2tf(odd ? z1 : z0);
                aP[mi][2] = f2tf(odd ? y1 : y0);
                aP[mi][3] = f2tf(odd ? w1 : w0);
            }
#pragma unroll
            for (int jn = 0; jn < 8; ++jn) {
                unsigned bb[2];
                bb[0] = Vc[(kk * 8 + t)     * VS_P + jn * 8 + g];
                bb[1] = Vc[(kk * 8 + t + 4) * VS_P + jn * 8 + g];
                mma8(o[0][jn], aP[0], bb);
                mma8(o[1][jn], aP[1], bb);
            }
        }

        if (kt < 31) {
            const int nxt = cur ^ 1;
            unsigned* Kn = Ks + nxt * 64 * QS_P;
            unsigned* Vn = Vs + nxt * 64 * VS_P;
#pragma unroll
            for (int p = 0; p < 4; ++p) {
                uint4 uk = { f2tf(pk[p].x), f2tf(pk[p].y), f2tf(pk[p].z), f2tf(pk[p].w) };
                uint4 uv = { f2tf(pv[p].x), f2tf(pv[p].y), f2tf(pv[p].z), f2tf(pv[p].w) };
                *(uint4*)&Kn[(kr + 16 * p) * QS_P + kc] = uk;
                *(uint4*)&Vn[(kr + 16 * p) * VS_P + kc] = uv;
            }
            __syncthreads();
        }
    }

    // Normalize + write (b,s,D)
#pragma unroll
    for (int mi = 0; mi < 2; ++mi) {
        float inv0 = 1.f / lx[2 * mi + 0], inv1 = 1.f / lx[2 * mi + 1];
        int r0 = qt * 256 + wrow + mi * 16 + g, r1 = r0 + 8;
#pragma unroll
        for (int jn = 0; jn < 8; ++jn) {
            int col = h * HDIM + jn * 8 + 2 * t;
            float2 v0 = { o[mi][jn][0] * inv0, o[mi][jn][1] * inv0 };
            float2 v1 = { o[mi][jn][2] * inv1, o[mi][jn][3] * inv1 };
            *(float2*)&g_o[((size_t)b * S_LEN + r0) * D_MODEL + col] = v0;
            *(float2*)&g_o[((size_t)b * S_LEN + r1) * D_MODEL + col] = v1;
        }
    }
}

// ---------------------------------------------------------------------------
// Output projection: g_o(4096x1024) @ Wo(1024x1024) -> out. 256x128 tile.
// ---------------------------------------------------------------------------
__global__ __launch_bounds__(256, 1) void out_gemm(
    const float* __restrict__ Wo, float* __restrict__ out)
{
    extern __shared__ unsigned smg[];
    unsigned (*As)[16][AP] = (unsigned (*)[16][AP])smg;
    unsigned (*Bs)[16][GP] = (unsigned (*)[16][GP])(smg + 2 * 16 * AP);

    const int tid  = threadIdx.x;
    const int lane = tid & 31, warp = tid >> 5;
    const int g = lane >> 2, t = lane & 3;
    const int wm = (warp >> 1) * 64, wn = (warp & 1) * 64;
    const int bn = blockIdx.x * 128, bm = blockIdx.y * 256;

    const int a_row = tid >> 2, a_kc = (tid & 3) << 2;
    const int b_r   = tid >> 5, b_c  = (tid & 31) << 2;
    const float* Ap_[4];
#pragma unroll
    for (int q = 0; q < 4; ++q)
        Ap_[q] = g_o + (size_t)(bm + a_row + q * 64) * 1024 + a_kc;
    const float* Bq0 = Wo + (size_t)b_r * 1024 + bn + b_c;
    const float* Bq1 = Wo + (size_t)(b_r + 8) * 1024 + bn + b_c;

    float acc[4][8][4];
#pragma unroll
    for (int mi = 0; mi < 4; ++mi)
#pragma unroll
        for (int ni = 0; ni < 8; ++ni)
#pragma unroll
            for (int c = 0; c < 4; ++c) acc[mi][ni][c] = 0.f;

    float4 ra[4], rb0, rb1;
#pragma unroll
    for (int q = 0; q < 4; ++q) ra[q] = *(const float4*)(Ap_[q]);
    rb0 = *(const float4*)(Bq0);
    rb1 = *(const float4*)(Bq1);
#pragma unroll
    for (int q = 0; q < 4; ++q) {
        int r = a_row + q * 64;
        As[0][a_kc + 0][r] = f2tf(ra[q].x);
        As[0][a_kc + 1][r] = f2tf(ra[q].y);
        As[0][a_kc + 2][r] = f2tf(ra[q].z);
        As[0][a_kc + 3][r] = f2tf(ra[q].w);
    }
    {
        uint4 u0 = { f2tf(rb0.x), f2tf(rb0.y), f2tf(rb0.z), f2tf(rb0.w) };
        uint4 u1 = { f2tf(rb1.x), f2tf(rb1.y), f2tf(rb1.z), f2tf(rb1.w) };
        *(uint4*)&Bs[0][b_r][b_c]     = u0;
        *(uint4*)&Bs[0][b_r + 8][b_c] = u1;
    }
    __syncthreads();

    for (int kt = 0; kt < 64; ++kt) {
        const int cur = kt & 1;
        if (kt < 63) {
            int ko = (kt + 1) * 16;
#pragma unroll
            for (int q = 0; q < 4; ++q) ra[q] = *(const float4*)(Ap_[q] + ko);
            rb0 = *(const float4*)(Bq0 + (size_t)ko * 1024);
            rb1 = *(const float4*)(Bq1 + (size_t)ko * 1024);
        }

#pragma unroll
        for (int kk = 0; kk < 2; ++kk) {
            unsigned a[4][4], b[8][2];
#pragma unroll
            for (int mi = 0; mi < 4; ++mi) {
                int m = wm + mi * 16 + g;
                a[mi][0] = As[cur][kk * 8 + t]    [m];
                a[mi][1] = As[cur][kk * 8 + t]    [m + 8];
                a[mi][2] = As[cur][kk * 8 + t + 4][m];
                a[mi][3] = As[cur][kk * 8 + t + 4][m + 8];
            }
#pragma unroll
            for (int ni = 0; ni < 8; ++ni) {
                int n = wn + ni * 8 + g;
                b[ni][0] = Bs[cur][kk * 8 + t]    [n];
                b[ni][1] = Bs[cur][kk * 8 + t + 4][n];
            }
#pragma unroll
            for (int mi = 0; mi < 4; ++mi)
#pragma unroll
                for (int ni = 0; ni < 8; ++ni)
                    mma8(acc[mi][ni], a[mi], b[ni]);
        }

        if (kt < 63) {
            const int nxt = cur ^ 1;
#pragma unroll
            for (int q = 0; q < 4; ++q) {
                int r = a_row + q * 64;
                As[nxt][a_kc + 0][r] = f2tf(ra[q].x);
                As[nxt][a_kc + 1][r] = f2tf(ra[q].y);
                As[nxt][a_kc + 2][r] = f2tf(ra[q].z);
                As[nxt][a_kc + 3][r] = f2tf(ra[q].w);
            }
            uint4 u0 = { f2tf(rb0.x), f2tf(rb0.y), f2tf(rb0.z), f2tf(rb0.w) };
            uint4 u1 = { f2tf(rb1.x), f2tf(rb1.y), f2tf(rb1.z), f2tf(rb1.w) };
            *(uint4*)&Bs[nxt][b_r][b_c]     = u0;
            *(uint4*)&Bs[nxt][b_r + 8][b_c] = u1;
            __syncthreads();
        }
    }

#pragma unroll
    for (int mi = 0; mi < 4; ++mi)
#pragma unroll
        for (int ni = 0; ni < 8; ++ni) {
            int n = bn + wn + ni * 8 + 2 * t;
#pragma unroll
            for (int half = 0; half < 2; ++half) {
                int m = bm + wm + mi * 16 + g + half * 8;
                float2 r = { acc[mi][ni][half * 2 + 0], acc[mi][ni][half * 2 + 1] };
                *(float2*)&out[(size_t)m * 1024 + n] = r;
            }
        }
}

// ---------------------------------------------------------------------------
extern "C" void kernel_launch(void* const* d_in, const int* in_sizes, int n_in,
                              void* d_out, int out_size)
{
    const float* x  = (const float*)d_in[0];
    const float* Wq = (const float*)d_in[1];
    const float* Wk = (const float*)d_in[2];
    const float* Wv = (const float*)d_in[3];
    const float* Wo = (const float*)d_in[4];
    float* out = (float*)d_out;

    (void)in_sizes; (void)n_in; (void)out_size;

    cudaFuncSetAttribute(flash_kernel,
                         cudaFuncAttributeMaxDynamicSharedMemorySize, FA_BYTES);
    cudaFuncSetAttribute(qkv_gemm,
                         cudaFuncAttributeMaxDynamicSharedMemorySize, GEMM_SMEM_BYTES);
    cudaFuncSetAttribute(out_gemm,
                         cudaFuncAttributeMaxDynamicSharedMemorySize, GEMM_SMEM_BYTES);

    rope_table<<<(S_LEN * 512) / 256, 256>>>();
    qkv_gemm<<<dim3(12, 16), 256, GEMM_SMEM_BYTES>>>(x, Wq, Wk, Wv);
    flash_kernel<<<dim3(8, 16, 2), 256, FA_BYTES>>>();
    out_gemm<<<dim3(8, 16), 256, GEMM_SMEM_BYTES>>>(Wo, out);
}

// round 10
// speedup vs baseline: 4.6129x; 1.3079x over previous
#include <cuda_runtime.h>
#include <cuda_fp16.h>
#include <math.h>
#include <stdint.h>

// Problem constants
#define S_LEN   2048
#define D_MODEL 1024
#define NH      16
#define NKV     4
#define HDIM    64
#define BATCH   2

// Scratch (device globals — no allocation allowed). All fp16 now.
__device__ __half g_q[(size_t)BATCH * NH  * S_LEN * HDIM]; // (b,h,s,d) roped
__device__ __half g_k[(size_t)BATCH * NKV * S_LEN * HDIM]; // (b,kvh,s,d) roped
__device__ __half g_v[(size_t)BATCH * NKV * S_LEN * HDIM];
__device__ __half g_o[(size_t)BATCH * S_LEN * D_MODEL];    // (b,s,h*64+d)
__device__ float2 g_rope[(size_t)S_LEN * 512];             // [s][p] = (cos, sin)
__device__ __half g_wt [(size_t)1536 * 1024];              // [n][k] = (Wq|Wk|Wv)^T
__device__ __half g_wto[(size_t)1024 * 1024];              // Wo^T

// ---------------------------------------------------------------------------
// RoPE table: angle = s * theta^(-2p/1024).
// ---------------------------------------------------------------------------
__global__ __launch_bounds__(256) void rope_table()
{
    int idx = blockIdx.x * 256 + threadIdx.x;
    int s = idx >> 9, p = idx & 511;
    const double CL2 = 9.210340371976184 / 512.0; // ln(10000)/512
    double inv = exp(-(double)p * CL2);
    double ang = (double)s * inv;
    const double TWO_PI = 6.283185307179586476925;
    double r = ang - TWO_PI * rint(ang * (1.0 / TWO_PI));
    float sf, cf;
    __sincosf((float)r, &sf, &cf);
    g_rope[idx] = make_float2(cf, sf);
}

// ---------------------------------------------------------------------------
// Weight transpose to fp16: dst[n][k] = (half)src[k][n].
// which: 0 -> g_wt (+row offset), 1 -> g_wto
// ---------------------------------------------------------------------------
__global__ __launch_bounds__(256) void transpose_w(
    const float* __restrict__ src, int cols, int row_ofs, int which)
{
    __shared__ float tile[32][33];
    __half* dst = (which ? g_wto : g_wt) + (size_t)row_ofs * 1024;
    int bx = blockIdx.x * 32;   // n base
    int by = blockIdx.y * 32;   // k base
    int tx = threadIdx.x & 31, ty = threadIdx.x >> 5;
#pragma unroll
    for (int i = 0; i < 32; i += 8)
        tile[ty + i][tx] = src[(size_t)(by + ty + i) * cols + bx + tx];
    __syncthreads();
#pragma unroll
    for (int i = 0; i < 32; i += 8)
        dst[(size_t)(bx + ty + i) * 1024 + by + tx] = __float2half_rn(tile[tx][ty + i]);
}

// ---------------------------------------------------------------------------
// fp16 m16n8k16 MMA (fp32 accumulate)
// ---------------------------------------------------------------------------
__device__ __forceinline__ void mmah(float* d, const unsigned* a, const unsigned* b) {
    asm volatile(
        "mma.sync.aligned.m16n8k16.row.col.f32.f16.f16.f32 "
        "{%0,%1,%2,%3}, {%4,%5,%6,%7}, {%8,%9}, {%0,%1,%2,%3};"
        : "+f"(d[0]), "+f"(d[1]), "+f"(d[2]), "+f"(d[3])
        : "r"(a[0]), "r"(a[1]), "r"(a[2]), "r"(a[3]),
          "r"(b[0]), "r"(b[1]));
}
__device__ __forceinline__ unsigned fh2(float lo, float hi) {
    __half2 h = __floats2half2_rn(lo, hi);   // low 16 bits = lo
    return *(unsigned*)&h;
}

// ---------------------------------------------------------------------------
// GEMM geometry: 128x128 CTA tile, BK=16 halves, 8 warps (2x4), warp 64x32.
// Smem rows padded to 24 halves (12 words: 12g+t distinct mod 32).
// ---------------------------------------------------------------------------
#define HPW 12   // words per smem row (24 halves)

// ---------------------------------------------------------------------------
// Fused QKV projection: X(4096x1024 fp32) @ Wt(1536x1024 fp16)^T. RoPE epi.
// ---------------------------------------------------------------------------
__global__ __launch_bounds__(256, 2) void qkv_gemm(const float* __restrict__ X)
{
    __shared__ __half Ash[2][128 * 24];
    __shared__ __half Bsh[2][128 * 24];

    const int tid  = threadIdx.x;
    const int lane = tid & 31, warp = tid >> 5;
    const int g = lane >> 2, t = lane & 3;
    const int wm = (warp >> 2) * 64, wn = (warp & 3) * 32;
    const int bn = blockIdx.x * 128, bm = blockIdx.y * 128;

    const int kind = (bn < 1024) ? 0 : (bn < 1280) ? 1 : 2;

    // Load coordinates
    const int a_r = tid >> 1, a_q = tid & 1;   // A: 2 float4 (kq = a_q, a_q+2)
    const int b_r = tid >> 1, b_q = tid & 1;   // B: 1 uint4 (8 halves)
    const float* Ap = X + (size_t)(bm + a_r) * 1024 + a_q * 4;
    const __half* Bp = g_wt + (size_t)(bn + b_r) * 1024 + b_q * 8;

    float acc[4][4][4];
#pragma unroll
    for (int mi = 0; mi < 4; ++mi)
#pragma unroll
        for (int ni = 0; ni < 4; ++ni)
#pragma unroll
            for (int c = 0; c < 4; ++c) acc[mi][ni][c] = 0.f;

    float4 ra0, ra1; uint4 rb;
    ra0 = *(const float4*)(Ap);
    ra1 = *(const float4*)(Ap + 8);
    rb  = *(const uint4*)(Bp);
    {
        uint2 u0 = { fh2(ra0.x, ra0.y), fh2(ra0.z, ra0.w) };
        uint2 u1 = { fh2(ra1.x, ra1.y), fh2(ra1.z, ra1.w) };
        *(uint2*)&Ash[0][a_r * 24 + a_q * 4]     = u0;
        *(uint2*)&Ash[0][a_r * 24 + a_q * 4 + 8] = u1;
        *(uint4*)&Bsh[0][b_r * 24 + b_q * 8]     = rb;
    }
    __syncthreads();

    for (int kt = 0; kt < 64; ++kt) {
        const int cur = kt & 1;
        if (kt < 63) {
            int ko = (kt + 1) * 16;
            ra0 = *(const float4*)(Ap + ko);
            ra1 = *(const float4*)(Ap + ko + 8);
            rb  = *(const uint4*)(Bp + ko);
        }

        const unsigned* Aw = (const unsigned*)&Ash[cur][0];
        const unsigned* Bw = (const unsigned*)&Bsh[cur][0];
        unsigned a[4][4], b[4][2];
#pragma unroll
        for (int mi = 0; mi < 4; ++mi) {
            int r = (wm + mi * 16 + g) * HPW + t;
            a[mi][0] = Aw[r];
            a[mi][1] = Aw[r + 8 * HPW];
            a[mi][2] = Aw[r + 4];
            a[mi][3] = Aw[r + 8 * HPW + 4];
        }
#pragma unroll
        for (int ni = 0; ni < 4; ++ni) {
            int r = (wn + ni * 8 + g) * HPW + t;
            b[ni][0] = Bw[r];
            b[ni][1] = Bw[r + 4];
        }
#pragma unroll
        for (int mi = 0; mi < 4; ++mi)
#pragma unroll
            for (int ni = 0; ni < 4; ++ni)
                mmah(acc[mi][ni], a[mi], b[ni]);

        if (kt < 63) {
            const int nxt = cur ^ 1;
            uint2 u0 = { fh2(ra0.x, ra0.y), fh2(ra0.z, ra0.w) };
            uint2 u1 = { fh2(ra1.x, ra1.y), fh2(ra1.z, ra1.w) };
            *(uint2*)&Ash[nxt][a_r * 24 + a_q * 4]     = u0;
            *(uint2*)&Ash[nxt][a_r * 24 + a_q * 4 + 8] = u1;
            *(uint4*)&Bsh[nxt][b_r * 24 + b_q * 8]     = rb;
            __syncthreads();
        }
    }

    // Epilogue: RoPE via table + scatter (fp16 stores).
#pragma unroll
    for (int mi = 0; mi < 4; ++mi) {
#pragma unroll
        for (int ni = 0; ni < 4; ++ni) {
            int n = bn + wn + ni * 8 + 2 * t;       // even
#pragma unroll
            for (int half_ = 0; half_ < 2; ++half_) {
                int m = bm + wm + mi * 16 + g + half_ * 8;
                int b_ = m >> 11, s = m & 2047;
                float c0 = acc[mi][ni][half_ * 2 + 0];
                float c1 = acc[mi][ni][half_ * 2 + 1];
                if (kind == 0) {
                    float2 cs = g_rope[(size_t)s * 512 + (n >> 1)];
                    int h = n >> 6, d = n & 63;
                    *(__half2*)(g_q + (((size_t)b_ * NH + h) * S_LEN + s) * HDIM + d) =
                        __floats2half2_rn(c0 * cs.x - c1 * cs.y, c0 * cs.y + c1 * cs.x);
                } else if (kind == 1) {
                    int np = n - 1024, kvh = np >> 6, d = np & 63;
                    float2 cs = g_rope[(size_t)s * 512 + (d >> 1)];
                    *(__half2*)(g_k + (((size_t)b_ * NKV + kvh) * S_LEN + s) * HDIM + d) =
                        __floats2half2_rn(c0 * cs.x - c1 * cs.y, c0 * cs.y + c1 * cs.x);
                } else {
                    int np = n - 1280, kvh = np >> 6, d = np & 63;
                    *(__half2*)(g_v + (((size_t)b_ * NKV + kvh) * S_LEN + s) * HDIM + d) =
                        __floats2half2_rn(c0, c1);
                }
            }
        }
    }
}

// ---------------------------------------------------------------------------
// Flash attention (fp16 m16n8k16): CTA = (b, h, 128 q rows), 8 warps x 16 rows.
// KV tiles of 64, double-buffered, V stored transposed [d][kv].
// P reuses S C-fragment directly as PV A-fragment (no shuffles).
// Smem rows 72 halves (36 words: 4g+t distinct mod 32).
// ---------------------------------------------------------------------------
#define FW 36                       // words per row
#define FH 72                       // halves per row
#define KV_H (64 * FH)              // halves per K/V buffer
#define FA_HALVES (128 * FH + 2 * KV_H + 2 * KV_H)
#define FA_BYTES (FA_HALVES * 2)

__global__ __launch_bounds__(256, 2) void flash_kernel()
{
    extern __shared__ __half fsm[];
    __half* Qs = fsm;                  // [128][72]
    __half* Ks = fsm + 128 * FH;       // [2][64][72]   (rows = kv, cols = d)
    __half* Vt = Ks + 2 * KV_H;        // [2][64][72]   (rows = d, cols = kv)

    const int tid  = threadIdx.x;
    const int lane = tid & 31, warp = tid >> 5;
    const int g = lane >> 2, t = lane & 3;
    const int qt = blockIdx.x, h = blockIdx.y, b = blockIdx.z;
    const int kvh = h >> 2;
    const int wrow = warp * 16;

    const __half* Qg = g_q + (((size_t)b * NH  + h  ) * S_LEN + qt * 128) * HDIM;
    const __half* Kg = g_k + (((size_t)b * NKV + kvh) * S_LEN) * HDIM;
    const __half* Vg = g_v + (((size_t)b * NKV + kvh) * S_LEN) * HDIM;

    // Load Q tile (128x64 halves)
#pragma unroll
    for (int p = 0; p < 4; ++p) {
        int f = tid + p * 256;
        int r = f >> 3, c8 = (f & 7) << 3;
        *(uint4*)&Qs[r * FH + c8] = *(const uint4*)&Qg[(size_t)r * HDIM + c8];
    }

    // K/V fill mapping: f -> kv row f>>3, d cols (f&7)*8..+7
    uint4 pk[2], pv[2];
#pragma unroll
    for (int i = 0; i < 2; ++i) {
        int f = tid + i * 256;
        int kv = f >> 3, c8 = (f & 7) << 3;
        pk[i] = *(const uint4*)&Kg[(size_t)kv * HDIM + c8];
        pv[i] = *(const uint4*)&Vg[(size_t)kv * HDIM + c8];
    }
#pragma unroll
    for (int i = 0; i < 2; ++i) {
        int f = tid + i * 256;
        int kv = f >> 3, c8 = (f & 7) << 3;
        *(uint4*)&Ks[kv * FH + c8] = pk[i];
        const __half* hv = (const __half*)&pv[i];
#pragma unroll
        for (int j = 0; j < 8; ++j) Vt[(c8 + j) * FH + kv] = hv[j];
    }
    __syncthreads();

    float o[8][4];
#pragma unroll
    for (int j = 0; j < 8; ++j)
#pragma unroll
        for (int c = 0; c < 4; ++c) o[j][c] = 0.f;
    float m0 = -INFINITY, m1 = -INFINITY, l0 = 0.f, l1 = 0.f;
    const float scale = 0.03125f;  // 1/sqrt(1024)
    const unsigned FULL = 0xffffffffu;

    for (int kt = 0; kt < 32; ++kt) {
        const int cur = kt & 1;
        const unsigned* Kw = (const unsigned*)(Ks + cur * KV_H);
        const unsigned* Vw = (const unsigned*)(Vt + cur * KV_H);

        if (kt < 31) {
            const __half* Kt = Kg + (size_t)(kt + 1) * 64 * HDIM;
            const __half* Vtg = Vg + (size_t)(kt + 1) * 64 * HDIM;
#pragma unroll
            for (int i = 0; i < 2; ++i) {
                int f = tid + i * 256;
                int kv = f >> 3, c8 = (f & 7) << 3;
                pk[i] = *(const uint4*)&Kt[(size_t)kv * HDIM + c8];
                pv[i] = *(const uint4*)&Vtg[(size_t)kv * HDIM + c8];
            }
        }

        // S = Q K^T : warp computes 16 x 64, 4 k16-steps
        float s[8][4];
#pragma unroll
        for (int j = 0; j < 8; ++j)
#pragma unroll
            for (int c = 0; c < 4; ++c) s[j][c] = 0.f;

        const unsigned* Qw = (const unsigned*)Qs;
#pragma unroll
        for (int kk = 0; kk < 4; ++kk) {
            unsigned a[4];
            int rq = (wrow + g) * FW + kk * 8 + t;
            a[0] = Qw[rq];
            a[1] = Qw[rq + 8 * FW];
            a[2] = Qw[rq + 4];
            a[3] = Qw[rq + 8 * FW + 4];
#pragma unroll
            for (int j = 0; j < 8; ++j) {
                int rk = (j * 8 + g) * FW + kk * 8 + t;
                unsigned bb[2] = { Kw[rk], Kw[rk + 4] };
                mmah(s[j], a, bb);
            }
        }

#pragma unroll
        for (int j = 0; j < 8; ++j)
#pragma unroll
            for (int c = 0; c < 4; ++c) s[j][c] *= scale;

        // Online softmax (rows g, g+8), reduce over 4-lane quad
        float rm0 = -INFINITY, rm1 = -INFINITY;
#pragma unroll
        for (int j = 0; j < 8; ++j) {
            rm0 = fmaxf(rm0, fmaxf(s[j][0], s[j][1]));
            rm1 = fmaxf(rm1, fmaxf(s[j][2], s[j][3]));
        }
#pragma unroll
        for (int off = 1; off <= 2; off <<= 1) {
            rm0 = fmaxf(rm0, __shfl_xor_sync(FULL, rm0, off));
            rm1 = fmaxf(rm1, __shfl_xor_sync(FULL, rm1, off));
        }
        float nm0 = fmaxf(m0, rm0), nm1 = fmaxf(m1, rm1);
        float cf0 = __expf(m0 - nm0), cf1 = __expf(m1 - nm1);

        float rs0 = 0.f, rs1 = 0.f;
#pragma unroll
        for (int j = 0; j < 8; ++j) {
            s[j][0] = __expf(s[j][0] - nm0);
            s[j][1] = __expf(s[j][1] - nm0);
            s[j][2] = __expf(s[j][2] - nm1);
            s[j][3] = __expf(s[j][3] - nm1);
            rs0 += s[j][0] + s[j][1];
            rs1 += s[j][2] + s[j][3];
        }
#pragma unroll
        for (int off = 1; off <= 2; off <<= 1) {
            rs0 += __shfl_xor_sync(FULL, rs0, off);
            rs1 += __shfl_xor_sync(FULL, rs1, off);
        }
        l0 = l0 * cf0 + rs0;  m0 = nm0;
        l1 = l1 * cf1 + rs1;  m1 = nm1;

        // O = O*cf + P V : A-fragment built directly from S C-fragments.
#pragma unroll
        for (int jn = 0; jn < 8; ++jn) {
            o[jn][0] *= cf0; o[jn][1] *= cf0;
            o[jn][2] *= cf1; o[jn][3] *= cf1;
        }
#pragma unroll
        for (int kk = 0; kk < 4; ++kk) {
            unsigned aP[4];
            aP[0] = fh2(s[2 * kk][0],     s[2 * kk][1]);      // P[g][16kk+2t..]
            aP[1] = fh2(s[2 * kk][2],     s[2 * kk][3]);      // P[g+8][...]
            aP[2] = fh2(s[2 * kk + 1][0], s[2 * kk + 1][1]);  // P[g][16kk+8+2t..]
            aP[3] = fh2(s[2 * kk + 1][2], s[2 * kk + 1][3]);
#pragma unroll
            for (int jn = 0; jn < 8; ++jn) {
                int rv = (jn * 8 + g) * FW + kk * 8 + t;
                unsigned bb[2] = { Vw[rv], Vw[rv + 4] };
                mmah(o[jn], aP, bb);
            }
        }

        if (kt < 31) {
            const int nxt = cur ^ 1;
            __half* Kn = Ks + nxt * KV_H;
            __half* Vn = Vt + nxt * KV_H;
#pragma unroll
            for (int i = 0; i < 2; ++i) {
                int f = tid + i * 256;
                int kv = f >> 3, c8 = (f & 7) << 3;
                *(uint4*)&Kn[kv * FH + c8] = pk[i];
                const __half* hv = (const __half*)&pv[i];
#pragma unroll
                for (int j = 0; j < 8; ++j) Vn[(c8 + j) * FH + kv] = hv[j];
            }
            __syncthreads();
        }
    }

    // Normalize + write (b,s,D) as fp16
    float inv0 = 1.f / l0, inv1 = 1.f / l1;
    int r0 = qt * 128 + wrow + g, r1 = r0 + 8;
#pragma unroll
    for (int jn = 0; jn < 8; ++jn) {
        int col = h * HDIM + jn * 8 + 2 * t;
        *(__half2*)&g_o[((size_t)b * S_LEN + r0) * D_MODEL + col] =
            __floats2half2_rn(o[jn][0] * inv0, o[jn][1] * inv0);
        *(__half2*)&g_o[((size_t)b * S_LEN + r1) * D_MODEL + col] =
            __floats2half2_rn(o[jn][2] * inv1, o[jn][3] * inv1);
    }
}

// ---------------------------------------------------------------------------
// Output projection: g_o(4096x1024 fp16) @ Wo^T(1024x1024 fp16) -> out fp32
// ---------------------------------------------------------------------------
__global__ __launch_bounds__(256, 2) void out_gemm(float* __restrict__ out)
{
    __shared__ __half Ash[2][128 * 24];
    __shared__ __half Bsh[2][128 * 24];

    const int tid  = threadIdx.x;
    const int lane = tid & 31, warp = tid >> 5;
    const int g = lane >> 2, t = lane & 3;
    const int wm = (warp >> 2) * 64, wn = (warp & 3) * 32;
    const int bn = blockIdx.x * 128, bm = blockIdx.y * 128;

    const int a_r = tid >> 1, a_q = tid & 1;
    const __half* Ap = g_o  + (size_t)(bm + a_r) * 1024 + a_q * 8;
    const __half* Bp = g_wto + (size_t)(bn + a_r) * 1024 + a_q * 8;

    float acc[4][4][4];
#pragma unroll
    for (int mi = 0; mi < 4; ++mi)
#pragma unroll
        for (int ni = 0; ni < 4; ++ni)
#pragma unroll
            for (int c = 0; c < 4; ++c) acc[mi][ni][c] = 0.f;

    uint4 ra, rb;
    ra = *(const uint4*)(Ap);
    rb = *(const uint4*)(Bp);
    *(uint4*)&Ash[0][a_r * 24 + a_q * 8] = ra;
    *(uint4*)&Bsh[0][a_r * 24 + a_q * 8] = rb;
    __syncthreads();

    for (int kt = 0; kt < 64; ++kt) {
        const int cur = kt & 1;
        if (kt < 63) {
            int ko = (kt + 1) * 16;
            ra = *(const uint4*)(Ap + ko);
            rb = *(const uint4*)(Bp + ko);
        }

        const unsigned* Aw = (const unsigned*)&Ash[cur][0];
        const unsigned* Bw = (const unsigned*)&Bsh[cur][0];
        unsigned a[4][4], b[4][2];
#pragma unroll
        for (int mi = 0; mi < 4; ++mi) {
            int r = (wm + mi * 16 + g) * HPW + t;
            a[mi][0] = Aw[r];
            a[mi][1] = Aw[r + 8 * HPW];
            a[mi][2] = Aw[r + 4];
            a[mi][3] = Aw[r + 8 * HPW + 4];
        }
#pragma unroll
        for (int ni = 0; ni < 4; ++ni) {
            int r = (wn + ni * 8 + g) * HPW + t;
            b[ni][0] = Bw[r];
            b[ni][1] = Bw[r + 4];
        }
#pragma unroll
        for (int mi = 0; mi < 4; ++mi)
#pragma unroll
            for (int ni = 0; ni < 4; ++ni)
                mmah(acc[mi][ni], a[mi], b[ni]);

        if (kt < 63) {
            const int nxt = cur ^ 1;
            *(uint4*)&Ash[nxt][a_r * 24 + a_q * 8] = ra;
            *(uint4*)&Bsh[nxt][a_r * 24 + a_q * 8] = rb;
            __syncthreads();
        }
    }

#pragma unroll
    for (int mi = 0; mi < 4; ++mi)
#pragma unroll
        for (int ni = 0; ni < 4; ++ni) {
            int n = bn + wn + ni * 8 + 2 * t;
#pragma unroll
            for (int half_ = 0; half_ < 2; ++half_) {
                int m = bm + wm + mi * 16 + g + half_ * 8;
                float2 r = { acc[mi][ni][half_ * 2 + 0], acc[mi][ni][half_ * 2 + 1] };
                *(float2*)&out[(size_t)m * 1024 + n] = r;
            }
        }
}

// ---------------------------------------------------------------------------
extern "C" void kernel_launch(void* const* d_in, const int* in_sizes, int n_in,
                              void* d_out, int out_size)
{
    const float* x  = (const float*)d_in[0];
    const float* Wq = (const float*)d_in[1];
    const float* Wk = (const float*)d_in[2];
    const float* Wv = (const float*)d_in[3];
    const float* Wo = (const float*)d_in[4];
    float* out = (float*)d_out;

    (void)in_sizes; (void)n_in; (void)out_size;

    cudaFuncSetAttribute(flash_kernel,
                         cudaFuncAttributeMaxDynamicSharedMemorySize, FA_BYTES);

    rope_table<<<(S_LEN * 512) / 256, 256>>>();
    transpose_w<<<dim3(32, 32), 256>>>(Wq, 1024, 0,    0);
    transpose_w<<<dim3(8,  32), 256>>>(Wk, 256,  1024, 0);
    transpose_w<<<dim3(8,  32), 256>>>(Wv, 256,  1280, 0);
    transpose_w<<<dim3(32, 32), 256>>>(Wo, 1024, 0,    1);
    qkv_gemm<<<dim3(12, 32), 256>>>(x);
    flash_kernel<<<dim3(16, 16, 2), 256, FA_BYTES>>>();
    out_gemm<<<dim3(8, 32), 256>>>(out);
}

// round 11
// speedup vs baseline: 5.4682x; 1.1854x over previous
#include <cuda_runtime.h>
#include <cuda_fp16.h>
#include <math.h>
#include <stdint.h>

// Problem constants
#define S_LEN   2048
#define D_MODEL 1024
#define NH      16
#define NKV     4
#define HDIM    64
#define BATCH   2

// Scratch (device globals — no allocation allowed). All fp16.
__device__ __half g_q[(size_t)BATCH * NH  * S_LEN * HDIM]; // (b,h,s,d) roped
__device__ __half g_k[(size_t)BATCH * NKV * S_LEN * HDIM]; // (b,kvh,s,d) roped
__device__ __half g_v[(size_t)BATCH * NKV * S_LEN * HDIM];
__device__ __half g_o[(size_t)BATCH * S_LEN * D_MODEL];    // (b,s,h*64+d)
__device__ float2 g_rope[(size_t)S_LEN * 512];             // [s][p] = (cos, sin)
__device__ __half g_wt [(size_t)1536 * 1024];              // [n][k] = (Wq|Wk|Wv)^T
__device__ __half g_wto[(size_t)1024 * 1024];              // Wo^T

// ---------------------------------------------------------------------------
// RoPE table
// ---------------------------------------------------------------------------
__global__ __launch_bounds__(256) void rope_table()
{
    int idx = blockIdx.x * 256 + threadIdx.x;
    int s = idx >> 9, p = idx & 511;
    const double CL2 = 9.210340371976184 / 512.0;
    double inv = exp(-(double)p * CL2);
    double ang = (double)s * inv;
    const double TWO_PI = 6.283185307179586476925;
    double r = ang - TWO_PI * rint(ang * (1.0 / TWO_PI));
    float sf, cf;
    __sincosf((float)r, &sf, &cf);
    g_rope[idx] = make_float2(cf, sf);
}

// ---------------------------------------------------------------------------
// Weight transpose to fp16: dst[n][k] = (half)src[k][n].
// ---------------------------------------------------------------------------
__global__ __launch_bounds__(256) void transpose_w(
    const float* __restrict__ src, int cols, int row_ofs, int which)
{
    __shared__ float tile[32][33];
    __half* dst = (which ? g_wto : g_wt) + (size_t)row_ofs * 1024;
    int bx = blockIdx.x * 32;
    int by = blockIdx.y * 32;
    int tx = threadIdx.x & 31, ty = threadIdx.x >> 5;
#pragma unroll
    for (int i = 0; i < 32; i += 8)
        tile[ty + i][tx] = src[(size_t)(by + ty + i) * cols + bx + tx];
    __syncthreads();
#pragma unroll
    for (int i = 0; i < 32; i += 8)
        dst[(size_t)(bx + ty + i) * 1024 + by + tx] = __float2half_rn(tile[tx][ty + i]);
}

// ---------------------------------------------------------------------------
// MMA / ldmatrix helpers
// ---------------------------------------------------------------------------
__device__ __forceinline__ void mmah(float* d, const unsigned* a, const unsigned* b) {
    asm volatile(
        "mma.sync.aligned.m16n8k16.row.col.f32.f16.f16.f32 "
        "{%0,%1,%2,%3}, {%4,%5,%6,%7}, {%8,%9}, {%0,%1,%2,%3};"
        : "+f"(d[0]), "+f"(d[1]), "+f"(d[2]), "+f"(d[3])
        : "r"(a[0]), "r"(a[1]), "r"(a[2]), "r"(a[3]),
          "r"(b[0]), "r"(b[1]));
}
__device__ __forceinline__ unsigned fh2(float lo, float hi) {
    __half2 h = __floats2half2_rn(lo, hi);
    return *(unsigned*)&h;
}
__device__ __forceinline__ uint32_t smem_u32(const void* p) {
    uint32_t a;
    asm("{ .reg .u64 t; cvta.to.shared.u64 t, %1; cvt.u32.u64 %0, t; }"
        : "=r"(a) : "l"(p));
    return a;
}
__device__ __forceinline__ void ldsm4(
    unsigned& r0, unsigned& r1, unsigned& r2, unsigned& r3, uint32_t a) {
    asm volatile("ldmatrix.sync.aligned.m8n8.x4.shared.b16 {%0,%1,%2,%3}, [%4];"
        : "=r"(r0), "=r"(r1), "=r"(r2), "=r"(r3) : "r"(a));
}
__device__ __forceinline__ void ldsm4t(
    unsigned& r0, unsigned& r1, unsigned& r2, unsigned& r3, uint32_t a) {
    asm volatile("ldmatrix.sync.aligned.m8n8.x4.trans.shared.b16 {%0,%1,%2,%3}, [%4];"
        : "=r"(r0), "=r"(r1), "=r"(r2), "=r"(r3) : "r"(a));
}

// ---------------------------------------------------------------------------
// GEMM geometry: 128x128 CTA, BK=16 halves, 8 warps (2x4), warp 64x32.
// Smem rows 24 halves (48B): ldmatrix 8-row groups conflict-free.
// ---------------------------------------------------------------------------
#define HROW 24   // halves per smem row

// ---------------------------------------------------------------------------
// Fused QKV projection: X(4096x1024 fp32) @ Wt^T. RoPE epilogue.
// ---------------------------------------------------------------------------
__global__ __launch_bounds__(256, 2) void qkv_gemm(const float* __restrict__ X)
{
    __shared__ __half Ash[2][128 * HROW];
    __shared__ __half Bsh[2][128 * HROW];

    const int tid  = threadIdx.x;
    const int lane = tid & 31, warp = tid >> 5;
    const int g = lane >> 2, t = lane & 3;
    const int l7 = lane & 7, lm = (lane >> 3) & 1, lh = (lane >> 4) & 1;
    const int wm = (warp >> 2) * 64, wn = (warp & 3) * 32;
    const int bn = blockIdx.x * 128, bm = blockIdx.y * 128;
    const int kind = (bn < 1024) ? 0 : (bn < 1280) ? 1 : 2;

    const int a_r = tid >> 1, a_q = tid & 1;
    const float* Ap = X + (size_t)(bm + a_r) * 1024 + a_q * 4;
    const __half* Bp = g_wt + (size_t)(bn + a_r) * 1024 + a_q * 8;

    float acc[4][4][4];
#pragma unroll
    for (int mi = 0; mi < 4; ++mi)
#pragma unroll
        for (int ni = 0; ni < 4; ++ni)
#pragma unroll
            for (int c = 0; c < 4; ++c) acc[mi][ni][c] = 0.f;

    float4 ra0, ra1; uint4 rb;
    ra0 = *(const float4*)(Ap);
    ra1 = *(const float4*)(Ap + 8);
    rb  = *(const uint4*)(Bp);
    {
        uint2 u0 = { fh2(ra0.x, ra0.y), fh2(ra0.z, ra0.w) };
        uint2 u1 = { fh2(ra1.x, ra1.y), fh2(ra1.z, ra1.w) };
        *(uint2*)&Ash[0][a_r * HROW + a_q * 4]     = u0;
        *(uint2*)&Ash[0][a_r * HROW + a_q * 4 + 8] = u1;
        *(uint4*)&Bsh[0][a_r * HROW + a_q * 8]     = rb;
    }
    __syncthreads();

    for (int kt = 0; kt < 64; ++kt) {
        const int cur = kt & 1;
        if (kt < 63) {
            int ko = (kt + 1) * 16;
            ra0 = *(const float4*)(Ap + ko);
            ra1 = *(const float4*)(Ap + ko + 8);
            rb  = *(const uint4*)(Bp + ko);
        }

        const uint32_t ab = smem_u32(&Ash[cur][0]);
        const uint32_t bb = smem_u32(&Bsh[cur][0]);
        unsigned a[4][4], b[4][2];
#pragma unroll
        for (int mi = 0; mi < 4; ++mi)
            ldsm4(a[mi][0], a[mi][1], a[mi][2], a[mi][3],
                  ab + (wm + mi * 16 + lm * 8 + l7) * 48 + lh * 16);
#pragma unroll
        for (int p = 0; p < 2; ++p) {
            unsigned r0, r1, r2, r3;
            ldsm4(r0, r1, r2, r3,
                  bb + (wn + (2 * p + lh) * 8 + l7) * 48 + lm * 16);
            b[2 * p][0] = r0; b[2 * p][1] = r1;
            b[2 * p + 1][0] = r2; b[2 * p + 1][1] = r3;
        }
#pragma unroll
        for (int mi = 0; mi < 4; ++mi)
#pragma unroll
            for (int ni = 0; ni < 4; ++ni)
                mmah(acc[mi][ni], a[mi], b[ni]);

        if (kt < 63) {
            const int nxt = cur ^ 1;
            uint2 u0 = { fh2(ra0.x, ra0.y), fh2(ra0.z, ra0.w) };
            uint2 u1 = { fh2(ra1.x, ra1.y), fh2(ra1.z, ra1.w) };
            *(uint2*)&Ash[nxt][a_r * HROW + a_q * 4]     = u0;
            *(uint2*)&Ash[nxt][a_r * HROW + a_q * 4 + 8] = u1;
            *(uint4*)&Bsh[nxt][a_r * HROW + a_q * 8]     = rb;
            __syncthreads();
        }
    }

    // Epilogue: RoPE via table + scatter (fp16 stores).
#pragma unroll
    for (int mi = 0; mi < 4; ++mi) {
#pragma unroll
        for (int ni = 0; ni < 4; ++ni) {
            int n = bn + wn + ni * 8 + 2 * t;
#pragma unroll
            for (int half_ = 0; half_ < 2; ++half_) {
                int m = bm + wm + mi * 16 + g + half_ * 8;
                int b_ = m >> 11, s = m & 2047;
                float c0 = acc[mi][ni][half_ * 2 + 0];
                float c1 = acc[mi][ni][half_ * 2 + 1];
                if (kind == 0) {
                    float2 cs = g_rope[(size_t)s * 512 + (n >> 1)];
                    int h = n >> 6, d = n & 63;
                    *(__half2*)(g_q + (((size_t)b_ * NH + h) * S_LEN + s) * HDIM + d) =
                        __floats2half2_rn(c0 * cs.x - c1 * cs.y, c0 * cs.y + c1 * cs.x);
                } else if (kind == 1) {
                    int np = n - 1024, kvh = np >> 6, d = np & 63;
                    float2 cs = g_rope[(size_t)s * 512 + (d >> 1)];
                    *(__half2*)(g_k + (((size_t)b_ * NKV + kvh) * S_LEN + s) * HDIM + d) =
                        __floats2half2_rn(c0 * cs.x - c1 * cs.y, c0 * cs.y + c1 * cs.x);
                } else {
                    int np = n - 1280, kvh = np >> 6, d = np & 63;
                    *(__half2*)(g_v + (((size_t)b_ * NKV + kvh) * S_LEN + s) * HDIM + d) =
                        __floats2half2_rn(c0, c1);
                }
            }
        }
    }
}

// ---------------------------------------------------------------------------
// Flash attention: CTA = (b, h, 256 q rows), 8 warps x 32 rows (mi=0,1).
// fp16 m16n8k16, ldmatrix fragments, V loaded via ldmatrix.trans.
// Smem rows 72 halves (144B). KV tiles 64, double-buffered, reg prefetch.
// ---------------------------------------------------------------------------
#define FH 72                          // halves per row
#define KV_H (64 * FH)
#define FA_HALVES (256 * FH + 2 * KV_H + 2 * KV_H)
#define FA_BYTES (FA_HALVES * 2)

__global__ __launch_bounds__(256) void flash_kernel()
{
    extern __shared__ __half fsm[];
    __half* Qs = fsm;                  // [256][72]
    __half* Ks = fsm + 256 * FH;       // [2][64][72]  rows = kv, cols = d
    __half* Vs = Ks + 2 * KV_H;        // [2][64][72]  rows = kv, cols = d

    const int tid  = threadIdx.x;
    const int lane = tid & 31, warp = tid >> 5;
    const int g = lane >> 2, t = lane & 3;
    const int l7 = lane & 7, lm = (lane >> 3) & 1, lh = (lane >> 4) & 1;
    const int qt = blockIdx.x, h = blockIdx.y, b = blockIdx.z;
    const int kvh = h >> 2;
    const int wrow = warp * 32;

    const __half* Qg = g_q + (((size_t)b * NH  + h  ) * S_LEN + qt * 256) * HDIM;
    const __half* Kg = g_k + (((size_t)b * NKV + kvh) * S_LEN) * HDIM;
    const __half* Vg = g_v + (((size_t)b * NKV + kvh) * S_LEN) * HDIM;

    const uint32_t qs_b = smem_u32(Qs);
    const uint32_t ks_b = smem_u32(Ks);
    const uint32_t vs_b = smem_u32(Vs);

    // Load Q tile (256x64 halves), 8 uint4/thread
#pragma unroll
    for (int p = 0; p < 8; ++p) {
        int f = tid + p * 256;
        int r = f >> 3, c8 = (f & 7) << 3;
        *(uint4*)&Qs[r * FH + c8] = *(const uint4*)&Qg[(size_t)r * HDIM + c8];
    }

    // K/V fill: f -> kv = f>>3, cols (f&7)*8
    uint4 pk[2], pv[2];
#pragma unroll
    for (int i = 0; i < 2; ++i) {
        int f = tid + i * 256;
        int kv = f >> 3, c8 = (f & 7) << 3;
        pk[i] = *(const uint4*)&Kg[(size_t)kv * HDIM + c8];
        pv[i] = *(const uint4*)&Vg[(size_t)kv * HDIM + c8];
    }
#pragma unroll
    for (int i = 0; i < 2; ++i) {
        int f = tid + i * 256;
        int kv = f >> 3, c8 = (f & 7) << 3;
        *(uint4*)&Ks[kv * FH + c8] = pk[i];
        *(uint4*)&Vs[kv * FH + c8] = pv[i];
    }
    __syncthreads();

    float o[2][8][4];
#pragma unroll
    for (int mi = 0; mi < 2; ++mi)
#pragma unroll
        for (int j = 0; j < 8; ++j)
#pragma unroll
            for (int c = 0; c < 4; ++c) o[mi][j][c] = 0.f;
    float mx[4] = {-INFINITY, -INFINITY, -INFINITY, -INFINITY};
    float lx[4] = {0.f, 0.f, 0.f, 0.f};
    const float scale = 0.03125f;
    const unsigned FULL = 0xffffffffu;

    for (int kt = 0; kt < 32; ++kt) {
        const int cur = kt & 1;
        const uint32_t kc_b = ks_b + cur * KV_H * 2;
        const uint32_t vc_b = vs_b + cur * KV_H * 2;

        if (kt < 31) {
            const __half* Kt = Kg + (size_t)(kt + 1) * 64 * HDIM;
            const __half* Vt = Vg + (size_t)(kt + 1) * 64 * HDIM;
#pragma unroll
            for (int i = 0; i < 2; ++i) {
                int f = tid + i * 256;
                int kv = f >> 3, c8 = (f & 7) << 3;
                pk[i] = *(const uint4*)&Kt[(size_t)kv * HDIM + c8];
                pv[i] = *(const uint4*)&Vt[(size_t)kv * HDIM + c8];
            }
        }

        // S = Q K^T : warp computes 32 x 64 over k=64 (4 k16 steps)
        float s[2][8][4];
#pragma unroll
        for (int mi = 0; mi < 2; ++mi)
#pragma unroll
            for (int j = 0; j < 8; ++j)
#pragma unroll
                for (int c = 0; c < 4; ++c) s[mi][j][c] = 0.f;

#pragma unroll
        for (int kk = 0; kk < 4; ++kk) {
            unsigned a[2][4];
#pragma unroll
            for (int mi = 0; mi < 2; ++mi)
                ldsm4(a[mi][0], a[mi][1], a[mi][2], a[mi][3],
                      qs_b + (wrow + mi * 16 + lm * 8 + l7) * 144 + kk * 32 + lh * 16);
#pragma unroll
            for (int p = 0; p < 4; ++p) {
                unsigned r0, r1, r2, r3;
                ldsm4(r0, r1, r2, r3,
                      kc_b + ((2 * p + lh) * 8 + l7) * 144 + kk * 32 + lm * 16);
                unsigned b0[2] = { r0, r1 }, b1[2] = { r2, r3 };
                mmah(s[0][2 * p],     a[0], b0);
                mmah(s[1][2 * p],     a[1], b0);
                mmah(s[0][2 * p + 1], a[0], b1);
                mmah(s[1][2 * p + 1], a[1], b1);
            }
        }

        // Online softmax per mi (rows g, g+8 of each 16-row block)
        float cf[4];
#pragma unroll
        for (int mi = 0; mi < 2; ++mi) {
#pragma unroll
            for (int j = 0; j < 8; ++j)
#pragma unroll
                for (int c = 0; c < 4; ++c) s[mi][j][c] *= scale;

            float rm0 = -INFINITY, rm1 = -INFINITY;
#pragma unroll
            for (int j = 0; j < 8; ++j) {
                rm0 = fmaxf(rm0, fmaxf(s[mi][j][0], s[mi][j][1]));
                rm1 = fmaxf(rm1, fmaxf(s[mi][j][2], s[mi][j][3]));
            }
#pragma unroll
            for (int off = 1; off <= 2; off <<= 1) {
                rm0 = fmaxf(rm0, __shfl_xor_sync(FULL, rm0, off));
                rm1 = fmaxf(rm1, __shfl_xor_sync(FULL, rm1, off));
            }
            float nm0 = fmaxf(mx[2 * mi + 0], rm0);
            float nm1 = fmaxf(mx[2 * mi + 1], rm1);
            cf[2 * mi + 0] = __expf(mx[2 * mi + 0] - nm0);
            cf[2 * mi + 1] = __expf(mx[2 * mi + 1] - nm1);

            float rs0 = 0.f, rs1 = 0.f;
#pragma unroll
            for (int j = 0; j < 8; ++j) {
                s[mi][j][0] = __expf(s[mi][j][0] - nm0);
                s[mi][j][1] = __expf(s[mi][j][1] - nm0);
                s[mi][j][2] = __expf(s[mi][j][2] - nm1);
                s[mi][j][3] = __expf(s[mi][j][3] - nm1);
                rs0 += s[mi][j][0] + s[mi][j][1];
                rs1 += s[mi][j][2] + s[mi][j][3];
            }
#pragma unroll
            for (int off = 1; off <= 2; off <<= 1) {
                rs0 += __shfl_xor_sync(FULL, rs0, off);
                rs1 += __shfl_xor_sync(FULL, rs1, off);
            }
            lx[2 * mi + 0] = lx[2 * mi + 0] * cf[2 * mi + 0] + rs0;
            lx[2 * mi + 1] = lx[2 * mi + 1] * cf[2 * mi + 1] + rs1;
            mx[2 * mi + 0] = nm0;
            mx[2 * mi + 1] = nm1;
        }

        // O = O*cf + P V ; P from S C-frags, V via ldmatrix.trans (shared by mi)
#pragma unroll
        for (int mi = 0; mi < 2; ++mi)
#pragma unroll
            for (int jn = 0; jn < 8; ++jn) {
                o[mi][jn][0] *= cf[2 * mi + 0]; o[mi][jn][1] *= cf[2 * mi + 0];
                o[mi][jn][2] *= cf[2 * mi + 1]; o[mi][jn][3] *= cf[2 * mi + 1];
            }
#pragma unroll
        for (int kk = 0; kk < 4; ++kk) {
            unsigned aP[2][4];
#pragma unroll
            for (int mi = 0; mi < 2; ++mi) {
                aP[mi][0] = fh2(s[mi][2 * kk][0],     s[mi][2 * kk][1]);
                aP[mi][1] = fh2(s[mi][2 * kk][2],     s[mi][2 * kk][3]);
                aP[mi][2] = fh2(s[mi][2 * kk + 1][0], s[mi][2 * kk + 1][1]);
                aP[mi][3] = fh2(s[mi][2 * kk + 1][2], s[mi][2 * kk + 1][3]);
            }
#pragma unroll
            for (int p = 0; p < 4; ++p) {
                unsigned r0, r1, r2, r3;
                ldsm4t(r0, r1, r2, r3,
                       vc_b + (kk * 16 + lm * 8 + l7) * 144 + (2 * p + lh) * 16);
                unsigned b0[2] = { r0, r1 }, b1[2] = { r2, r3 };
                mmah(o[0][2 * p],     aP[0], b0);
                mmah(o[1][2 * p],     aP[1], b0);
                mmah(o[0][2 * p + 1], aP[0], b1);
                mmah(o[1][2 * p + 1], aP[1], b1);
            }
        }

        if (kt < 31) {
            const int nxt = cur ^ 1;
            __half* Kn = Ks + nxt * KV_H;
            __half* Vn = Vs + nxt * KV_H;
#pragma unroll
            for (int i = 0; i < 2; ++i) {
                int f = tid + i * 256;
                int kv = f >> 3, c8 = (f & 7) << 3;
                *(uint4*)&Kn[kv * FH + c8] = pk[i];
                *(uint4*)&Vn[kv * FH + c8] = pv[i];
            }
            __syncthreads();
        }
    }

    // Normalize + write (b,s,D) as fp16
#pragma unroll
    for (int mi = 0; mi < 2; ++mi) {
        float inv0 = 1.f / lx[2 * mi + 0], inv1 = 1.f / lx[2 * mi + 1];
        int r0 = qt * 256 + wrow + mi * 16 + g, r1 = r0 + 8;
#pragma unroll
        for (int jn = 0; jn < 8; ++jn) {
            int col = h * HDIM + jn * 8 + 2 * t;
            *(__half2*)&g_o[((size_t)b * S_LEN + r0) * D_MODEL + col] =
                __floats2half2_rn(o[mi][jn][0] * inv0, o[mi][jn][1] * inv0);
            *(__half2*)&g_o[((size_t)b * S_LEN + r1) * D_MODEL + col] =
                __floats2half2_rn(o[mi][jn][2] * inv1, o[mi][jn][3] * inv1);
        }
    }
}

// ---------------------------------------------------------------------------
// Output projection: g_o(4096x1024 fp16) @ Wo^T -> out fp32
// ---------------------------------------------------------------------------
__global__ __launch_bounds__(256, 2) void out_gemm(float* __restrict__ out)
{
    __shared__ __half Ash[2][128 * HROW];
    __shared__ __half Bsh[2][128 * HROW];

    const int tid  = threadIdx.x;
    const int lane = tid & 31, warp = tid >> 5;
    const int g = lane >> 2, t = lane & 3;
    const int l7 = lane & 7, lm = (lane >> 3) & 1, lh = (lane >> 4) & 1;
    const int wm = (warp >> 2) * 64, wn = (warp & 3) * 32;
    const int bn = blockIdx.x * 128, bm = blockIdx.y * 128;

    const int a_r = tid >> 1, a_q = tid & 1;
    const __half* Ap = g_o   + (size_t)(bm + a_r) * 1024 + a_q * 8;
    const __half* Bp = g_wto + (size_t)(bn + a_r) * 1024 + a_q * 8;

    float acc[4][4][4];
#pragma unroll
    for (int mi = 0; mi < 4; ++mi)
#pragma unroll
        for (int ni = 0; ni < 4; ++ni)
#pragma unroll
            for (int c = 0; c < 4; ++c) acc[mi][ni][c] = 0.f;

    uint4 ra, rb;
    ra = *(const uint4*)(Ap);
    rb = *(const uint4*)(Bp);
    *(uint4*)&Ash[0][a_r * HROW + a_q * 8] = ra;
    *(uint4*)&Bsh[0][a_r * HROW + a_q * 8] = rb;
    __syncthreads();

    for (int kt = 0; kt < 64; ++kt) {
        const int cur = kt & 1;
        if (kt < 63) {
            int ko = (kt + 1) * 16;
            ra = *(const uint4*)(Ap + ko);
            rb = *(const uint4*)(Bp + ko);
        }

        const uint32_t ab = smem_u32(&Ash[cur][0]);
        const uint32_t bb = smem_u32(&Bsh[cur][0]);
        unsigned a[4][4], b[4][2];
#pragma unroll
        for (int mi = 0; mi < 4; ++mi)
            ldsm4(a[mi][0], a[mi][1], a[mi][2], a[mi][3],
                  ab + (wm + mi * 16 + lm * 8 + l7) * 48 + lh * 16);
#pragma unroll
        for (int p = 0; p < 2; ++p) {
            unsigned r0, r1, r2, r3;
            ldsm4(r0, r1, r2, r3,
                  bb + (wn + (2 * p + lh) * 8 + l7) * 48 + lm * 16);
            b[2 * p][0] = r0; b[2 * p][1] = r1;
            b[2 * p + 1][0] = r2; b[2 * p + 1][1] = r3;
        }
#pragma unroll
        for (int mi = 0; mi < 4; ++mi)
#pragma unroll
            for (int ni = 0; ni < 4; ++ni)
                mmah(acc[mi][ni], a[mi], b[ni]);

        if (kt < 63) {
            const int nxt = cur ^ 1;
            *(uint4*)&Ash[nxt][a_r * HROW + a_q * 8] = ra;
            *(uint4*)&Bsh[nxt][a_r * HROW + a_q * 8] = rb;
            __syncthreads();
        }
    }

#pragma unroll
    for (int mi = 0; mi < 4; ++mi)
#pragma unroll
        for (int ni = 0; ni < 4; ++ni) {
            int n = bn + wn + ni * 8 + 2 * t;
#pragma unroll
            for (int half_ = 0; half_ < 2; ++half_) {
                int m = bm + wm + mi * 16 + g + half_ * 8;
                float2 r = { acc[mi][ni][half_ * 2 + 0], acc[mi][ni][half_ * 2 + 1] };
                *(float2*)&out[(size_t)m * 1024 + n] = r;
            }
        }
}

// ---------------------------------------------------------------------------
extern "C" void kernel_launch(void* const* d_in, const int* in_sizes, int n_in,
                              void* d_out, int out_size)
{
    const float* x  = (const float*)d_in[0];
    const float* Wq = (const float*)d_in[1];
    const float* Wk = (const float*)d_in[2];
    const float* Wv = (const float*)d_in[3];
    const float* Wo = (const float*)d_in[4];
    float* out = (float*)d_out;

    (void)in_sizes; (void)n_in; (void)out_size;

    cudaFuncSetAttribute(flash_kernel,
                         cudaFuncAttributeMaxDynamicSharedMemorySize, FA_BYTES);

    rope_table<<<(S_LEN * 512) / 256, 256>>>();
    transpose_w<<<dim3(32, 32), 256>>>(Wq, 1024, 0,    0);
    transpose_w<<<dim3(8,  32), 256>>>(Wk, 256,  1024, 0);
    transpose_w<<<dim3(8,  32), 256>>>(Wv, 256,  1280, 0);
    transpose_w<<<dim3(32, 32), 256>>>(Wo, 1024, 0,    1);
    qkv_gemm<<<dim3(12, 32), 256>>>(x);
    flash_kernel<<<dim3(8, 16, 2), 256, FA_BYTES>>>();
    out_gemm<<<dim3(8, 32), 256>>>(out);
}

// round 12
// speedup vs baseline: 5.7546x; 1.0524x over previous
#include <cuda_runtime.h>
#include <cuda_fp16.h>
#include <math.h>
#include <stdint.h>

// Problem constants
#define S_LEN   2048
#define D_MODEL 1024
#define NH      16
#define NKV     4
#define HDIM    64
#define BATCH   2

// Scratch (device globals — no allocation allowed). All fp16.
__device__ __half g_q[(size_t)BATCH * NH  * S_LEN * HDIM]; // (b,h,s,d) roped, pre-scaled
__device__ __half g_k[(size_t)BATCH * NKV * S_LEN * HDIM]; // (b,kvh,s,d) roped
__device__ __half g_v[(size_t)BATCH * NKV * S_LEN * HDIM];
__device__ __half g_o[(size_t)BATCH * S_LEN * D_MODEL];    // (b,s,h*64+d)
__device__ float2 g_rope[(size_t)S_LEN * 512];             // [s][p] = (cos, sin)
__device__ __half g_wt [(size_t)1536 * 1024];              // [n][k] = (Wq|Wk|Wv)^T
__device__ __half g_wto[(size_t)1024 * 1024];              // Wo^T

// ---------------------------------------------------------------------------
// Fused prep kernel: rope table + 4 weight transposes, one launch.
// Block ranges: [0,4096) rope | [4096,5120) Wq | [5120,5376) Wk
//               [5376,5632) Wv | [5632,6656) Wo
// ---------------------------------------------------------------------------
__device__ __forceinline__ void do_transpose(
    const float* __restrict__ src, int cols, __half* dst,
    int bx, int by, int tx, int ty, float (*tile)[33])
{
#pragma unroll
    for (int i = 0; i < 32; i += 8)
        tile[ty + i][tx] = src[(size_t)(by + ty + i) * cols + bx + tx];
    __syncthreads();
#pragma unroll
    for (int i = 0; i < 32; i += 8)
        dst[(size_t)(bx + ty + i) * 1024 + by + tx] = __float2half_rn(tile[tx][ty + i]);
}

__global__ __launch_bounds__(256) void prep_kernel(
    const float* __restrict__ Wq, const float* __restrict__ Wk,
    const float* __restrict__ Wv, const float* __restrict__ Wo)
{
    __shared__ float tile[32][33];
    const int blk = blockIdx.x;
    const int tid = threadIdx.x;

    if (blk < 4096) {
        int idx = blk * 256 + tid;
        int s = idx >> 9, p = idx & 511;
        const double CL2 = 9.210340371976184 / 512.0;
        double inv = exp(-(double)p * CL2);
        double ang = (double)s * inv;
        const double TWO_PI = 6.283185307179586476925;
        double r = ang - TWO_PI * rint(ang * (1.0 / TWO_PI));
        float sf, cf;
        __sincosf((float)r, &sf, &cf);
        g_rope[idx] = make_float2(cf, sf);
        return;
    }

    const int tx = tid & 31, ty = tid >> 5;
    if (blk < 5120) {            // Wq: 32x32 blocks
        int r = blk - 4096;
        do_transpose(Wq, 1024, g_wt, (r & 31) * 32, (r >> 5) * 32, tx, ty, tile);
    } else if (blk < 5376) {     // Wk: 8x32 blocks
        int r = blk - 5120;
        do_transpose(Wk, 256, g_wt + (size_t)1024 * 1024, (r & 7) * 32, (r >> 3) * 32, tx, ty, tile);
    } else if (blk < 5632) {     // Wv: 8x32 blocks
        int r = blk - 5376;
        do_transpose(Wv, 256, g_wt + (size_t)1280 * 1024, (r & 7) * 32, (r >> 3) * 32, tx, ty, tile);
    } else {                     // Wo: 32x32 blocks
        int r = blk - 5632;
        do_transpose(Wo, 1024, g_wto, (r & 31) * 32, (r >> 5) * 32, tx, ty, tile);
    }
}

// ---------------------------------------------------------------------------
// MMA / ldmatrix helpers
// ---------------------------------------------------------------------------
__device__ __forceinline__ void mmah(float* d, const unsigned* a, const unsigned* b) {
    asm volatile(
        "mma.sync.aligned.m16n8k16.row.col.f32.f16.f16.f32 "
        "{%0,%1,%2,%3}, {%4,%5,%6,%7}, {%8,%9}, {%0,%1,%2,%3};"
        : "+f"(d[0]), "+f"(d[1]), "+f"(d[2]), "+f"(d[3])
        : "r"(a[0]), "r"(a[1]), "r"(a[2]), "r"(a[3]),
          "r"(b[0]), "r"(b[1]));
}
__device__ __forceinline__ unsigned fh2(float lo, float hi) {
    __half2 h = __floats2half2_rn(lo, hi);
    return *(unsigned*)&h;
}
__device__ __forceinline__ uint32_t smem_u32(const void* p) {
    uint32_t a;
    asm("{ .reg .u64 t; cvta.to.shared.u64 t, %1; cvt.u32.u64 %0, t; }"
        : "=r"(a) : "l"(p));
    return a;
}
__device__ __forceinline__ void ldsm4(
    unsigned& r0, unsigned& r1, unsigned& r2, unsigned& r3, uint32_t a) {
    asm volatile("ldmatrix.sync.aligned.m8n8.x4.shared.b16 {%0,%1,%2,%3}, [%4];"
        : "=r"(r0), "=r"(r1), "=r"(r2), "=r"(r3) : "r"(a));
}
__device__ __forceinline__ void ldsm4t(
    unsigned& r0, unsigned& r1, unsigned& r2, unsigned& r3, uint32_t a) {
    asm volatile("ldmatrix.sync.aligned.m8n8.x4.trans.shared.b16 {%0,%1,%2,%3}, [%4];"
        : "=r"(r0), "=r"(r1), "=r"(r2), "=r"(r3) : "r"(a));
}

#define HROW 24   // GEMM smem halves per row

// ---------------------------------------------------------------------------
// Fused QKV projection: X(4096x1024 fp32) @ Wt^T. RoPE epilogue.
// Q output pre-scaled by (1/sqrt(D))*log2(e) for exp2-domain softmax.
// ---------------------------------------------------------------------------
#define QSCALE 0.04508422f   // 0.03125 * 1.4426950408889634

__global__ __launch_bounds__(256, 2) void qkv_gemm(const float* __restrict__ X)
{
    __shared__ __half Ash[2][128 * HROW];
    __shared__ __half Bsh[2][128 * HROW];

    const int tid  = threadIdx.x;
    const int lane = tid & 31, warp = tid >> 5;
    const int g = lane >> 2, t = lane & 3;
    const int l7 = lane & 7, lm = (lane >> 3) & 1, lh = (lane >> 4) & 1;
    const int wm = (warp >> 2) * 64, wn = (warp & 3) * 32;
    const int bn = blockIdx.x * 128, bm = blockIdx.y * 128;
    const int kind = (bn < 1024) ? 0 : (bn < 1280) ? 1 : 2;

    const int a_r = tid >> 1, a_q = tid & 1;
    const float* Ap = X + (size_t)(bm + a_r) * 1024 + a_q * 4;
    const __half* Bp = g_wt + (size_t)(bn + a_r) * 1024 + a_q * 8;

    float acc[4][4][4];
#pragma unroll
    for (int mi = 0; mi < 4; ++mi)
#pragma unroll
        for (int ni = 0; ni < 4; ++ni)
#pragma unroll
            for (int c = 0; c < 4; ++c) acc[mi][ni][c] = 0.f;

    float4 ra0, ra1; uint4 rb;
    ra0 = *(const float4*)(Ap);
    ra1 = *(const float4*)(Ap + 8);
    rb  = *(const uint4*)(Bp);
    {
        uint2 u0 = { fh2(ra0.x, ra0.y), fh2(ra0.z, ra0.w) };
        uint2 u1 = { fh2(ra1.x, ra1.y), fh2(ra1.z, ra1.w) };
        *(uint2*)&Ash[0][a_r * HROW + a_q * 4]     = u0;
        *(uint2*)&Ash[0][a_r * HROW + a_q * 4 + 8] = u1;
        *(uint4*)&Bsh[0][a_r * HROW + a_q * 8]     = rb;
    }
    __syncthreads();

    for (int kt = 0; kt < 64; ++kt) {
        const int cur = kt & 1;
        if (kt < 63) {
            int ko = (kt + 1) * 16;
            ra0 = *(const float4*)(Ap + ko);
            ra1 = *(const float4*)(Ap + ko + 8);
            rb  = *(const uint4*)(Bp + ko);
        }

        const uint32_t ab = smem_u32(&Ash[cur][0]);
        const uint32_t bb = smem_u32(&Bsh[cur][0]);
        unsigned a[4][4], b[4][2];
#pragma unroll
        for (int mi = 0; mi < 4; ++mi)
            ldsm4(a[mi][0], a[mi][1], a[mi][2], a[mi][3],
                  ab + (wm + mi * 16 + lm * 8 + l7) * 48 + lh * 16);
#pragma unroll
        for (int p = 0; p < 2; ++p) {
            unsigned r0, r1, r2, r3;
            ldsm4(r0, r1, r2, r3,
                  bb + (wn + (2 * p + lh) * 8 + l7) * 48 + lm * 16);
            b[2 * p][0] = r0; b[2 * p][1] = r1;
            b[2 * p + 1][0] = r2; b[2 * p + 1][1] = r3;
        }
#pragma unroll
        for (int mi = 0; mi < 4; ++mi)
#pragma unroll
            for (int ni = 0; ni < 4; ++ni)
                mmah(acc[mi][ni], a[mi], b[ni]);

        if (kt < 63) {
            const int nxt = cur ^ 1;
            uint2 u0 = { fh2(ra0.x, ra0.y), fh2(ra0.z, ra0.w) };
            uint2 u1 = { fh2(ra1.x, ra1.y), fh2(ra1.z, ra1.w) };
            *(uint2*)&Ash[nxt][a_r * HROW + a_q * 4]     = u0;
            *(uint2*)&Ash[nxt][a_r * HROW + a_q * 4 + 8] = u1;
            *(uint4*)&Bsh[nxt][a_r * HROW + a_q * 8]     = rb;
            __syncthreads();
        }
    }

    // Epilogue: RoPE via table + scatter (fp16 stores). Q pre-scaled.
#pragma unroll
    for (int mi = 0; mi < 4; ++mi) {
#pragma unroll
        for (int ni = 0; ni < 4; ++ni) {
            int n = bn + wn + ni * 8 + 2 * t;
#pragma unroll
            for (int half_ = 0; half_ < 2; ++half_) {
                int m = bm + wm + mi * 16 + g + half_ * 8;
                int b_ = m >> 11, s = m & 2047;
                float c0 = acc[mi][ni][half_ * 2 + 0];
                float c1 = acc[mi][ni][half_ * 2 + 1];
                if (kind == 0) {
                    float2 cs = g_rope[(size_t)s * 512 + (n >> 1)];
                    int h = n >> 6, d = n & 63;
                    *(__half2*)(g_q + (((size_t)b_ * NH + h) * S_LEN + s) * HDIM + d) =
                        __floats2half2_rn((c0 * cs.x - c1 * cs.y) * QSCALE,
                                          (c0 * cs.y + c1 * cs.x) * QSCALE);
                } else if (kind == 1) {
                    int np = n - 1024, kvh = np >> 6, d = np & 63;
                    float2 cs = g_rope[(size_t)s * 512 + (d >> 1)];
                    *(__half2*)(g_k + (((size_t)b_ * NKV + kvh) * S_LEN + s) * HDIM + d) =
                        __floats2half2_rn(c0 * cs.x - c1 * cs.y, c0 * cs.y + c1 * cs.x);
                } else {
                    int np = n - 1280, kvh = np >> 6, d = np & 63;
                    *(__half2*)(g_v + (((size_t)b_ * NKV + kvh) * S_LEN + s) * HDIM + d) =
                        __floats2half2_rn(c0, c1);
                }
            }
        }
    }
}

// ---------------------------------------------------------------------------
// Flash attention: 128-thread CTA = (b, h, 128 q rows), 4 warps x 32 rows.
// 2 CTAs/SM. exp2-domain softmax (Q pre-scaled). Rescale-skip vote.
// ---------------------------------------------------------------------------
#define FH 72                          // halves per row
#define KV_H (64 * FH)
#define FA_HALVES (128 * FH + 2 * KV_H + 2 * KV_H)
#define FA_BYTES (FA_HALVES * 2)       // 55296

__global__ __launch_bounds__(128, 2) void flash_kernel()
{
    extern __shared__ __half fsm[];
    __half* Qs = fsm;                  // [128][72]
    __half* Ks = fsm + 128 * FH;       // [2][64][72]
    __half* Vs = Ks + 2 * KV_H;        // [2][64][72]

    const int tid  = threadIdx.x;
    const int lane = tid & 31, warp = tid >> 5;
    const int g = lane >> 2, t = lane & 3;
    const int l7 = lane & 7, lm = (lane >> 3) & 1, lh = (lane >> 4) & 1;
    const int qt = blockIdx.x, h = blockIdx.y, b = blockIdx.z;
    const int kvh = h >> 2;
    const int wrow = warp * 32;

    const __half* Qg = g_q + (((size_t)b * NH  + h  ) * S_LEN + qt * 128) * HDIM;
    const __half* Kg = g_k + (((size_t)b * NKV + kvh) * S_LEN) * HDIM;
    const __half* Vg = g_v + (((size_t)b * NKV + kvh) * S_LEN) * HDIM;

    const uint32_t qs_b = smem_u32(Qs);
    const uint32_t ks_b = smem_u32(Ks);
    const uint32_t vs_b = smem_u32(Vs);

    // Load Q tile (128x64 halves), 8 uint4/thread
#pragma unroll
    for (int p = 0; p < 8; ++p) {
        int f = tid + p * 128;
        int r = f >> 3, c8 = (f & 7) << 3;
        *(uint4*)&Qs[r * FH + c8] = *(const uint4*)&Qg[(size_t)r * HDIM + c8];
    }

    // K/V fill: 4 uint4/thread each
    uint4 pk[4], pv[4];
#pragma unroll
    for (int i = 0; i < 4; ++i) {
        int f = tid + i * 128;
        int kv = f >> 3, c8 = (f & 7) << 3;
        pk[i] = *(const uint4*)&Kg[(size_t)kv * HDIM + c8];
        pv[i] = *(const uint4*)&Vg[(size_t)kv * HDIM + c8];
    }
#pragma unroll
    for (int i = 0; i < 4; ++i) {
        int f = tid + i * 128;
        int kv = f >> 3, c8 = (f & 7) << 3;
        *(uint4*)&Ks[kv * FH + c8] = pk[i];
        *(uint4*)&Vs[kv * FH + c8] = pv[i];
    }
    __syncthreads();

    float o[2][8][4];
#pragma unroll
    for (int mi = 0; mi < 2; ++mi)
#pragma unroll
        for (int j = 0; j < 8; ++j)
#pragma unroll
            for (int c = 0; c < 4; ++c) o[mi][j][c] = 0.f;
    float mx[4] = {-INFINITY, -INFINITY, -INFINITY, -INFINITY};
    float lx[4] = {0.f, 0.f, 0.f, 0.f};
    const unsigned FULL = 0xffffffffu;

    for (int kt = 0; kt < 32; ++kt) {
        const int cur = kt & 1;
        const uint32_t kc_b = ks_b + cur * KV_H * 2;
        const uint32_t vc_b = vs_b + cur * KV_H * 2;

        if (kt < 31) {
            const __half* Kt = Kg + (size_t)(kt + 1) * 64 * HDIM;
            const __half* Vt = Vg + (size_t)(kt + 1) * 64 * HDIM;
#pragma unroll
            for (int i = 0; i < 4; ++i) {
                int f = tid + i * 128;
                int kv = f >> 3, c8 = (f & 7) << 3;
                pk[i] = *(const uint4*)&Kt[(size_t)kv * HDIM + c8];
                pv[i] = *(const uint4*)&Vt[(size_t)kv * HDIM + c8];
            }
        }

        // S = Q K^T (log2-domain; Q pre-scaled): 32 x 64 per warp
        float s[2][8][4];
#pragma unroll
        for (int mi = 0; mi < 2; ++mi)
#pragma unroll
            for (int j = 0; j < 8; ++j)
#pragma unroll
                for (int c = 0; c < 4; ++c) s[mi][j][c] = 0.f;

#pragma unroll
        for (int kk = 0; kk < 4; ++kk) {
            unsigned a[2][4];
#pragma unroll
            for (int mi = 0; mi < 2; ++mi)
                ldsm4(a[mi][0], a[mi][1], a[mi][2], a[mi][3],
                      qs_b + (wrow + mi * 16 + lm * 8 + l7) * 144 + kk * 32 + lh * 16);
#pragma unroll
            for (int p = 0; p < 4; ++p) {
                unsigned r0, r1, r2, r3;
                ldsm4(r0, r1, r2, r3,
                      kc_b + ((2 * p + lh) * 8 + l7) * 144 + kk * 32 + lm * 16);
                unsigned b0[2] = { r0, r1 }, b1[2] = { r2, r3 };
                mmah(s[0][2 * p],     a[0], b0);
                mmah(s[1][2 * p],     a[1], b0);
                mmah(s[0][2 * p + 1], a[0], b1);
                mmah(s[1][2 * p + 1], a[1], b1);
            }
        }

        // Online softmax in exp2 domain
        float cf[4];
#pragma unroll
        for (int mi = 0; mi < 2; ++mi) {
            float rm0 = -INFINITY, rm1 = -INFINITY;
#pragma unroll
            for (int j = 0; j < 8; ++j) {
                rm0 = fmaxf(rm0, fmaxf(s[mi][j][0], s[mi][j][1]));
                rm1 = fmaxf(rm1, fmaxf(s[mi][j][2], s[mi][j][3]));
            }
#pragma unroll
            for (int off = 1; off <= 2; off <<= 1) {
                rm0 = fmaxf(rm0, __shfl_xor_sync(FULL, rm0, off));
                rm1 = fmaxf(rm1, __shfl_xor_sync(FULL, rm1, off));
            }
            float nm0 = fmaxf(mx[2 * mi + 0], rm0);
            float nm1 = fmaxf(mx[2 * mi + 1], rm1);
            cf[2 * mi + 0] = exp2f(mx[2 * mi + 0] - nm0);
            cf[2 * mi + 1] = exp2f(mx[2 * mi + 1] - nm1);

            float rs0 = 0.f, rs1 = 0.f;
#pragma unroll
            for (int j = 0; j < 8; ++j) {
                s[mi][j][0] = exp2f(s[mi][j][0] - nm0);
                s[mi][j][1] = exp2f(s[mi][j][1] - nm0);
                s[mi][j][2] = exp2f(s[mi][j][2] - nm1);
                s[mi][j][3] = exp2f(s[mi][j][3] - nm1);
                rs0 += s[mi][j][0] + s[mi][j][1];
                rs1 += s[mi][j][2] + s[mi][j][3];
            }
#pragma unroll
            for (int off = 1; off <= 2; off <<= 1) {
                rs0 += __shfl_xor_sync(FULL, rs0, off);
                rs1 += __shfl_xor_sync(FULL, rs1, off);
            }
            lx[2 * mi + 0] = lx[2 * mi + 0] * cf[2 * mi + 0] + rs0;
            lx[2 * mi + 1] = lx[2 * mi + 1] * cf[2 * mi + 1] + rs1;
            mx[2 * mi + 0] = nm0;
            mx[2 * mi + 1] = nm1;
        }

        // Rescale O only if some row's max moved (exp2f(0)==1 exactly)
        bool nochg = (cf[0] == 1.f) & (cf[1] == 1.f) & (cf[2] == 1.f) & (cf[3] == 1.f);
        if (!__all_sync(FULL, nochg)) {
#pragma unroll
            for (int mi = 0; mi < 2; ++mi)
#pragma unroll
                for (int jn = 0; jn < 8; ++jn) {
                    o[mi][jn][0] *= cf[2 * mi + 0]; o[mi][jn][1] *= cf[2 * mi + 0];
                    o[mi][jn][2] *= cf[2 * mi + 1]; o[mi][jn][3] *= cf[2 * mi + 1];
                }
        }

        // O += P V ; P from S C-frags, V via ldmatrix.trans (shared across mi)
#pragma unroll
        for (int kk = 0; kk < 4; ++kk) {
            unsigned aP[2][4];
#pragma unroll
            for (int mi = 0; mi < 2; ++mi) {
                aP[mi][0] = fh2(s[mi][2 * kk][0],     s[mi][2 * kk][1]);
                aP[mi][1] = fh2(s[mi][2 * kk][2],     s[mi][2 * kk][3]);
                aP[mi][2] = fh2(s[mi][2 * kk + 1][0], s[mi][2 * kk + 1][1]);
                aP[mi][3] = fh2(s[mi][2 * kk + 1][2], s[mi][2 * kk + 1][3]);
            }
#pragma unroll
            for (int p = 0; p < 4; ++p) {
                unsigned r0, r1, r2, r3;
                ldsm4t(r0, r1, r2, r3,
                       vc_b + (kk * 16 + lm * 8 + l7) * 144 + (2 * p + lh) * 16);
                unsigned b0[2] = { r0, r1 }, b1[2] = { r2, r3 };
                mmah(o[0][2 * p],     aP[0], b0);
                mmah(o[1][2 * p],     aP[1], b0);
                mmah(o[0][2 * p + 1], aP[0], b1);
                mmah(o[1][2 * p + 1], aP[1], b1);
            }
        }

        if (kt < 31) {
            const int nxt = cur ^ 1;
            __half* Kn = Ks + nxt * KV_H;
            __half* Vn = Vs + nxt * KV_H;
#pragma unroll
            for (int i = 0; i < 4; ++i) {
                int f = tid + i * 128;
                int kv = f >> 3, c8 = (f & 7) << 3;
                *(uint4*)&Kn[kv * FH + c8] = pk[i];
                *(uint4*)&Vn[kv * FH + c8] = pv[i];
            }
            __syncthreads();
        }
    }

    // Normalize + write (b,s,D) as fp16
#pragma unroll
    for (int mi = 0; mi < 2; ++mi) {
        float inv0 = 1.f / lx[2 * mi + 0], inv1 = 1.f / lx[2 * mi + 1];
        int r0 = qt * 128 + wrow + mi * 16 + g, r1 = r0 + 8;
#pragma unroll
        for (int jn = 0; jn < 8; ++jn) {
            int col = h * HDIM + jn * 8 + 2 * t;
            *(__half2*)&g_o[((size_t)b * S_LEN + r0) * D_MODEL + col] =
                __floats2half2_rn(o[mi][jn][0] * inv0, o[mi][jn][1] * inv0);
            *(__half2*)&g_o[((size_t)b * S_LEN + r1) * D_MODEL + col] =
                __floats2half2_rn(o[mi][jn][2] * inv1, o[mi][jn][3] * inv1);
        }
    }
}

// ---------------------------------------------------------------------------
// Output projection: g_o(4096x1024 fp16) @ Wo^T -> out fp32
// ---------------------------------------------------------------------------
__global__ __launch_bounds__(256, 2) void out_gemm(float* __restrict__ out)
{
    __shared__ __half Ash[2][128 * HROW];
    __shared__ __half Bsh[2][128 * HROW];

    const int tid  = threadIdx.x;
    const int lane = tid & 31, warp = tid >> 5;
    const int g = lane >> 2, t = lane & 3;
    const int l7 = lane & 7, lm = (lane >> 3) & 1, lh = (lane >> 4) & 1;
    const int wm = (warp >> 2) * 64, wn = (warp & 3) * 32;
    const int bn = blockIdx.x * 128, bm = blockIdx.y * 128;

    const int a_r = tid >> 1, a_q = tid & 1;
    const __half* Ap = g_o   + (size_t)(bm + a_r) * 1024 + a_q * 8;
    const __half* Bp = g_wto + (size_t)(bn + a_r) * 1024 + a_q * 8;

    float acc[4][4][4];
#pragma unroll
    for (int mi = 0; mi < 4; ++mi)
#pragma unroll
        for (int ni = 0; ni < 4; ++ni)
#pragma unroll
            for (int c = 0; c < 4; ++c) acc[mi][ni][c] = 0.f;

    uint4 ra, rb;
    ra = *(const uint4*)(Ap);
    rb = *(const uint4*)(Bp);
    *(uint4*)&Ash[0][a_r * HROW + a_q * 8] = ra;
    *(uint4*)&Bsh[0][a_r * HROW + a_q * 8] = rb;
    __syncthreads();

    for (int kt = 0; kt < 64; ++kt) {
        const int cur = kt & 1;
        if (kt < 63) {
            int ko = (kt + 1) * 16;
            ra = *(const uint4*)(Ap + ko);
            rb = *(const uint4*)(Bp + ko);
        }

        const uint32_t ab = smem_u32(&Ash[cur][0]);
        const uint32_t bb = smem_u32(&Bsh[cur][0]);
        unsigned a[4][4], b[4][2];
#pragma unroll
        for (int mi = 0; mi < 4; ++mi)
            ldsm4(a[mi][0], a[mi][1], a[mi][2], a[mi][3],
                  ab + (wm + mi * 16 + lm * 8 + l7) * 48 + lh * 16);
#pragma unroll
        for (int p = 0; p < 2; ++p) {
            unsigned r0, r1, r2, r3;
            ldsm4(r0, r1, r2, r3,
                  bb + (wn + (2 * p + lh) * 8 + l7) * 48 + lm * 16);
            b[2 * p][0] = r0; b[2 * p][1] = r1;
            b[2 * p + 1][0] = r2; b[2 * p + 1][1] = r3;
        }
#pragma unroll
        for (int mi = 0; mi < 4; ++mi)
#pragma unroll
            for (int ni = 0; ni < 4; ++ni)
                mmah(acc[mi][ni], a[mi], b[ni]);

        if (kt < 63) {
            const int nxt = cur ^ 1;
            *(uint4*)&Ash[nxt][a_r * HROW + a_q * 8] = ra;
            *(uint4*)&Bsh[nxt][a_r * HROW + a_q * 8] = rb;
            __syncthreads();
        }
    }

#pragma unroll
    for (int mi = 0; mi < 4; ++mi)
#pragma unroll
        for (int ni = 0; ni < 4; ++ni) {
            int n = bn + wn + ni * 8 + 2 * t;
#pragma unroll
            for (int half_ = 0; half_ < 2; ++half_) {
                int m = bm + wm + mi * 16 + g + half_ * 8;
                float2 r = { acc[mi][ni][half_ * 2 + 0], acc[mi][ni][half_ * 2 + 1] };
                *(float2*)&out[(size_t)m * 1024 + n] = r;
            }
        }
}

// ---------------------------------------------------------------------------
extern "C" void kernel_launch(void* const* d_in, const int* in_sizes, int n_in,
                              void* d_out, int out_size)
{
    const float* x  = (const float*)d_in[0];
    const float* Wq = (const float*)d_in[1];
    const float* Wk = (const float*)d_in[2];
    const float* Wv = (const float*)d_in[3];
    const float* Wo = (const float*)d_in[4];
    float* out = (float*)d_out;

    (void)in_sizes; (void)n_in; (void)out_size;

    cudaFuncSetAttribute(flash_kernel,
                         cudaFuncAttributeMaxDynamicSharedMemorySize, FA_BYTES);

    prep_kernel<<<6656, 256>>>(Wq, Wk, Wv, Wo);
    qkv_gemm<<<dim3(12, 32), 256>>>(x);
    flash_kernel<<<dim3(16, 16, 2), 128, FA_BYTES>>>();
    out_gemm<<<dim3(8, 32), 256>>>(out);
}

// round 13
// speedup vs baseline: 6.4915x; 1.1281x over previous
#include <cuda_runtime.h>
#include <cuda_fp16.h>
#include <math.h>
#include <stdint.h>

// Problem constants
#define S_LEN   2048
#define D_MODEL 1024
#define NH      16
#define NKV     4
#define HDIM    64
#define BATCH   2

// Scratch (device globals — no allocation allowed). All fp16.
__device__ __half g_xh[(size_t)BATCH * S_LEN * D_MODEL];   // X converted to fp16
__device__ __half g_q[(size_t)BATCH * NH  * S_LEN * HDIM]; // (b,h,s,d) roped, pre-scaled
__device__ __half g_k[(size_t)BATCH * NKV * S_LEN * HDIM]; // (b,kvh,s,d) roped
__device__ __half g_v[(size_t)BATCH * NKV * S_LEN * HDIM];
__device__ __half g_o[(size_t)BATCH * S_LEN * D_MODEL];    // (b,s,h*64+d)
__device__ float2 g_rope[(size_t)S_LEN * 512];             // [s][p] = (cos, sin)
__device__ __half g_wt [(size_t)1536 * 1024];              // [n][k] = (Wq|Wk|Wv)^T
__device__ __half g_wto[(size_t)1024 * 1024];              // Wo^T

// ---------------------------------------------------------------------------
// Helpers
// ---------------------------------------------------------------------------
__device__ __forceinline__ void mmah(float* d, const unsigned* a, const unsigned* b) {
    asm volatile(
        "mma.sync.aligned.m16n8k16.row.col.f32.f16.f16.f32 "
        "{%0,%1,%2,%3}, {%4,%5,%6,%7}, {%8,%9}, {%0,%1,%2,%3};"
        : "+f"(d[0]), "+f"(d[1]), "+f"(d[2]), "+f"(d[3])
        : "r"(a[0]), "r"(a[1]), "r"(a[2]), "r"(a[3]),
          "r"(b[0]), "r"(b[1]));
}
__device__ __forceinline__ unsigned fh2(float lo, float hi) {
    __half2 h = __floats2half2_rn(lo, hi);
    return *(unsigned*)&h;
}
__device__ __forceinline__ uint32_t smem_u32(const void* p) {
    uint32_t a;
    asm("{ .reg .u64 t; cvta.to.shared.u64 t, %1; cvt.u32.u64 %0, t; }"
        : "=r"(a) : "l"(p));
    return a;
}
__device__ __forceinline__ void ldsm4(
    unsigned& r0, unsigned& r1, unsigned& r2, unsigned& r3, uint32_t a) {
    asm volatile("ldmatrix.sync.aligned.m8n8.x4.shared.b16 {%0,%1,%2,%3}, [%4];"
        : "=r"(r0), "=r"(r1), "=r"(r2), "=r"(r3) : "r"(a));
}
__device__ __forceinline__ void ldsm4t(
    unsigned& r0, unsigned& r1, unsigned& r2, unsigned& r3, uint32_t a) {
    asm volatile("ldmatrix.sync.aligned.m8n8.x4.trans.shared.b16 {%0,%1,%2,%3}, [%4];"
        : "=r"(r0), "=r"(r1), "=r"(r2), "=r"(r3) : "r"(a));
}
__device__ __forceinline__ void cpa16(uint32_t dst, const void* src) {
    asm volatile("cp.async.cg.shared.global [%0], [%1], 16;"
                 :: "r"(dst), "l"(src) : "memory");
}
#define CPA_COMMIT() asm volatile("cp.async.commit_group;" ::: "memory")
#define CPA_WAIT0()  asm volatile("cp.async.wait_group 0;" ::: "memory")

// ---------------------------------------------------------------------------
// Fused prep: rope table + 4 weight transposes + X fp16 conversion.
// Blocks: [0,4096) rope | [4096,5120) Wq | [5120,5376) Wk | [5376,5632) Wv
//         [5632,6656) Wo | [6656,8704) X convert
// ---------------------------------------------------------------------------
__device__ __forceinline__ void do_transpose(
    const float* __restrict__ src, int cols, __half* dst,
    int bx, int by, int tx, int ty, float (*tile)[33])
{
#pragma unroll
    for (int i = 0; i < 32; i += 8)
        tile[ty + i][tx] = src[(size_t)(by + ty + i) * cols + bx + tx];
    __syncthreads();
#pragma unroll
    for (int i = 0; i < 32; i += 8)
        dst[(size_t)(bx + ty + i) * 1024 + by + tx] = __float2half_rn(tile[tx][ty + i]);
}

__global__ __launch_bounds__(256) void prep_kernel(
    const float* __restrict__ X,
    const float* __restrict__ Wq, const float* __restrict__ Wk,
    const float* __restrict__ Wv, const float* __restrict__ Wo)
{
    __shared__ float tile[32][33];
    const int blk = blockIdx.x;
    const int tid = threadIdx.x;

    if (blk < 4096) {
        int idx = blk * 256 + tid;
        int s = idx >> 9, p = idx & 511;
        const double CL2 = 9.210340371976184 / 512.0;
        double inv = exp(-(double)p * CL2);
        double ang = (double)s * inv;
        const double TWO_PI = 6.283185307179586476925;
        double r = ang - TWO_PI * rint(ang * (1.0 / TWO_PI));
        float sf, cf;
        __sincosf((float)r, &sf, &cf);
        g_rope[idx] = make_float2(cf, sf);
        return;
    }
    if (blk >= 6656) {
        // X convert: 2048 elements per block, 8 per thread
        size_t base = (size_t)(blk - 6656) * 2048 + tid * 8;
        float4 v0 = *(const float4*)(X + base);
        float4 v1 = *(const float4*)(X + base + 4);
        uint4 u = { fh2(v0.x, v0.y), fh2(v0.z, v0.w),
                    fh2(v1.x, v1.y), fh2(v1.z, v1.w) };
        *(uint4*)(g_xh + base) = u;
        return;
    }

    const int tx = tid & 31, ty = tid >> 5;
    if (blk < 5120) {
        int r = blk - 4096;
        do_transpose(Wq, 1024, g_wt, (r & 31) * 32, (r >> 5) * 32, tx, ty, tile);
    } else if (blk < 5376) {
        int r = blk - 5120;
        do_transpose(Wk, 256, g_wt + (size_t)1024 * 1024, (r & 7) * 32, (r >> 3) * 32, tx, ty, tile);
    } else if (blk < 5632) {
        int r = blk - 5376;
        do_transpose(Wv, 256, g_wt + (size_t)1280 * 1024, (r & 7) * 32, (r >> 3) * 32, tx, ty, tile);
    } else {
        int r = blk - 5632;
        do_transpose(Wo, 1024, g_wto, (r & 31) * 32, (r >> 5) * 32, tx, ty, tile);
    }
}

#define HROW 24   // GEMM smem halves per row (48B = 3x16B)

// ---------------------------------------------------------------------------
// Generic fp16 GEMM core: C(128x128) = A[M][1024] @ B[N][1024]^T, cp.async
// fills, double buffer. Used by qkv (RoPE epi) and out projection.
// ---------------------------------------------------------------------------
#define QSCALE 0.04508422f   // (1/32) * log2(e)

__global__ __launch_bounds__(256, 2) void qkv_gemm()
{
    __shared__ __half Ash[2][128 * HROW];
    __shared__ __half Bsh[2][128 * HROW];

    const int tid  = threadIdx.x;
    const int lane = tid & 31, warp = tid >> 5;
    const int g = lane >> 2, t = lane & 3;
    const int l7 = lane & 7, lm = (lane >> 3) & 1, lh = (lane >> 4) & 1;
    const int wm = (warp >> 2) * 64, wn = (warp & 3) * 32;
    const int bn = blockIdx.x * 128, bm = blockIdx.y * 128;
    const int kind = (bn < 1024) ? 0 : (bn < 1280) ? 1 : 2;

    const int a_r = tid >> 1, a_c = (tid & 1) * 8;
    const __half* Ap = g_xh + (size_t)(bm + a_r) * 1024 + a_c;
    const __half* Bp = g_wt + (size_t)(bn + a_r) * 1024 + a_c;
    const uint32_t as_off = (a_r * HROW + a_c) * 2;
    const uint32_t asb[2] = { smem_u32(&Ash[0][0]) + as_off, smem_u32(&Ash[1][0]) + as_off };
    const uint32_t bsb[2] = { smem_u32(&Bsh[0][0]) + as_off, smem_u32(&Bsh[1][0]) + as_off };

    float acc[4][4][4];
#pragma unroll
    for (int mi = 0; mi < 4; ++mi)
#pragma unroll
        for (int ni = 0; ni < 4; ++ni)
#pragma unroll
            for (int c = 0; c < 4; ++c) acc[mi][ni][c] = 0.f;

    cpa16(asb[0], Ap);
    cpa16(bsb[0], Bp);
    CPA_COMMIT();
    CPA_WAIT0();
    __syncthreads();

    for (int kt = 0; kt < 64; ++kt) {
        const int cur = kt & 1;
        if (kt < 63) {
            int ko = (kt + 1) * 16;
            cpa16(asb[cur ^ 1], Ap + ko);
            cpa16(bsb[cur ^ 1], Bp + ko);
            CPA_COMMIT();
        }

        const uint32_t ab = smem_u32(&Ash[cur][0]);
        const uint32_t bb = smem_u32(&Bsh[cur][0]);
        unsigned a[4][4], b[4][2];
#pragma unroll
        for (int mi = 0; mi < 4; ++mi)
            ldsm4(a[mi][0], a[mi][1], a[mi][2], a[mi][3],
                  ab + (wm + mi * 16 + lm * 8 + l7) * 48 + lh * 16);
#pragma unroll
        for (int p = 0; p < 2; ++p) {
            unsigned r0, r1, r2, r3;
            ldsm4(r0, r1, r2, r3,
                  bb + (wn + (2 * p + lh) * 8 + l7) * 48 + lm * 16);
            b[2 * p][0] = r0; b[2 * p][1] = r1;
            b[2 * p + 1][0] = r2; b[2 * p + 1][1] = r3;
        }
#pragma unroll
        for (int mi = 0; mi < 4; ++mi)
#pragma unroll
            for (int ni = 0; ni < 4; ++ni)
                mmah(acc[mi][ni], a[mi], b[ni]);

        if (kt < 63) {
            CPA_WAIT0();
            __syncthreads();
        }
    }

    // Epilogue: RoPE via table + scatter (fp16 stores). Q pre-scaled.
#pragma unroll
    for (int mi = 0; mi < 4; ++mi) {
#pragma unroll
        for (int ni = 0; ni < 4; ++ni) {
            int n = bn + wn + ni * 8 + 2 * t;
#pragma unroll
            for (int half_ = 0; half_ < 2; ++half_) {
                int m = bm + wm + mi * 16 + g + half_ * 8;
                int b_ = m >> 11, s = m & 2047;
                float c0 = acc[mi][ni][half_ * 2 + 0];
                float c1 = acc[mi][ni][half_ * 2 + 1];
                if (kind == 0) {
                    float2 cs = g_rope[(size_t)s * 512 + (n >> 1)];
                    int h = n >> 6, d = n & 63;
                    *(__half2*)(g_q + (((size_t)b_ * NH + h) * S_LEN + s) * HDIM + d) =
                        __floats2half2_rn((c0 * cs.x - c1 * cs.y) * QSCALE,
                                          (c0 * cs.y + c1 * cs.x) * QSCALE);
                } else if (kind == 1) {
                    int np = n - 1024, kvh = np >> 6, d = np & 63;
                    float2 cs = g_rope[(size_t)s * 512 + (d >> 1)];
                    *(__half2*)(g_k + (((size_t)b_ * NKV + kvh) * S_LEN + s) * HDIM + d) =
                        __floats2half2_rn(c0 * cs.x - c1 * cs.y, c0 * cs.y + c1 * cs.x);
                } else {
                    int np = n - 1280, kvh = np >> 6, d = np & 63;
                    *(__half2*)(g_v + (((size_t)b_ * NKV + kvh) * S_LEN + s) * HDIM + d) =
                        __floats2half2_rn(c0, c1);
                }
            }
        }
    }
}

// ---------------------------------------------------------------------------
// Flash attention: 128-thread CTA = (b, h, 128 q rows), 4 warps x 32 rows,
// 2 CTAs/SM, cp.async K/V double buffer, exp2-domain softmax, rescale skip.
// ---------------------------------------------------------------------------
#define FH 72
#define KV_H (64 * FH)
#define FA_HALVES (128 * FH + 2 * KV_H + 2 * KV_H)
#define FA_BYTES (FA_HALVES * 2)       // 55296

__global__ __launch_bounds__(128, 2) void flash_kernel()
{
    extern __shared__ __half fsm[];
    __half* Qs = fsm;                  // [128][72]
    __half* Ks = fsm + 128 * FH;       // [2][64][72]
    __half* Vs = Ks + 2 * KV_H;        // [2][64][72]

    const int tid  = threadIdx.x;
    const int lane = tid & 31, warp = tid >> 5;
    const int g = lane >> 2, t = lane & 3;
    const int l7 = lane & 7, lm = (lane >> 3) & 1, lh = (lane >> 4) & 1;
    const int qt = blockIdx.x, h = blockIdx.y, b = blockIdx.z;
    const int kvh = h >> 2;
    const int wrow = warp * 32;

    const __half* Qg = g_q + (((size_t)b * NH  + h  ) * S_LEN + qt * 128) * HDIM;
    const __half* Kg = g_k + (((size_t)b * NKV + kvh) * S_LEN) * HDIM;
    const __half* Vg = g_v + (((size_t)b * NKV + kvh) * S_LEN) * HDIM;

    const uint32_t qs_b = smem_u32(Qs);
    const uint32_t ks_b = smem_u32(Ks);
    const uint32_t vs_b = smem_u32(Vs);

    // cp.async fills: Q 8 chunks/thread; K/V 4 chunks/thread per tile
#pragma unroll
    for (int p = 0; p < 8; ++p) {
        int f = tid + p * 128;
        int r = f >> 3, c8 = (f & 7) << 3;
        cpa16(qs_b + (r * FH + c8) * 2, Qg + (size_t)r * HDIM + c8);
    }
#pragma unroll
    for (int i = 0; i < 4; ++i) {
        int f = tid + i * 128;
        int kv = f >> 3, c8 = (f & 7) << 3;
        cpa16(ks_b + (kv * FH + c8) * 2, Kg + (size_t)kv * HDIM + c8);
        cpa16(vs_b + (kv * FH + c8) * 2, Vg + (size_t)kv * HDIM + c8);
    }
    CPA_COMMIT();
    CPA_WAIT0();
    __syncthreads();

    float o[2][8][4];
#pragma unroll
    for (int mi = 0; mi < 2; ++mi)
#pragma unroll
        for (int j = 0; j < 8; ++j)
#pragma unroll
            for (int c = 0; c < 4; ++c) o[mi][j][c] = 0.f;
    float mx[4] = {-INFINITY, -INFINITY, -INFINITY, -INFINITY};
    float lx[4] = {0.f, 0.f, 0.f, 0.f};
    const unsigned FULL = 0xffffffffu;

    for (int kt = 0; kt < 32; ++kt) {
        const int cur = kt & 1;
        const uint32_t kc_b = ks_b + cur * KV_H * 2;
        const uint32_t vc_b = vs_b + cur * KV_H * 2;

        if (kt < 31) {
            const int nxt = cur ^ 1;
            const __half* Kt = Kg + (size_t)(kt + 1) * 64 * HDIM;
            const __half* Vt = Vg + (size_t)(kt + 1) * 64 * HDIM;
            const uint32_t kn_b = ks_b + nxt * KV_H * 2;
            const uint32_t vn_b = vs_b + nxt * KV_H * 2;
#pragma unroll
            for (int i = 0; i < 4; ++i) {
                int f = tid + i * 128;
                int kv = f >> 3, c8 = (f & 7) << 3;
                cpa16(kn_b + (kv * FH + c8) * 2, Kt + (size_t)kv * HDIM + c8);
                cpa16(vn_b + (kv * FH + c8) * 2, Vt + (size_t)kv * HDIM + c8);
            }
            CPA_COMMIT();
        }

        // S = Q K^T (log2-domain; Q pre-scaled): 32 x 64 per warp
        float s[2][8][4];
#pragma unroll
        for (int mi = 0; mi < 2; ++mi)
#pragma unroll
            for (int j = 0; j < 8; ++j)
#pragma unroll
                for (int c = 0; c < 4; ++c) s[mi][j][c] = 0.f;

#pragma unroll
        for (int kk = 0; kk < 4; ++kk) {
            unsigned a[2][4];
#pragma unroll
            for (int mi = 0; mi < 2; ++mi)
                ldsm4(a[mi][0], a[mi][1], a[mi][2], a[mi][3],
                      qs_b + (wrow + mi * 16 + lm * 8 + l7) * 144 + kk * 32 + lh * 16);
#pragma unroll
            for (int p = 0; p < 4; ++p) {
                unsigned r0, r1, r2, r3;
                ldsm4(r0, r1, r2, r3,
                      kc_b + ((2 * p + lh) * 8 + l7) * 144 + kk * 32 + lm * 16);
                unsigned b0[2] = { r0, r1 }, b1[2] = { r2, r3 };
                mmah(s[0][2 * p],     a[0], b0);
                mmah(s[1][2 * p],     a[1], b0);
                mmah(s[0][2 * p + 1], a[0], b1);
                mmah(s[1][2 * p + 1], a[1], b1);
            }
        }

        // Online softmax in exp2 domain
        float cf[4];
#pragma unroll
        for (int mi = 0; mi < 2; ++mi) {
            float rm0 = -INFINITY, rm1 = -INFINITY;
#pragma unroll
            for (int j = 0; j < 8; ++j) {
                rm0 = fmaxf(rm0, fmaxf(s[mi][j][0], s[mi][j][1]));
                rm1 = fmaxf(rm1, fmaxf(s[mi][j][2], s[mi][j][3]));
            }
#pragma unroll
            for (int off = 1; off <= 2; off <<= 1) {
                rm0 = fmaxf(rm0, __shfl_xor_sync(FULL, rm0, off));
                rm1 = fmaxf(rm1, __shfl_xor_sync(FULL, rm1, off));
            }
            float nm0 = fmaxf(mx[2 * mi + 0], rm0);
            float nm1 = fmaxf(mx[2 * mi + 1], rm1);
            cf[2 * mi + 0] = exp2f(mx[2 * mi + 0] - nm0);
            cf[2 * mi + 1] = exp2f(mx[2 * mi + 1] - nm1);

            float rs0 = 0.f, rs1 = 0.f;
#pragma unroll
            for (int j = 0; j < 8; ++j) {
                s[mi][j][0] = exp2f(s[mi][j][0] - nm0);
                s[mi][j][1] = exp2f(s[mi][j][1] - nm0);
                s[mi][j][2] = exp2f(s[mi][j][2] - nm1);
                s[mi][j][3] = exp2f(s[mi][j][3] - nm1);
                rs0 += s[mi][j][0] + s[mi][j][1];
                rs1 += s[mi][j][2] + s[mi][j][3];
            }
#pragma unroll
            for (int off = 1; off <= 2; off <<= 1) {
                rs0 += __shfl_xor_sync(FULL, rs0, off);
                rs1 += __shfl_xor_sync(FULL, rs1, off);
            }
            lx[2 * mi + 0] = lx[2 * mi + 0] * cf[2 * mi + 0] + rs0;
            lx[2 * mi + 1] = lx[2 * mi + 1] * cf[2 * mi + 1] + rs1;
            mx[2 * mi + 0] = nm0;
            mx[2 * mi + 1] = nm1;
        }

        // Rescale O only if some row's max moved (exp2f(0)==1 exactly)
        bool nochg = (cf[0] == 1.f) & (cf[1] == 1.f) & (cf[2] == 1.f) & (cf[3] == 1.f);
        if (!__all_sync(FULL, nochg)) {
#pragma unroll
            for (int mi = 0; mi < 2; ++mi)
#pragma unroll
                for (int jn = 0; jn < 8; ++jn) {
                    o[mi][jn][0] *= cf[2 * mi + 0]; o[mi][jn][1] *= cf[2 * mi + 0];
                    o[mi][jn][2] *= cf[2 * mi + 1]; o[mi][jn][3] *= cf[2 * mi + 1];
                }
        }

        // O += P V ; P from S C-frags, V via ldmatrix.trans (shared across mi)
#pragma unroll
        for (int kk = 0; kk < 4; ++kk) {
            unsigned aP[2][4];
#pragma unroll
            for (int mi = 0; mi < 2; ++mi) {
                aP[mi][0] = fh2(s[mi][2 * kk][0],     s[mi][2 * kk][1]);
                aP[mi][1] = fh2(s[mi][2 * kk][2],     s[mi][2 * kk][3]);
                aP[mi][2] = fh2(s[mi][2 * kk + 1][0], s[mi][2 * kk + 1][1]);
                aP[mi][3] = fh2(s[mi][2 * kk + 1][2], s[mi][2 * kk + 1][3]);
            }
#pragma unroll
            for (int p = 0; p < 4; ++p) {
                unsigned r0, r1, r2, r3;
                ldsm4t(r0, r1, r2, r3,
                       vc_b + (kk * 16 + lm * 8 + l7) * 144 + (2 * p + lh) * 16);
                unsigned b0[2] = { r0, r1 }, b1[2] = { r2, r3 };
                mmah(o[0][2 * p],     aP[0], b0);
                mmah(o[1][2 * p],     aP[1], b0);
                mmah(o[0][2 * p + 1], aP[0], b1);
                mmah(o[1][2 * p + 1], aP[1], b1);
            }
        }

        if (kt < 31) {
            CPA_WAIT0();
            __syncthreads();
        }
    }

    // Normalize + write (b,s,D) as fp16
#pragma unroll
    for (int mi = 0; mi < 2; ++mi) {
        float inv0 = 1.f / lx[2 * mi + 0], inv1 = 1.f / lx[2 * mi + 1];
        int r0 = qt * 128 + wrow + mi * 16 + g, r1 = r0 + 8;
#pragma unroll
        for (int jn = 0; jn < 8; ++jn) {
            int col = h * HDIM + jn * 8 + 2 * t;
            *(__half2*)&g_o[((size_t)b * S_LEN + r0) * D_MODEL + col] =
                __floats2half2_rn(o[mi][jn][0] * inv0, o[mi][jn][1] * inv0);
            *(__half2*)&g_o[((size_t)b * S_LEN + r1) * D_MODEL + col] =
                __floats2half2_rn(o[mi][jn][2] * inv1, o[mi][jn][3] * inv1);
        }
    }
}

// ---------------------------------------------------------------------------
// Output projection: g_o(4096x1024 fp16) @ Wo^T -> out fp32. cp.async fills.
// ---------------------------------------------------------------------------
__global__ __launch_bounds__(256, 2) void out_gemm(float* __restrict__ out)
{
    __shared__ __half Ash[2][128 * HROW];
    __shared__ __half Bsh[2][128 * HROW];

    const int tid  = threadIdx.x;
    const int lane = tid & 31, warp = tid >> 5;
    const int g = lane >> 2, t = lane & 3;
    const int l7 = lane & 7, lm = (lane >> 3) & 1, lh = (lane >> 4) & 1;
    const int wm = (warp >> 2) * 64, wn = (warp & 3) * 32;
    const int bn = blockIdx.x * 128, bm = blockIdx.y * 128;

    const int a_r = tid >> 1, a_c = (tid & 1) * 8;
    const __half* Ap = g_o   + (size_t)(bm + a_r) * 1024 + a_c;
    const __half* Bp = g_wto + (size_t)(bn + a_r) * 1024 + a_c;
    const uint32_t as_off = (a_r * HROW + a_c) * 2;
    const uint32_t asb[2] = { smem_u32(&Ash[0][0]) + as_off, smem_u32(&Ash[1][0]) + as_off };
    const uint32_t bsb[2] = { smem_u32(&Bsh[0][0]) + as_off, smem_u32(&Bsh[1][0]) + as_off };

    float acc[4][4][4];
#pragma unroll
    for (int mi = 0; mi < 4; ++mi)
#pragma unroll
        for (int ni = 0; ni < 4; ++ni)
#pragma unroll
            for (int c = 0; c < 4; ++c) acc[mi][ni][c] = 0.f;

    cpa16(asb[0], Ap);
    cpa16(bsb[0], Bp);
    CPA_COMMIT();
    CPA_WAIT0();
    __syncthreads();

    for (int kt = 0; kt < 64; ++kt) {
        const int cur = kt & 1;
        if (kt < 63) {
            int ko = (kt + 1) * 16;
            cpa16(asb[cur ^ 1], Ap + ko);
            cpa16(bsb[cur ^ 1], Bp + ko);
            CPA_COMMIT();
        }

        const uint32_t ab = smem_u32(&Ash[cur][0]);
        const uint32_t bb = smem_u32(&Bsh[cur][0]);
        unsigned a[4][4], b[4][2];
#pragma unroll
        for (int mi = 0; mi < 4; ++mi)
            ldsm4(a[mi][0], a[mi][1], a[mi][2], a[mi][3],
                  ab + (wm + mi * 16 + lm * 8 + l7) * 48 + lh * 16);
#pragma unroll
        for (int p = 0; p < 2; ++p) {
            unsigned r0, r1, r2, r3;
            ldsm4(r0, r1, r2, r3,
                  bb + (wn + (2 * p + lh) * 8 + l7) * 48 + lm * 16);
            b[2 * p][0] = r0; b[2 * p][1] = r1;
            b[2 * p + 1][0] = r2; b[2 * p + 1][1] = r3;
        }
#pragma unroll
        for (int mi = 0; mi < 4; ++mi)
#pragma unroll
            for (int ni = 0; ni < 4; ++ni)
                mmah(acc[mi][ni], a[mi], b[ni]);

        if (kt < 63) {
            CPA_WAIT0();
            __syncthreads();
        }
    }

#pragma unroll
    for (int mi = 0; mi < 4; ++mi)
#pragma unroll
        for (int ni = 0; ni < 4; ++ni) {
            int n = bn + wn + ni * 8 + 2 * t;
#pragma unroll
            for (int half_ = 0; half_ < 2; ++half_) {
                int m = bm + wm + mi * 16 + g + half_ * 8;
                float2 r = { acc[mi][ni][half_ * 2 + 0], acc[mi][ni][half_ * 2 + 1] };
                *(float2*)&out[(size_t)m * 1024 + n] = r;
            }
        }
}

// ---------------------------------------------------------------------------
extern "C" void kernel_launch(void* const* d_in, const int* in_sizes, int n_in,
                              void* d_out, int out_size)
{
    const float* x  = (const float*)d_in[0];
    const float* Wq = (const float*)d_in[1];
    const float* Wk = (const float*)d_in[2];
    const float* Wv = (const float*)d_in[3];
    const float* Wo = (const float*)d_in[4];
    float* out = (float*)d_out;

    (void)in_sizes; (void)n_in; (void)out_size;

    cudaFuncSetAttribute(flash_kernel,
                         cudaFuncAttributeMaxDynamicSharedMemorySize, FA_BYTES);

    prep_kernel<<<8704, 256>>>(x, Wq, Wk, Wv, Wo);
    qkv_gemm<<<dim3(12, 32), 256>>>();
    flash_kernel<<<dim3(16, 16, 2), 128, FA_BYTES>>>();
    out_gemm<<<dim3(8, 32), 256>>>(out);
}

// round 14
// speedup vs baseline: 7.0461x; 1.0854x over previous
#include <cuda_runtime.h>
#include <cuda_fp16.h>
#include <math.h>
#include <stdint.h>

// Problem constants
#define S_LEN   2048
#define D_MODEL 1024
#define NH      16
#define NKV     4
#define HDIM    64
#define BATCH   2

// Scratch (device globals — no allocation allowed). All fp16.
__device__ __half g_xh[(size_t)BATCH * S_LEN * D_MODEL];   // X converted to fp16
__device__ __half g_q[(size_t)BATCH * NH  * S_LEN * HDIM]; // (b,h,s,d) roped, pre-scaled
__device__ __half g_k[(size_t)BATCH * NKV * S_LEN * HDIM]; // (b,kvh,s,d) roped
__device__ __half g_v[(size_t)BATCH * NKV * S_LEN * HDIM];
__device__ __half g_o[(size_t)BATCH * S_LEN * D_MODEL];    // (b,s,h*64+d)
__device__ float2 g_rope[(size_t)S_LEN * 512];             // [s][p] = (cos, sin)
__device__ __half g_wt [(size_t)1536 * 1024];              // [n][k] = (Wq|Wk|Wv)^T
__device__ __half g_wto[(size_t)1024 * 1024];              // Wo^T

// ---------------------------------------------------------------------------
// Helpers
// ---------------------------------------------------------------------------
__device__ __forceinline__ void mmah(float* d, const unsigned* a, const unsigned* b) {
    asm volatile(
        "mma.sync.aligned.m16n8k16.row.col.f32.f16.f16.f32 "
        "{%0,%1,%2,%3}, {%4,%5,%6,%7}, {%8,%9}, {%0,%1,%2,%3};"
        : "+f"(d[0]), "+f"(d[1]), "+f"(d[2]), "+f"(d[3])
        : "r"(a[0]), "r"(a[1]), "r"(a[2]), "r"(a[3]),
          "r"(b[0]), "r"(b[1]));
}
__device__ __forceinline__ unsigned fh2(float lo, float hi) {
    __half2 h = __floats2half2_rn(lo, hi);
    return *(unsigned*)&h;
}
__device__ __forceinline__ unsigned h2exp2u(unsigned x) {
    unsigned r;
    asm("ex2.approx.f16x2 %0, %1;" : "=r"(r) : "r"(x));
    return r;
}
__device__ __forceinline__ uint32_t smem_u32(const void* p) {
    uint32_t a;
    asm("{ .reg .u64 t; cvta.to.shared.u64 t, %1; cvt.u32.u64 %0, t; }"
        : "=r"(a) : "l"(p));
    return a;
}
__device__ __forceinline__ void ldsm4(
    unsigned& r0, unsigned& r1, unsigned& r2, unsigned& r3, uint32_t a) {
    asm volatile("ldmatrix.sync.aligned.m8n8.x4.shared.b16 {%0,%1,%2,%3}, [%4];"
        : "=r"(r0), "=r"(r1), "=r"(r2), "=r"(r3) : "r"(a));
}
__device__ __forceinline__ void ldsm4t(
    unsigned& r0, unsigned& r1, unsigned& r2, unsigned& r3, uint32_t a) {
    asm volatile("ldmatrix.sync.aligned.m8n8.x4.trans.shared.b16 {%0,%1,%2,%3}, [%4];"
        : "=r"(r0), "=r"(r1), "=r"(r2), "=r"(r3) : "r"(a));
}
__device__ __forceinline__ void cpa16(uint32_t dst, const void* src) {
    asm volatile("cp.async.cg.shared.global [%0], [%1], 16;"
                 :: "r"(dst), "l"(src) : "memory");
}
#define CPA_COMMIT() asm volatile("cp.async.commit_group;" ::: "memory")
#define CPA_WAIT0()  asm volatile("cp.async.wait_group 0;" ::: "memory")
#define CPA_WAIT1()  asm volatile("cp.async.wait_group 1;" ::: "memory")

// ---------------------------------------------------------------------------
// Fused prep: rope table + 4 weight transposes + X fp16 conversion.
// ---------------------------------------------------------------------------
__device__ __forceinline__ void do_transpose(
    const float* __restrict__ src, int cols, __half* dst,
    int bx, int by, int tx, int ty, float (*tile)[33])
{
#pragma unroll
    for (int i = 0; i < 32; i += 8)
        tile[ty + i][tx] = src[(size_t)(by + ty + i) * cols + bx + tx];
    __syncthreads();
#pragma unroll
    for (int i = 0; i < 32; i += 8)
        dst[(size_t)(bx + ty + i) * 1024 + by + tx] = __float2half_rn(tile[tx][ty + i]);
}

__global__ __launch_bounds__(256) void prep_kernel(
    const float* __restrict__ X,
    const float* __restrict__ Wq, const float* __restrict__ Wk,
    const float* __restrict__ Wv, const float* __restrict__ Wo)
{
    __shared__ float tile[32][33];
    const int blk = blockIdx.x;
    const int tid = threadIdx.x;

    if (blk < 4096) {
        int idx = blk * 256 + tid;
        int s = idx >> 9, p = idx & 511;
        const double CL2 = 9.210340371976184 / 512.0;
        double inv = exp(-(double)p * CL2);
        double ang = (double)s * inv;
        const double TWO_PI = 6.283185307179586476925;
        double r = ang - TWO_PI * rint(ang * (1.0 / TWO_PI));
        float sf, cf;
        __sincosf((float)r, &sf, &cf);
        g_rope[idx] = make_float2(cf, sf);
        return;
    }
    if (blk >= 6656) {
        size_t base = (size_t)(blk - 6656) * 2048 + tid * 8;
        float4 v0 = *(const float4*)(X + base);
        float4 v1 = *(const float4*)(X + base + 4);
        uint4 u = { fh2(v0.x, v0.y), fh2(v0.z, v0.w),
                    fh2(v1.x, v1.y), fh2(v1.z, v1.w) };
        *(uint4*)(g_xh + base) = u;
        return;
    }

    const int tx = tid & 31, ty = tid >> 5;
    if (blk < 5120) {
        int r = blk - 4096;
        do_transpose(Wq, 1024, g_wt, (r & 31) * 32, (r >> 5) * 32, tx, ty, tile);
    } else if (blk < 5376) {
        int r = blk - 5120;
        do_transpose(Wk, 256, g_wt + (size_t)1024 * 1024, (r & 7) * 32, (r >> 3) * 32, tx, ty, tile);
    } else if (blk < 5632) {
        int r = blk - 5376;
        do_transpose(Wv, 256, g_wt + (size_t)1280 * 1024, (r & 7) * 32, (r >> 3) * 32, tx, ty, tile);
    } else {
        int r = blk - 5632;
        do_transpose(Wo, 1024, g_wto, (r & 31) * 32, (r >> 5) * 32, tx, ty, tile);
    }
}

#define HROW 24   // GEMM smem halves per row (48B)

// ---------------------------------------------------------------------------
// Fused QKV projection: g_xh @ Wt^T, 3-stage cp.async pipeline. RoPE epi.
// ---------------------------------------------------------------------------
#define QSCALE 0.04508422f   // (1/32) * log2(e)

__global__ __launch_bounds__(256, 2) void qkv_gemm()
{
    __shared__ __half Ash[3][128 * HROW];
    __shared__ __half Bsh[3][128 * HROW];

    const int tid  = threadIdx.x;
    const int lane = tid & 31, warp = tid >> 5;
    const int g = lane >> 2, t = lane & 3;
    const int l7 = lane & 7, lm = (lane >> 3) & 1, lh = (lane >> 4) & 1;
    const int wm = (warp >> 2) * 64, wn = (warp & 3) * 32;
    const int bn = blockIdx.x * 128, bm = blockIdx.y * 128;
    const int kind = (bn < 1024) ? 0 : (bn < 1280) ? 1 : 2;

    const int a_r = tid >> 1, a_c = (tid & 1) * 8;
    const __half* Ap = g_xh + (size_t)(bm + a_r) * 1024 + a_c;
    const __half* Bp = g_wt + (size_t)(bn + a_r) * 1024 + a_c;
    const uint32_t so = (a_r * HROW + a_c) * 2;
    uint32_t asb[3], bsb[3];
#pragma unroll
    for (int i = 0; i < 3; ++i) {
        asb[i] = smem_u32(&Ash[i][0]) + so;
        bsb[i] = smem_u32(&Bsh[i][0]) + so;
    }

    float acc[4][4][4];
#pragma unroll
    for (int mi = 0; mi < 4; ++mi)
#pragma unroll
        for (int ni = 0; ni < 4; ++ni)
#pragma unroll
            for (int c = 0; c < 4; ++c) acc[mi][ni][c] = 0.f;

    // prologue: tiles 0,1
    cpa16(asb[0], Ap);      cpa16(bsb[0], Bp);      CPA_COMMIT();
    cpa16(asb[1], Ap + 16); cpa16(bsb[1], Bp + 16); CPA_COMMIT();
    CPA_WAIT1();
    __syncthreads();

    for (int kt = 0; kt < 64; ++kt) {
        const int cur = kt % 3;
        if (kt + 2 < 64) {
            int ko = (kt + 2) * 16;
            int nb = (kt + 2) % 3;
            cpa16(asb[nb], Ap + ko);
            cpa16(bsb[nb], Bp + ko);
            CPA_COMMIT();
        }

        const uint32_t ab = smem_u32(&Ash[cur][0]);
        const uint32_t bb = smem_u32(&Bsh[cur][0]);
        unsigned a[4][4], b[4][2];
#pragma unroll
        for (int mi = 0; mi < 4; ++mi)
            ldsm4(a[mi][0], a[mi][1], a[mi][2], a[mi][3],
                  ab + (wm + mi * 16 + lm * 8 + l7) * 48 + lh * 16);
#pragma unroll
        for (int p = 0; p < 2; ++p) {
            unsigned r0, r1, r2, r3;
            ldsm4(r0, r1, r2, r3,
                  bb + (wn + (2 * p + lh) * 8 + l7) * 48 + lm * 16);
            b[2 * p][0] = r0; b[2 * p][1] = r1;
            b[2 * p + 1][0] = r2; b[2 * p + 1][1] = r3;
        }
#pragma unroll
        for (int mi = 0; mi < 4; ++mi)
#pragma unroll
            for (int ni = 0; ni < 4; ++ni)
                mmah(acc[mi][ni], a[mi], b[ni]);

        if (kt < 62) CPA_WAIT1();
        else if (kt == 62) CPA_WAIT0();
        if (kt < 63) __syncthreads();
    }

    // Epilogue: RoPE via table + scatter (fp16 stores). Q pre-scaled.
#pragma unroll
    for (int mi = 0; mi < 4; ++mi) {
#pragma unroll
        for (int ni = 0; ni < 4; ++ni) {
            int n = bn + wn + ni * 8 + 2 * t;
#pragma unroll
            for (int half_ = 0; half_ < 2; ++half_) {
                int m = bm + wm + mi * 16 + g + half_ * 8;
                int b_ = m >> 11, s = m & 2047;
                float c0 = acc[mi][ni][half_ * 2 + 0];
                float c1 = acc[mi][ni][half_ * 2 + 1];
                if (kind == 0) {
                    float2 cs = g_rope[(size_t)s * 512 + (n >> 1)];
                    int h = n >> 6, d = n & 63;
                    *(__half2*)(g_q + (((size_t)b_ * NH + h) * S_LEN + s) * HDIM + d) =
                        __floats2half2_rn((c0 * cs.x - c1 * cs.y) * QSCALE,
                                          (c0 * cs.y + c1 * cs.x) * QSCALE);
                } else if (kind == 1) {
                    int np = n - 1024, kvh = np >> 6, d = np & 63;
                    float2 cs = g_rope[(size_t)s * 512 + (d >> 1)];
                    *(__half2*)(g_k + (((size_t)b_ * NKV + kvh) * S_LEN + s) * HDIM + d) =
                        __floats2half2_rn(c0 * cs.x - c1 * cs.y, c0 * cs.y + c1 * cs.x);
                } else {
                    int np = n - 1280, kvh = np >> 6, d = np & 63;
                    *(__half2*)(g_v + (((size_t)b_ * NKV + kvh) * S_LEN + s) * HDIM + d) =
                        __floats2half2_rn(c0, c1);
                }
            }
        }
    }
}

// ---------------------------------------------------------------------------
// Flash attention: 128-thread CTA, 4 warps x 32 q-rows, 2 CTAs/SM.
// exp2-domain softmax via ex2.approx.f16x2; results feed PV directly.
// ---------------------------------------------------------------------------
#define FH 72
#define KV_H (64 * FH)
#define FA_HALVES (128 * FH + 2 * KV_H + 2 * KV_H)
#define FA_BYTES (FA_HALVES * 2)       // 55296

__global__ __launch_bounds__(128, 2) void flash_kernel()
{
    extern __shared__ __half fsm[];
    __half* Qs = fsm;                  // [128][72]
    __half* Ks = fsm + 128 * FH;       // [2][64][72]
    __half* Vs = Ks + 2 * KV_H;        // [2][64][72]

    const int tid  = threadIdx.x;
    const int lane = tid & 31, warp = tid >> 5;
    const int g = lane >> 2, t = lane & 3;
    const int l7 = lane & 7, lm = (lane >> 3) & 1, lh = (lane >> 4) & 1;
    const int qt = blockIdx.x, h = blockIdx.y, b = blockIdx.z;
    const int kvh = h >> 2;
    const int wrow = warp * 32;

    const __half* Qg = g_q + (((size_t)b * NH  + h  ) * S_LEN + qt * 128) * HDIM;
    const __half* Kg = g_k + (((size_t)b * NKV + kvh) * S_LEN) * HDIM;
    const __half* Vg = g_v + (((size_t)b * NKV + kvh) * S_LEN) * HDIM;

    const uint32_t qs_b = smem_u32(Qs);
    const uint32_t ks_b = smem_u32(Ks);
    const uint32_t vs_b = smem_u32(Vs);

#pragma unroll
    for (int p = 0; p < 8; ++p) {
        int f = tid + p * 128;
        int r = f >> 3, c8 = (f & 7) << 3;
        cpa16(qs_b + (r * FH + c8) * 2, Qg + (size_t)r * HDIM + c8);
    }
#pragma unroll
    for (int i = 0; i < 4; ++i) {
        int f = tid + i * 128;
        int kv = f >> 3, c8 = (f & 7) << 3;
        cpa16(ks_b + (kv * FH + c8) * 2, Kg + (size_t)kv * HDIM + c8);
        cpa16(vs_b + (kv * FH + c8) * 2, Vg + (size_t)kv * HDIM + c8);
    }
    CPA_COMMIT();
    CPA_WAIT0();
    __syncthreads();

    float o[2][8][4];
#pragma unroll
    for (int mi = 0; mi < 2; ++mi)
#pragma unroll
        for (int j = 0; j < 8; ++j)
#pragma unroll
            for (int c = 0; c < 4; ++c) o[mi][j][c] = 0.f;
    float mx[4] = {-INFINITY, -INFINITY, -INFINITY, -INFINITY};
    float lx[4] = {0.f, 0.f, 0.f, 0.f};
    const unsigned FULL = 0xffffffffu;

    for (int kt = 0; kt < 32; ++kt) {
        const int cur = kt & 1;
        const uint32_t kc_b = ks_b + cur * KV_H * 2;
        const uint32_t vc_b = vs_b + cur * KV_H * 2;

        if (kt < 31) {
            const int nxt = cur ^ 1;
            const __half* Kt = Kg + (size_t)(kt + 1) * 64 * HDIM;
            const __half* Vt = Vg + (size_t)(kt + 1) * 64 * HDIM;
            const uint32_t kn_b = ks_b + nxt * KV_H * 2;
            const uint32_t vn_b = vs_b + nxt * KV_H * 2;
#pragma unroll
            for (int i = 0; i < 4; ++i) {
                int f = tid + i * 128;
                int kv = f >> 3, c8 = (f & 7) << 3;
                cpa16(kn_b + (kv * FH + c8) * 2, Kt + (size_t)kv * HDIM + c8);
                cpa16(vn_b + (kv * FH + c8) * 2, Vt + (size_t)kv * HDIM + c8);
            }
            CPA_COMMIT();
        }

        // S = Q K^T (log2-domain; Q pre-scaled): 32 x 64 per warp
        float s[2][8][4];
#pragma unroll
        for (int mi = 0; mi < 2; ++mi)
#pragma unroll
            for (int j = 0; j < 8; ++j)
#pragma unroll
                for (int c = 0; c < 4; ++c) s[mi][j][c] = 0.f;

#pragma unroll
        for (int kk = 0; kk < 4; ++kk) {
            unsigned a[2][4];
#pragma unroll
            for (int mi = 0; mi < 2; ++mi)
                ldsm4(a[mi][0], a[mi][1], a[mi][2], a[mi][3],
                      qs_b + (wrow + mi * 16 + lm * 8 + l7) * 144 + kk * 32 + lh * 16);
#pragma unroll
            for (int p = 0; p < 4; ++p) {
                unsigned r0, r1, r2, r3;
                ldsm4(r0, r1, r2, r3,
                      kc_b + ((2 * p + lh) * 8 + l7) * 144 + kk * 32 + lm * 16);
                unsigned b0[2] = { r0, r1 }, b1[2] = { r2, r3 };
                mmah(s[0][2 * p],     a[0], b0);
                mmah(s[1][2 * p],     a[1], b0);
                mmah(s[0][2 * p + 1], a[0], b1);
                mmah(s[1][2 * p + 1], a[1], b1);
            }
        }

        // Online softmax in exp2 domain; P computed in fp16x2 (feeds PV directly)
        float cf[4];
        unsigned eh[2][8][2];   // [mi][j][row-half]: packed exp2 pairs
#pragma unroll
        for (int mi = 0; mi < 2; ++mi) {
            float rm0 = -INFINITY, rm1 = -INFINITY;
#pragma unroll
            for (int j = 0; j < 8; ++j) {
                rm0 = fmaxf(rm0, fmaxf(s[mi][j][0], s[mi][j][1]));
                rm1 = fmaxf(rm1, fmaxf(s[mi][j][2], s[mi][j][3]));
            }
#pragma unroll
            for (int off = 1; off <= 2; off <<= 1) {
                rm0 = fmaxf(rm0, __shfl_xor_sync(FULL, rm0, off));
                rm1 = fmaxf(rm1, __shfl_xor_sync(FULL, rm1, off));
            }
            float nm0 = fmaxf(mx[2 * mi + 0], rm0);
            float nm1 = fmaxf(mx[2 * mi + 1], rm1);
            cf[2 * mi + 0] = exp2f(mx[2 * mi + 0] - nm0);
            cf[2 * mi + 1] = exp2f(mx[2 * mi + 1] - nm1);

            __half2 hs0 = __floats2half2_rn(0.f, 0.f);
            __half2 hs1 = hs0;
#pragma unroll
            for (int j = 0; j < 8; ++j) {
                unsigned e0 = h2exp2u(fh2(s[mi][j][0] - nm0, s[mi][j][1] - nm0));
                unsigned e1 = h2exp2u(fh2(s[mi][j][2] - nm1, s[mi][j][3] - nm1));
                eh[mi][j][0] = e0;
                eh[mi][j][1] = e1;
                hs0 = __hadd2(hs0, *(__half2*)&e0);
                hs1 = __hadd2(hs1, *(__half2*)&e1);
            }
            float2 f0 = __half22float2(hs0);
            float2 f1 = __half22float2(hs1);
            float rs0 = f0.x + f0.y, rs1 = f1.x + f1.y;
#pragma unroll
            for (int off = 1; off <= 2; off <<= 1) {
                rs0 += __shfl_xor_sync(FULL, rs0, off);
                rs1 += __shfl_xor_sync(FULL, rs1, off);
            }
            lx[2 * mi + 0] = lx[2 * mi + 0] * cf[2 * mi + 0] + rs0;
            lx[2 * mi + 1] = lx[2 * mi + 1] * cf[2 * mi + 1] + rs1;
            mx[2 * mi + 0] = nm0;
            mx[2 * mi + 1] = nm1;
        }

        // Rescale O only if some row's max moved (exp2f(0)==1 exactly)
        bool nochg = (cf[0] == 1.f) & (cf[1] == 1.f) & (cf[2] == 1.f) & (cf[3] == 1.f);
        if (!__all_sync(FULL, nochg)) {
#pragma unroll
            for (int mi = 0; mi < 2; ++mi)
#pragma unroll
                for (int jn = 0; jn < 8; ++jn) {
                    o[mi][jn][0] *= cf[2 * mi + 0]; o[mi][jn][1] *= cf[2 * mi + 0];
                    o[mi][jn][2] *= cf[2 * mi + 1]; o[mi][jn][3] *= cf[2 * mi + 1];
                }
        }

        // O += P V ; aP = eh directly, V via ldmatrix.trans (shared across mi)
#pragma unroll
        for (int kk = 0; kk < 4; ++kk) {
            unsigned aP[2][4];
#pragma unroll
            for (int mi = 0; mi < 2; ++mi) {
                aP[mi][0] = eh[mi][2 * kk][0];
                aP[mi][1] = eh[mi][2 * kk][1];
                aP[mi][2] = eh[mi][2 * kk + 1][0];
                aP[mi][3] = eh[mi][2 * kk + 1][1];
            }
#pragma unroll
            for (int p = 0; p < 4; ++p) {
                unsigned r0, r1, r2, r3;
                ldsm4t(r0, r1, r2, r3,
                       vc_b + (kk * 16 + lm * 8 + l7) * 144 + (2 * p + lh) * 16);
                unsigned b0[2] = { r0, r1 }, b1[2] = { r2, r3 };
                mmah(o[0][2 * p],     aP[0], b0);
                mmah(o[1][2 * p],     aP[1], b0);
                mmah(o[0][2 * p + 1], aP[0], b1);
                mmah(o[1][2 * p + 1], aP[1], b1);
            }
        }

        if (kt < 31) {
            CPA_WAIT0();
            __syncthreads();
        }
    }

    // Normalize + write (b,s,D) as fp16
#pragma unroll
    for (int mi = 0; mi < 2; ++mi) {
        float inv0 = 1.f / lx[2 * mi + 0], inv1 = 1.f / lx[2 * mi + 1];
        int r0 = qt * 128 + wrow + mi * 16 + g, r1 = r0 + 8;
#pragma unroll
        for (int jn = 0; jn < 8; ++jn) {
            int col = h * HDIM + jn * 8 + 2 * t;
            *(__half2*)&g_o[((size_t)b * S_LEN + r0) * D_MODEL + col] =
                __floats2half2_rn(o[mi][jn][0] * inv0, o[mi][jn][1] * inv0);
            *(__half2*)&g_o[((size_t)b * S_LEN + r1) * D_MODEL + col] =
                __floats2half2_rn(o[mi][jn][2] * inv1, o[mi][jn][3] * inv1);
        }
    }
}

// ---------------------------------------------------------------------------
// Output projection: g_o @ Wo^T -> out fp32. 3-stage cp.async pipeline.
// ---------------------------------------------------------------------------
__global__ __launch_bounds__(256, 2) void out_gemm(float* __restrict__ out)
{
    __shared__ __half Ash[3][128 * HROW];
    __shared__ __half Bsh[3][128 * HROW];

    const int tid  = threadIdx.x;
    const int lane = tid & 31, warp = tid >> 5;
    const int g = lane >> 2, t = lane & 3;
    const int l7 = lane & 7, lm = (lane >> 3) & 1, lh = (lane >> 4) & 1;
    const int wm = (warp >> 2) * 64, wn = (warp & 3) * 32;
    const int bn = blockIdx.x * 128, bm = blockIdx.y * 128;

    const int a_r = tid >> 1, a_c = (tid & 1) * 8;
    const __half* Ap = g_o   + (size_t)(bm + a_r) * 1024 + a_c;
    const __half* Bp = g_wto + (size_t)(bn + a_r) * 1024 + a_c;
    const uint32_t so = (a_r * HROW + a_c) * 2;
    uint32_t asb[3], bsb[3];
#pragma unroll
    for (int i = 0; i < 3; ++i) {
        asb[i] = smem_u32(&Ash[i][0]) + so;
        bsb[i] = smem_u32(&Bsh[i][0]) + so;
    }

    float acc[4][4][4];
#pragma unroll
    for (int mi = 0; mi < 4; ++mi)
#pragma unroll
        for (int ni = 0; ni < 4; ++ni)
#pragma unroll
            for (int c = 0; c < 4; ++c) acc[mi][ni][c] = 0.f;

    cpa16(asb[0], Ap);      cpa16(bsb[0], Bp);      CPA_COMMIT();
    cpa16(asb[1], Ap + 16); cpa16(bsb[1], Bp + 16); CPA_COMMIT();
    CPA_WAIT1();
    __syncthreads();

    for (int kt = 0; kt < 64; ++kt) {
        const int cur = kt % 3;
        if (kt + 2 < 64) {
            int ko = (kt + 2) * 16;
            int nb = (kt + 2) % 3;
            cpa16(asb[nb], Ap + ko);
            cpa16(bsb[nb], Bp + ko);
            CPA_COMMIT();
        }

        const uint32_t ab = smem_u32(&Ash[cur][0]);
        const uint32_t bb = smem_u32(&Bsh[cur][0]);
        unsigned a[4][4], b[4][2];
#pragma unroll
        for (int mi = 0; mi < 4; ++mi)
            ldsm4(a[mi][0], a[mi][1], a[mi][2], a[mi][3],
                  ab + (wm + mi * 16 + lm * 8 + l7) * 48 + lh * 16);
#pragma unroll
        for (int p = 0; p < 2; ++p) {
            unsigned r0, r1, r2, r3;
            ldsm4(r0, r1, r2, r3,
                  bb + (wn + (2 * p + lh) * 8 + l7) * 48 + lm * 16);
            b[2 * p][0] = r0; b[2 * p][1] = r1;
            b[2 * p + 1][0] = r2; b[2 * p + 1][1] = r3;
        }
#pragma unroll
        for (int mi = 0; mi < 4; ++mi)
#pragma unroll
            for (int ni = 0; ni < 4; ++ni)
                mmah(acc[mi][ni], a[mi], b[ni]);

        if (kt < 62) CPA_WAIT1();
        else if (kt == 62) CPA_WAIT0();
        if (kt < 63) __syncthreads();
    }

#pragma unroll
    for (int mi = 0; mi < 4; ++mi)
#pragma unroll
        for (int ni = 0; ni < 4; ++ni) {
            int n = bn + wn + ni * 8 + 2 * t;
#pragma unroll
            for (int half_ = 0; half_ < 2; ++half_) {
                int m = bm + wm + mi * 16 + g + half_ * 8;
                float2 r = { acc[mi][ni][half_ * 2 + 0], acc[mi][ni][half_ * 2 + 1] };
                *(float2*)&out[(size_t)m * 1024 + n] = r;
            }
        }
}

// ---------------------------------------------------------------------------
extern "C" void kernel_launch(void* const* d_in, const int* in_sizes, int n_in,
                              void* d_out, int out_size)
{
    const float* x  = (const float*)d_in[0];
    const float* Wq = (const float*)d_in[1];
    const float* Wk = (const float*)d_in[2];
    const float* Wv = (const float*)d_in[3];
    const float* Wo = (const float*)d_in[4];
    float* out = (float*)d_out;

    (void)in_sizes; (void)n_in; (void)out_size;

    cudaFuncSetAttribute(flash_kernel,
                         cudaFuncAttributeMaxDynamicSharedMemorySize, FA_BYTES);

    prep_kernel<<<8704, 256>>>(x, Wq, Wk, Wv, Wo);
    qkv_gemm<<<dim3(12, 32), 256>>>();
    flash_kernel<<<dim3(16, 16, 2), 128, FA_BYTES>>>();
    out_gemm<<<dim3(8, 32), 256>>>(out);
}

// round 15
// speedup vs baseline: 7.2772x; 1.0328x over previous
#include <cuda_runtime.h>
#include <cuda_fp16.h>
#include <math.h>
#include <stdint.h>

// Problem constants
#define S_LEN   2048
#define D_MODEL 1024
#define NH      16
#define NKV     4
#define HDIM    64
#define BATCH   2

// Scratch (device globals — no allocation allowed). All fp16.
__device__ __half g_xh[(size_t)BATCH * S_LEN * D_MODEL];   // X converted to fp16
__device__ __half g_q[(size_t)BATCH * NH  * S_LEN * HDIM]; // (b,h,s,d) roped, pre-scaled
__device__ __half g_k[(size_t)BATCH * NKV * S_LEN * HDIM]; // (b,kvh,s,d) roped
__device__ __half g_v[(size_t)BATCH * NKV * S_LEN * HDIM];
__device__ __half g_o[(size_t)BATCH * S_LEN * D_MODEL];    // (b,s,h*64+d)
__device__ float2 g_rope[(size_t)S_LEN * 512];             // [s][p] = (cos, sin)
__device__ __half g_wt [(size_t)1536 * 1024];              // [n][k] = (Wq|Wk|Wv)^T
__device__ __half g_wto[(size_t)1024 * 1024];              // Wo^T

// ---------------------------------------------------------------------------
// Helpers
// ---------------------------------------------------------------------------
__device__ __forceinline__ void mmah(float* d, const unsigned* a, const unsigned* b) {
    asm volatile(
        "mma.sync.aligned.m16n8k16.row.col.f32.f16.f16.f32 "
        "{%0,%1,%2,%3}, {%4,%5,%6,%7}, {%8,%9}, {%0,%1,%2,%3};"
        : "+f"(d[0]), "+f"(d[1]), "+f"(d[2]), "+f"(d[3])
        : "r"(a[0]), "r"(a[1]), "r"(a[2]), "r"(a[3]),
          "r"(b[0]), "r"(b[1]));
}
__device__ __forceinline__ unsigned fh2(float lo, float hi) {
    __half2 h = __floats2half2_rn(lo, hi);
    return *(unsigned*)&h;
}
__device__ __forceinline__ unsigned h2exp2u(unsigned x) {
    unsigned r;
    asm("ex2.approx.f16x2 %0, %1;" : "=r"(r) : "r"(x));
    return r;
}
__device__ __forceinline__ uint32_t smem_u32(const void* p) {
    uint32_t a;
    asm("{ .reg .u64 t; cvta.to.shared.u64 t, %1; cvt.u32.u64 %0, t; }"
        : "=r"(a) : "l"(p));
    return a;
}
__device__ __forceinline__ void ldsm4(
    unsigned& r0, unsigned& r1, unsigned& r2, unsigned& r3, uint32_t a) {
    asm volatile("ldmatrix.sync.aligned.m8n8.x4.shared.b16 {%0,%1,%2,%3}, [%4];"
        : "=r"(r0), "=r"(r1), "=r"(r2), "=r"(r3) : "r"(a));
}
__device__ __forceinline__ void ldsm4t(
    unsigned& r0, unsigned& r1, unsigned& r2, unsigned& r3, uint32_t a) {
    asm volatile("ldmatrix.sync.aligned.m8n8.x4.trans.shared.b16 {%0,%1,%2,%3}, [%4];"
        : "=r"(r0), "=r"(r1), "=r"(r2), "=r"(r3) : "r"(a));
}
__device__ __forceinline__ void cpa16(uint32_t dst, const void* src) {
    asm volatile("cp.async.cg.shared.global [%0], [%1], 16;"
                 :: "r"(dst), "l"(src) : "memory");
}
#define CPA_COMMIT() asm volatile("cp.async.commit_group;" ::: "memory")
#define CPA_WAIT0()  asm volatile("cp.async.wait_group 0;" ::: "memory")
#define CPA_WAIT1()  asm volatile("cp.async.wait_group 1;" ::: "memory")

// ---------------------------------------------------------------------------
// Fused prep: rope table + 4 weight transposes + X fp16 conversion.
// ---------------------------------------------------------------------------
__device__ __forceinline__ void do_transpose(
    const float* __restrict__ src, int cols, __half* dst,
    int bx, int by, int tx, int ty, float (*tile)[33])
{
#pragma unroll
    for (int i = 0; i < 32; i += 8)
        tile[ty + i][tx] = src[(size_t)(by + ty + i) * cols + bx + tx];
    __syncthreads();
#pragma unroll
    for (int i = 0; i < 32; i += 8)
        dst[(size_t)(bx + ty + i) * 1024 + by + tx] = __float2half_rn(tile[tx][ty + i]);
}

__global__ __launch_bounds__(256) void prep_kernel(
    const float* __restrict__ X,
    const float* __restrict__ Wq, const float* __restrict__ Wk,
    const float* __restrict__ Wv, const float* __restrict__ Wo)
{
    __shared__ float tile[32][33];
    const int blk = blockIdx.x;
    const int tid = threadIdx.x;

    if (blk < 4096) {
        int idx = blk * 256 + tid;
        int s = idx >> 9, p = idx & 511;
        const double CL2 = 9.210340371976184 / 512.0;
        double inv = exp(-(double)p * CL2);
        double ang = (double)s * inv;
        const double TWO_PI = 6.283185307179586476925;
        double r = ang - TWO_PI * rint(ang * (1.0 / TWO_PI));
        float sf, cf;
        __sincosf((float)r, &sf, &cf);
        g_rope[idx] = make_float2(cf, sf);
        return;
    }
    if (blk >= 6656) {
        size_t base = (size_t)(blk - 6656) * 2048 + tid * 8;
        float4 v0 = *(const float4*)(X + base);
        float4 v1 = *(const float4*)(X + base + 4);
        uint4 u = { fh2(v0.x, v0.y), fh2(v0.z, v0.w),
                    fh2(v1.x, v1.y), fh2(v1.z, v1.w) };
        *(uint4*)(g_xh + base) = u;
        return;
    }

    const int tx = tid & 31, ty = tid >> 5;
    if (blk < 5120) {
        int r = blk - 4096;
        do_transpose(Wq, 1024, g_wt, (r & 31) * 32, (r >> 5) * 32, tx, ty, tile);
    } else if (blk < 5376) {
        int r = blk - 5120;
        do_transpose(Wk, 256, g_wt + (size_t)1024 * 1024, (r & 7) * 32, (r >> 3) * 32, tx, ty, tile);
    } else if (blk < 5632) {
        int r = blk - 5376;
        do_transpose(Wv, 256, g_wt + (size_t)1280 * 1024, (r & 7) * 32, (r >> 3) * 32, tx, ty, tile);
    } else {
        int r = blk - 5632;
        do_transpose(Wo, 1024, g_wto, (r & 31) * 32, (r >> 5) * 32, tx, ty, tile);
    }
}

// ---------------------------------------------------------------------------
// GEMM geometry: 128x128 CTA, BK=32 halves, 8 warps (2x4), warp 64x32.
// Smem rows 40 halves (80B): LDSM 8-row bank pattern {0,20,8,28,...} distinct.
// 3-stage cp.async pipeline, dynamic smem.
// ---------------------------------------------------------------------------
#define HR2 40                          // halves per smem row
#define GST (128 * HR2)                 // halves per stage (one matrix)
#define GEMM_SMEM_BYTES (3 * 2 * GST * 2)   // 3 stages x (A+B) x 2B = 61440

#define QSCALE 0.04508422f   // (1/32) * log2(e)

__global__ __launch_bounds__(256, 2) void qkv_gemm()
{
    extern __shared__ __half gsm[];
    __half* Ash = gsm;                  // [3][GST]
    __half* Bsh = gsm + 3 * GST;        // [3][GST]

    const int tid  = threadIdx.x;
    const int lane = tid & 31, warp = tid >> 5;
    const int g = lane >> 2, t = lane & 3;
    const int l7 = lane & 7, lm = (lane >> 3) & 1, lh = (lane >> 4) & 1;
    const int wm = (warp >> 2) * 64, wn = (warp & 3) * 32;
    const int bn = blockIdx.x * 128, bm = blockIdx.y * 128;
    const int kind = (bn < 1024) ? 0 : (bn < 1280) ? 1 : 2;

    // fill: 512 chunks of 8 halves per matrix; 2 per thread
    const int f_r0 = tid >> 2, f_c0 = (tid & 3) * 8;       // chunk 0: rows 0..63
    const int f_r1 = (tid + 256) >> 2;                     // chunk 1: rows 64..127
    const __half* ApA = g_xh + (size_t)(bm + f_r0) * 1024 + f_c0;
    const __half* ApB = g_xh + (size_t)(bm + f_r1) * 1024 + f_c0;
    const __half* BpA = g_wt + (size_t)(bn + f_r0) * 1024 + f_c0;
    const __half* BpB = g_wt + (size_t)(bn + f_r1) * 1024 + f_c0;
    const uint32_t soA = (f_r0 * HR2 + f_c0) * 2;
    const uint32_t soB = (f_r1 * HR2 + f_c0) * 2;
    const uint32_t ash = smem_u32(Ash), bsh = smem_u32(Bsh);

    float acc[4][4][4];
#pragma unroll
    for (int mi = 0; mi < 4; ++mi)
#pragma unroll
        for (int ni = 0; ni < 4; ++ni)
#pragma unroll
            for (int c = 0; c < 4; ++c) acc[mi][ni][c] = 0.f;

    // prologue: tiles 0,1 (k offsets 0, 32)
#pragma unroll
    for (int pt = 0; pt < 2; ++pt) {
        uint32_t sb = pt * GST * 2;
        cpa16(ash + sb + soA, ApA + pt * 32);
        cpa16(ash + sb + soB, ApB + pt * 32);
        cpa16(bsh + sb + soA, BpA + pt * 32);
        cpa16(bsh + sb + soB, BpB + pt * 32);
        CPA_COMMIT();
    }
    CPA_WAIT1();
    __syncthreads();

    for (int kt = 0; kt < 32; ++kt) {
        const int cur = kt % 3;
        if (kt + 2 < 32) {
            int ko = (kt + 2) * 32;
            uint32_t sb = ((kt + 2) % 3) * GST * 2;
            cpa16(ash + sb + soA, ApA + ko);
            cpa16(ash + sb + soB, ApB + ko);
            cpa16(bsh + sb + soA, BpA + ko);
            cpa16(bsh + sb + soB, BpB + ko);
            CPA_COMMIT();
        }

        const uint32_t ab = ash + cur * GST * 2;
        const uint32_t bb = bsh + cur * GST * 2;
#pragma unroll
        for (int ks = 0; ks < 2; ++ks) {
            unsigned a[4][4], b[4][2];
#pragma unroll
            for (int mi = 0; mi < 4; ++mi)
                ldsm4(a[mi][0], a[mi][1], a[mi][2], a[mi][3],
                      ab + (wm + mi * 16 + lm * 8 + l7) * 80 + ks * 32 + lh * 16);
#pragma unroll
            for (int p = 0; p < 2; ++p) {
                unsigned r0, r1, r2, r3;
                ldsm4(r0, r1, r2, r3,
                      bb + (wn + (2 * p + lh) * 8 + l7) * 80 + ks * 32 + lm * 16);
                b[2 * p][0] = r0; b[2 * p][1] = r1;
                b[2 * p + 1][0] = r2; b[2 * p + 1][1] = r3;
            }
#pragma unroll
            for (int mi = 0; mi < 4; ++mi)
#pragma unroll
                for (int ni = 0; ni < 4; ++ni)
                    mmah(acc[mi][ni], a[mi], b[ni]);
        }

        if (kt < 30) CPA_WAIT1();
        else if (kt == 30) CPA_WAIT0();
        if (kt < 31) __syncthreads();
    }

    // Epilogue: RoPE via table + scatter (fp16 stores). Q pre-scaled.
#pragma unroll
    for (int mi = 0; mi < 4; ++mi) {
#pragma unroll
        for (int ni = 0; ni < 4; ++ni) {
            int n = bn + wn + ni * 8 + 2 * t;
#pragma unroll
            for (int half_ = 0; half_ < 2; ++half_) {
                int m = bm + wm + mi * 16 + g + half_ * 8;
                int b_ = m >> 11, s = m & 2047;
                float c0 = acc[mi][ni][half_ * 2 + 0];
                float c1 = acc[mi][ni][half_ * 2 + 1];
                if (kind == 0) {
                    float2 cs = g_rope[(size_t)s * 512 + (n >> 1)];
                    int h = n >> 6, d = n & 63;
                    *(__half2*)(g_q + (((size_t)b_ * NH + h) * S_LEN + s) * HDIM + d) =
                        __floats2half2_rn((c0 * cs.x - c1 * cs.y) * QSCALE,
                                          (c0 * cs.y + c1 * cs.x) * QSCALE);
                } else if (kind == 1) {
                    int np = n - 1024, kvh = np >> 6, d = np & 63;
                    float2 cs = g_rope[(size_t)s * 512 + (d >> 1)];
                    *(__half2*)(g_k + (((size_t)b_ * NKV + kvh) * S_LEN + s) * HDIM + d) =
                        __floats2half2_rn(c0 * cs.x - c1 * cs.y, c0 * cs.y + c1 * cs.x);
                } else {
                    int np = n - 1280, kvh = np >> 6, d = np & 63;
                    *(__half2*)(g_v + (((size_t)b_ * NKV + kvh) * S_LEN + s) * HDIM + d) =
                        __floats2half2_rn(c0, c1);
                }
            }
        }
    }
}

// ---------------------------------------------------------------------------
// Flash attention: 128-thread CTA, 4 warps x 32 q-rows, 2 CTAs/SM.
// fp16x2 softmax (hmax2/hsub2/ex2.f16x2); results feed PV directly.
// ---------------------------------------------------------------------------
#define FH 72
#define KV_H (64 * FH)
#define FA_HALVES (128 * FH + 2 * KV_H + 2 * KV_H)
#define FA_BYTES (FA_HALVES * 2)       // 55296

__global__ __launch_bounds__(128, 2) void flash_kernel()
{
    extern __shared__ __half fsm[];
    __half* Qs = fsm;                  // [128][72]
    __half* Ks = fsm + 128 * FH;       // [2][64][72]
    __half* Vs = Ks + 2 * KV_H;        // [2][64][72]

    const int tid  = threadIdx.x;
    const int lane = tid & 31, warp = tid >> 5;
    const int g = lane >> 2, t = lane & 3;
    const int l7 = lane & 7, lm = (lane >> 3) & 1, lh = (lane >> 4) & 1;
    const int qt = blockIdx.x, h = blockIdx.y, b = blockIdx.z;
    const int kvh = h >> 2;
    const int wrow = warp * 32;

    const __half* Qg = g_q + (((size_t)b * NH  + h  ) * S_LEN + qt * 128) * HDIM;
    const __half* Kg = g_k + (((size_t)b * NKV + kvh) * S_LEN) * HDIM;
    const __half* Vg = g_v + (((size_t)b * NKV + kvh) * S_LEN) * HDIM;

    const uint32_t qs_b = smem_u32(Qs);
    const uint32_t ks_b = smem_u32(Ks);
    const uint32_t vs_b = smem_u32(Vs);

#pragma unroll
    for (int p = 0; p < 8; ++p) {
        int f = tid + p * 128;
        int r = f >> 3, c8 = (f & 7) << 3;
        cpa16(qs_b + (r * FH + c8) * 2, Qg + (size_t)r * HDIM + c8);
    }
#pragma unroll
    for (int i = 0; i < 4; ++i) {
        int f = tid + i * 128;
        int kv = f >> 3, c8 = (f & 7) << 3;
        cpa16(ks_b + (kv * FH + c8) * 2, Kg + (size_t)kv * HDIM + c8);
        cpa16(vs_b + (kv * FH + c8) * 2, Vg + (size_t)kv * HDIM + c8);
    }
    CPA_COMMIT();
    CPA_WAIT0();
    __syncthreads();

    float o[2][8][4];
#pragma unroll
    for (int mi = 0; mi < 2; ++mi)
#pragma unroll
        for (int j = 0; j < 8; ++j)
#pragma unroll
            for (int c = 0; c < 4; ++c) o[mi][j][c] = 0.f;
    float mx[4] = {-INFINITY, -INFINITY, -INFINITY, -INFINITY};
    float lx[4] = {0.f, 0.f, 0.f, 0.f};
    const unsigned FULL = 0xffffffffu;

    for (int kt = 0; kt < 32; ++kt) {
        const int cur = kt & 1;
        const uint32_t kc_b = ks_b + cur * KV_H * 2;
        const uint32_t vc_b = vs_b + cur * KV_H * 2;

        if (kt < 31) {
            const int nxt = cur ^ 1;
            const __half* Kt = Kg + (size_t)(kt + 1) * 64 * HDIM;
            const __half* Vt = Vg + (size_t)(kt + 1) * 64 * HDIM;
            const uint32_t kn_b = ks_b + nxt * KV_H * 2;
            const uint32_t vn_b = vs_b + nxt * KV_H * 2;
#pragma unroll
            for (int i = 0; i < 4; ++i) {
                int f = tid + i * 128;
                int kv = f >> 3, c8 = (f & 7) << 3;
                cpa16(kn_b + (kv * FH + c8) * 2, Kt + (size_t)kv * HDIM + c8);
                cpa16(vn_b + (kv * FH + c8) * 2, Vt + (size_t)kv * HDIM + c8);
            }
            CPA_COMMIT();
        }

        // S = Q K^T (log2-domain; Q pre-scaled): 32 x 64 per warp
        float s[2][8][4];
#pragma unroll
        for (int mi = 0; mi < 2; ++mi)
#pragma unroll
            for (int j = 0; j < 8; ++j)
#pragma unroll
                for (int c = 0; c < 4; ++c) s[mi][j][c] = 0.f;

#pragma unroll
        for (int kk = 0; kk < 4; ++kk) {
            unsigned a[2][4];
#pragma unroll
            for (int mi = 0; mi < 2; ++mi)
                ldsm4(a[mi][0], a[mi][1], a[mi][2], a[mi][3],
                      qs_b + (wrow + mi * 16 + lm * 8 + l7) * 144 + kk * 32 + lh * 16);
#pragma unroll
            for (int p = 0; p < 4; ++p) {
                unsigned r0, r1, r2, r3;
                ldsm4(r0, r1, r2, r3,
                      kc_b + ((2 * p + lh) * 8 + l7) * 144 + kk * 32 + lm * 16);
                unsigned b0[2] = { r0, r1 }, b1[2] = { r2, r3 };
                mmah(s[0][2 * p],     a[0], b0);
                mmah(s[1][2 * p],     a[1], b0);
                mmah(s[0][2 * p + 1], a[0], b1);
                mmah(s[1][2 * p + 1], a[1], b1);
            }
        }

        // Online softmax, all fp16x2 (log2 domain; Q pre-scaled)
        float cf[4];
        unsigned eh[2][8][2];
#pragma unroll
        for (int mi = 0; mi < 2; ++mi) {
            __half2 ph0[8], ph1[8];
#pragma unroll
            for (int j = 0; j < 8; ++j) {
                unsigned u0 = fh2(s[mi][j][0], s[mi][j][1]);
                unsigned u1 = fh2(s[mi][j][2], s[mi][j][3]);
                ph0[j] = *(__half2*)&u0;
                ph1[j] = *(__half2*)&u1;
            }
            __half2 m0 = ph0[0], m1 = ph1[0];
#pragma unroll
            for (int j = 1; j < 8; ++j) {
                m0 = __hmax2(m0, ph0[j]);
                m1 = __hmax2(m1, ph1[j]);
            }
            float rm0 = fmaxf(__low2float(m0), __high2float(m0));
            float rm1 = fmaxf(__low2float(m1), __high2float(m1));
#pragma unroll
            for (int off = 1; off <= 2; off <<= 1) {
                rm0 = fmaxf(rm0, __shfl_xor_sync(FULL, rm0, off));
                rm1 = fmaxf(rm1, __shfl_xor_sync(FULL, rm1, off));
            }
            float nm0 = fmaxf(mx[2 * mi + 0], rm0);
            float nm1 = fmaxf(mx[2 * mi + 1], rm1);
            cf[2 * mi + 0] = exp2f(mx[2 * mi + 0] - nm0);
            cf[2 * mi + 1] = exp2f(mx[2 * mi + 1] - nm1);

            __half2 nh0 = __float2half2_rn(nm0);
            __half2 nh1 = __float2half2_rn(nm1);
            __half2 hs0 = __float2half2_rn(0.f), hs1 = hs0;
#pragma unroll
            for (int j = 0; j < 8; ++j) {
                __half2 d0 = __hsub2(ph0[j], nh0);
                __half2 d1 = __hsub2(ph1[j], nh1);
                unsigned e0 = h2exp2u(*(unsigned*)&d0);
                unsigned e1 = h2exp2u(*(unsigned*)&d1);
                eh[mi][j][0] = e0;
                eh[mi][j][1] = e1;
                hs0 = __hadd2(hs0, *(__half2*)&e0);
                hs1 = __hadd2(hs1, *(__half2*)&e1);
            }
            float2 f0 = __half22float2(hs0);
            float2 f1 = __half22float2(hs1);
            float rs0 = f0.x + f0.y, rs1 = f1.x + f1.y;
#pragma unroll
            for (int off = 1; off <= 2; off <<= 1) {
                rs0 += __shfl_xor_sync(FULL, rs0, off);
                rs1 += __shfl_xor_sync(FULL, rs1, off);
            }
            lx[2 * mi + 0] = lx[2 * mi + 0] * cf[2 * mi + 0] + rs0;
            lx[2 * mi + 1] = lx[2 * mi + 1] * cf[2 * mi + 1] + rs1;
            mx[2 * mi + 0] = nm0;
            mx[2 * mi + 1] = nm1;
        }

        // Rescale O only if some row's max moved (exp2f(0)==1 exactly)
        bool nochg = (cf[0] == 1.f) & (cf[1] == 1.f) & (cf[2] == 1.f) & (cf[3] == 1.f);
        if (!__all_sync(FULL, nochg)) {
#pragma unroll
            for (int mi = 0; mi < 2; ++mi)
#pragma unroll
                for (int jn = 0; jn < 8; ++jn) {
                    o[mi][jn][0] *= cf[2 * mi + 0]; o[mi][jn][1] *= cf[2 * mi + 0];
                    o[mi][jn][2] *= cf[2 * mi + 1]; o[mi][jn][3] *= cf[2 * mi + 1];
                }
        }

        // O += P V ; aP = eh directly, V via ldmatrix.trans (shared across mi)
#pragma unroll
        for (int kk = 0; kk < 4; ++kk) {
            unsigned aP[2][4];
#pragma unroll
            for (int mi = 0; mi < 2; ++mi) {
                aP[mi][0] = eh[mi][2 * kk][0];
                aP[mi][1] = eh[mi][2 * kk][1];
                aP[mi][2] = eh[mi][2 * kk + 1][0];
                aP[mi][3] = eh[mi][2 * kk + 1][1];
            }
#pragma unroll
            for (int p = 0; p < 4; ++p) {
                unsigned r0, r1, r2, r3;
                ldsm4t(r0, r1, r2, r3,
                       vc_b + (kk * 16 + lm * 8 + l7) * 144 + (2 * p + lh) * 16);
                unsigned b0[2] = { r0, r1 }, b1[2] = { r2, r3 };
                mmah(o[0][2 * p],     aP[0], b0);
                mmah(o[1][2 * p],     aP[1], b0);
                mmah(o[0][2 * p + 1], aP[0], b1);
                mmah(o[1][2 * p + 1], aP[1], b1);
            }
        }

        if (kt < 31) {
            CPA_WAIT0();
            __syncthreads();
        }
    }

    // Normalize + write (b,s,D) as fp16
#pragma unroll
    for (int mi = 0; mi < 2; ++mi) {
        float inv0 = 1.f / lx[2 * mi + 0], inv1 = 1.f / lx[2 * mi + 1];
        int r0 = qt * 128 + wrow + mi * 16 + g, r1 = r0 + 8;
#pragma unroll
        for (int jn = 0; jn < 8; ++jn) {
            int col = h * HDIM + jn * 8 + 2 * t;
            *(__half2*)&g_o[((size_t)b * S_LEN + r0) * D_MODEL + col] =
                __floats2half2_rn(o[mi][jn][0] * inv0, o[mi][jn][1] * inv0);
            *(__half2*)&g_o[((size_t)b * S_LEN + r1) * D_MODEL + col] =
                __floats2half2_rn(o[mi][jn][2] * inv1, o[mi][jn][3] * inv1);
        }
    }
}

// ---------------------------------------------------------------------------
// Output projection: g_o @ Wo^T -> out fp32. BK=32, 3-stage cp.async.
// ---------------------------------------------------------------------------
__global__ __launch_bounds__(256, 2) void out_gemm(float* __restrict__ out)
{
    extern __shared__ __half gsm[];
    __half* Ash = gsm;
    __half* Bsh = gsm + 3 * GST;

    const int tid  = threadIdx.x;
    const int lane = tid & 31, warp = tid >> 5;
    const int g = lane >> 2, t = lane & 3;
    const int l7 = lane & 7, lm = (lane >> 3) & 1, lh = (lane >> 4) & 1;
    const int wm = (warp >> 2) * 64, wn = (warp & 3) * 32;
    const int bn = blockIdx.x * 128, bm = blockIdx.y * 128;

    const int f_r0 = tid >> 2, f_c0 = (tid & 3) * 8;
    const int f_r1 = (tid + 256) >> 2;
    const __half* ApA = g_o  + (size_t)(bm + f_r0) * 1024 + f_c0;
    const __half* ApB = g_o  + (size_t)(bm + f_r1) * 1024 + f_c0;
    const __half* BpA = g_wto + (size_t)(bn + f_r0) * 1024 + f_c0;
    const __half* BpB = g_wto + (size_t)(bn + f_r1) * 1024 + f_c0;
    const uint32_t soA = (f_r0 * HR2 + f_c0) * 2;
    const uint32_t soB = (f_r1 * HR2 + f_c0) * 2;
    const uint32_t ash = smem_u32(Ash), bsh = smem_u32(Bsh);

    float acc[4][4][4];
#pragma unroll
    for (int mi = 0; mi < 4; ++mi)
#pragma unroll
        for (int ni = 0; ni < 4; ++ni)
#pragma unroll
            for (int c = 0; c < 4; ++c) acc[mi][ni][c] = 0.f;

#pragma unroll
    for (int pt = 0; pt < 2; ++pt) {
        uint32_t sb = pt * GST * 2;
        cpa16(ash + sb + soA, ApA + pt * 32);
        cpa16(ash + sb + soB, ApB + pt * 32);
        cpa16(bsh + sb + soA, BpA + pt * 32);
        cpa16(bsh + sb + soB, BpB + pt * 32);
        CPA_COMMIT();
    }
    CPA_WAIT1();
    __syncthreads();

    for (int kt = 0; kt < 32; ++kt) {
        const int cur = kt % 3;
        if (kt + 2 < 32) {
            int ko = (kt + 2) * 32;
            uint32_t sb = ((kt + 2) % 3) * GST * 2;
            cpa16(ash + sb + soA, ApA + ko);
            cpa16(ash + sb + soB, ApB + ko);
            cpa16(bsh + sb + soA, BpA + ko);
            cpa16(bsh + sb + soB, BpB + ko);
            CPA_COMMIT();
        }

        const uint32_t ab = ash + cur * GST * 2;
        const uint32_t bb = bsh + cur * GST * 2;
#pragma unroll
        for (int ks = 0; ks < 2; ++ks) {
            unsigned a[4][4], b[4][2];
#pragma unroll
            for (int mi = 0; mi < 4; ++mi)
                ldsm4(a[mi][0], a[mi][1], a[mi][2], a[mi][3],
                      ab + (wm + mi * 16 + lm * 8 + l7) * 80 + ks * 32 + lh * 16);
#pragma unroll
            for (int p = 0; p < 2; ++p) {
                unsigned r0, r1, r2, r3;
                ldsm4(r0, r1, r2, r3,
                      bb + (wn + (2 * p + lh) * 8 + l7) * 80 + ks * 32 + lm * 16);
                b[2 * p][0] = r0; b[2 * p][1] = r1;
                b[2 * p + 1][0] = r2; b[2 * p + 1][1] = r3;
            }
#pragma unroll
            for (int mi = 0; mi < 4; ++mi)
#pragma unroll
                for (int ni = 0; ni < 4; ++ni)
                    mmah(acc[mi][ni], a[mi], b[ni]);
        }

        if (kt < 30) CPA_WAIT1();
        else if (kt == 30) CPA_WAIT0();
        if (kt < 31) __syncthreads();
    }

#pragma unroll
    for (int mi = 0; mi < 4; ++mi)
#pragma unroll
        for (int ni = 0; ni < 4; ++ni) {
            int n = bn + wn + ni * 8 + 2 * t;
#pragma unroll
            for (int half_ = 0; half_ < 2; ++half_) {
                int m = bm + wm + mi * 16 + g + half_ * 8;
                float2 r = { acc[mi][ni][half_ * 2 + 0], acc[mi][ni][half_ * 2 + 1] };
                *(float2*)&out[(size_t)m * 1024 + n] = r;
            }
        }
}

// ---------------------------------------------------------------------------
extern "C" void kernel_launch(void* const* d_in, const int* in_sizes, int n_in,
                              void* d_out, int out_size)
{
    const float* x  = (const float*)d_in[0];
    const float* Wq = (const float*)d_in[1];
    const float* Wk = (const float*)d_in[2];
    const float* Wv = (const float*)d_in[3];
    const float* Wo = (const float*)d_in[4];
    float* out = (float*)d_out;

    (void)in_sizes; (void)n_in; (void)out_size;

    cudaFuncSetAttribute(flash_kernel,
                         cudaFuncAttributeMaxDynamicSharedMemorySize, FA_BYTES);
    cudaFuncSetAttribute(qkv_gemm,
                         cudaFuncAttributeMaxDynamicSharedMemorySize, GEMM_SMEM_BYTES);
    cudaFuncSetAttribute(out_gemm,
                         cudaFuncAttributeMaxDynamicSharedMemorySize, GEMM_SMEM_BYTES);

    prep_kernel<<<8704, 256>>>(x, Wq, Wk, Wv, Wo);
    qkv_gemm<<<dim3(12, 32), 256, GEMM_SMEM_BYTES>>>();
    flash_kernel<<<dim3(16, 16, 2), 128, FA_BYTES>>>();
    out_gemm<<<dim3(8, 32), 256, GEMM_SMEM_BYTES>>>(out);
}